// round 2
// baseline (speedup 1.0000x reference)
#include <cuda_runtime.h>
#include <math.h>

#define NUM_HEADS 16
#define D_HEAD 64
#define BATCH 2
#define SEQ 2048
#define BH (BATCH*NUM_HEADS)   // 32

// Scratch (no cudaMalloc allowed): [B,H,S,d] fp32 each = 16 MB
__device__ float g_Q[BH*SEQ*D_HEAD];
__device__ float g_K[BH*SEQ*D_HEAD];
__device__ float g_V[BH*SEQ*D_HEAD];
__device__ float g_O[BH*SEQ*D_HEAD];

// ---- packed f32x2 helpers (sm_103a) --------------------------------------
__device__ __forceinline__ void ffma2(unsigned long long& c, unsigned long long a, unsigned long long b) {
    asm("fma.rn.f32x2 %0, %1, %2, %0;" : "+l"(c) : "l"(a), "l"(b));
}
__device__ __forceinline__ void fmul2(unsigned long long& c, unsigned long long a) {
    asm("mul.rn.f32x2 %0, %0, %1;" : "+l"(c) : "l"(a));
}
__device__ __forceinline__ unsigned long long dup2(float a) {
    unsigned long long u; asm("mov.b64 %0, {%1, %1};" : "=l"(u) : "f"(a)); return u;
}
__device__ __forceinline__ float2 u2f(unsigned long long u) {
    float2 v; asm("mov.b64 {%0, %1}, %2;" : "=f"(v.x), "=f"(v.y) : "l"(u)); return v;
}

// ---------------------------------------------------------------------------
// Fused QKV projection: C[m,e] = sum_k x[m,k] * W[e,k]  (M=4096, K=1024)
// BM=128, BN=64 (one head), BK=32. 256 threads, 8x4 thread tiles, f32x2 FMA.
// Dot-product form: both operands K-contiguous -> natural smem layout.
// ---------------------------------------------------------------------------
__global__ __launch_bounds__(256) void qkv_gemm(const float* __restrict__ x,
                                                const float* __restrict__ Wq,
                                                const float* __restrict__ Wk,
                                                const float* __restrict__ Wv) {
    int mt = blockIdx.x;
    int which = blockIdx.y >> 4;
    int nt = blockIdx.y & 15;           // head
    const float* W = (which == 0) ? Wq : (which == 1) ? Wk : Wv;
    float* out = (which == 0) ? g_Q : (which == 1) ? g_K : g_V;

    __shared__ float As[128 * 36];      // [m][k], stride 36
    __shared__ float Bs[64 * 36];       // [n][k]

    int tid = threadIdx.x;
    int tx = tid & 15, ty = tid >> 4;

    const float* Ap = x + (size_t)(mt * 128 + (tid >> 1)) * 1024 + (tid & 1) * 16;
    const float* Bp = W + (size_t)(nt * 64 + (tid >> 2)) * 1024 + (tid & 3) * 8;
    float* Asw = &As[(tid >> 1) * 36 + (tid & 1) * 16];
    float* Bsw = &Bs[(tid >> 2) * 36 + (tid & 3) * 8];

    unsigned long long acc[8][4] = {};

    float4 ra[4], rb[2];
#pragma unroll
    for (int i = 0; i < 4; i++) ra[i] = *(const float4*)(Ap + i * 4);
#pragma unroll
    for (int i = 0; i < 2; i++) rb[i] = *(const float4*)(Bp + i * 4);

    for (int k0 = 0; k0 < 1024; k0 += 32) {
        __syncthreads();
#pragma unroll
        for (int i = 0; i < 4; i++) *(float4*)(Asw + i * 4) = ra[i];
#pragma unroll
        for (int i = 0; i < 2; i++) *(float4*)(Bsw + i * 4) = rb[i];
        __syncthreads();
        if (k0 + 32 < 1024) {
#pragma unroll
            for (int i = 0; i < 4; i++) ra[i] = *(const float4*)(Ap + k0 + 32 + i * 4);
#pragma unroll
            for (int i = 0; i < 2; i++) rb[i] = *(const float4*)(Bp + k0 + 32 + i * 4);
        }
#pragma unroll
        for (int kc = 0; kc < 32; kc += 4) {
            ulonglong2 aq[8], bq[4];
#pragma unroll
            for (int r = 0; r < 8; r++) aq[r] = *(const ulonglong2*)&As[(ty * 8 + r) * 36 + kc];
#pragma unroll
            for (int c = 0; c < 4; c++) bq[c] = *(const ulonglong2*)&Bs[(tx * 4 + c) * 36 + kc];
#pragma unroll
            for (int r = 0; r < 8; r++)
#pragma unroll
                for (int c = 0; c < 4; c++) {
                    ffma2(acc[r][c], aq[r].x, bq[c].x);
                    ffma2(acc[r][c], aq[r].y, bq[c].y);
                }
        }
    }

#pragma unroll
    for (int r = 0; r < 8; r++) {
        int m = mt * 128 + ty * 8 + r;
        int b = m >> 11, s = m & 2047;
        float2 v0 = u2f(acc[r][0]), v1 = u2f(acc[r][1]), v2 = u2f(acc[r][2]), v3 = u2f(acc[r][3]);
        float4 o = make_float4(v0.x + v0.y, v1.x + v1.y, v2.x + v2.y, v3.x + v3.y);
        *(float4*)(out + (((size_t)(b * 16 + nt) * SEQ + s) * 64 + tx * 4)) = o;
    }
}

// ---------------------------------------------------------------------------
// RoPE on Q and K in-place ([B,H,S,d] layout). One thread per even/odd pair.
// ---------------------------------------------------------------------------
__global__ void rope_kernel(const int* __restrict__ pos) {
    int t = blockIdx.x * blockDim.x + threadIdx.x;
    if (t >= BH * SEQ * 32) return;
    int p = t & 31;
    int s = (t >> 5) & 2047;
    double inv = exp(-(double)p * (9.210340371976184 / 32.0));
    double ang = (double)pos[s] * inv;
    double sn, cs;
    sincos(ang, &sn, &cs);
    float c = (float)cs, sf = (float)sn;

    float2 q = *(float2*)(g_Q + 2 * (size_t)t);
    float2 k = *(float2*)(g_K + 2 * (size_t)t);
    *(float2*)(g_Q + 2 * (size_t)t) = make_float2(q.x * c - q.y * sf, q.x * sf + q.y * c);
    *(float2*)(g_K + 2 * (size_t)t) = make_float2(k.x * c - k.y * sf, k.x * sf + k.y * c);
}

// ---------------------------------------------------------------------------
// Causal flash attention, fp32 + f32x2. Br=128, Bc=64, 256 threads (8x4 tiles).
// All smem tiles natural row-major (no transposed stores). 104448B dyn smem.
// ---------------------------------------------------------------------------
__global__ __launch_bounds__(256) void flash_attn() {
    int qt = gridDim.x - 1 - blockIdx.x;   // longest blocks first
    int bh = blockIdx.y;
    const float* Qp = g_Q + (size_t)bh * SEQ * 64;
    const float* Kp = g_K + (size_t)bh * SEQ * 64;
    const float* Vp = g_V + (size_t)bh * SEQ * 64;

    extern __shared__ float sm[];
    float* Qs = sm;                 // [128][68]  pre-scaled by 1/8
    float* Ks = Qs + 128 * 68;      // [64][68]
    float* Vs = Ks + 64 * 68;       // [64][68]
    float* Ps = Vs + 64 * 68;       // [128][68]

    int tid = threadIdx.x;
    int tx = tid & 15, ty = tid >> 4;

    // Load Q tile (128 x 64), scale by 1/8
    {
        int row = tid >> 1, off = (tid & 1) * 32;
        const float* src = Qp + (size_t)(qt * 128 + row) * 64 + off;
        float* dst = Qs + row * 68 + off;
#pragma unroll
        for (int i = 0; i < 8; i++) {
            float4 q = *(const float4*)(src + i * 4);
            q.x *= 0.125f; q.y *= 0.125f; q.z *= 0.125f; q.w *= 0.125f;
            *(float4*)(dst + i * 4) = q;
        }
    }

    unsigned long long O2[8][2] = {};     // O pairs along d-columns
    float mrow[8], lrow[8];
#pragma unroll
    for (int r = 0; r < 8; r++) { mrow[r] = -INFINITY; lrow[r] = 0.f; }

    int kmax = 2 * qt + 1;
    for (int kt = 0; kt <= kmax; kt++) {
        __syncthreads();   // prior PV reads done; Q visible on iter 0
        {
            int row = tid >> 2, off = (tid & 3) * 16;
            const float* ksrc = Kp + (size_t)(kt * 64 + row) * 64 + off;
            const float* vsrc = Vp + (size_t)(kt * 64 + row) * 64 + off;
            float* kdst = Ks + row * 68 + off;
            float* vdst = Vs + row * 68 + off;
#pragma unroll
            for (int i = 0; i < 4; i++) {
                *(float4*)(kdst + i * 4) = *(const float4*)(ksrc + i * 4);
                *(float4*)(vdst + i * 4) = *(const float4*)(vsrc + i * 4);
            }
        }
        __syncthreads();

        // S = Q K^T (dot form, pairs along d)
        unsigned long long sacc[8][4] = {};
#pragma unroll 4
        for (int d0 = 0; d0 < 64; d0 += 4) {
            ulonglong2 qv[8], kv[4];
#pragma unroll
            for (int r = 0; r < 8; r++) qv[r] = *(const ulonglong2*)&Qs[(ty * 8 + r) * 68 + d0];
#pragma unroll
            for (int c = 0; c < 4; c++) kv[c] = *(const ulonglong2*)&Ks[(tx * 4 + c) * 68 + d0];
#pragma unroll
            for (int r = 0; r < 8; r++)
#pragma unroll
                for (int c = 0; c < 4; c++) {
                    ffma2(sacc[r][c], qv[r].x, kv[c].x);
                    ffma2(sacc[r][c], qv[r].y, kv[c].y);
                }
        }

        float s[8][4];
#pragma unroll
        for (int r = 0; r < 8; r++)
#pragma unroll
            for (int c = 0; c < 4; c++) {
                float2 v = u2f(sacc[r][c]);
                s[r][c] = v.x + v.y;
            }

        if (kt >= 2 * qt) {   // diagonal tiles: causal mask
#pragma unroll
            for (int r = 0; r < 8; r++) {
                int i = qt * 128 + ty * 8 + r;
#pragma unroll
                for (int c = 0; c < 4; c++)
                    if (kt * 64 + tx * 4 + c > i) s[r][c] = -1e30f;
            }
        }

        // Online softmax per row (rows shared across 16 lanes of tx)
#pragma unroll
        for (int r = 0; r < 8; r++) {
            float mx = fmaxf(fmaxf(s[r][0], s[r][1]), fmaxf(s[r][2], s[r][3]));
#pragma unroll
            for (int off = 8; off >= 1; off >>= 1)
                mx = fmaxf(mx, __shfl_xor_sync(0xffffffffu, mx, off, 16));
            float mnew = fmaxf(mrow[r], mx);
            float alpha = __expf(mrow[r] - mnew);
            mrow[r] = mnew;
            float sum = 0.f;
#pragma unroll
            for (int c = 0; c < 4; c++) { s[r][c] = __expf(s[r][c] - mnew); sum += s[r][c]; }
#pragma unroll
            for (int off = 8; off >= 1; off >>= 1)
                sum += __shfl_xor_sync(0xffffffffu, sum, off, 16);
            lrow[r] = lrow[r] * alpha + sum;
            unsigned long long ad = dup2(alpha);
            fmul2(O2[r][0], ad);
            fmul2(O2[r][1], ad);
        }

        // Store P tile [i][j]
#pragma unroll
        for (int r = 0; r < 8; r++)
            *(float4*)&Ps[(ty * 8 + r) * 68 + tx * 4] = make_float4(s[r][0], s[r][1], s[r][2], s[r][3]);
        __syncthreads();

        // O += P V (outer form over j; dup p to both lanes, pairs along d-cols)
#pragma unroll 4
        for (int j = 0; j < 64; j++) {
            ulonglong2 vv = *(const ulonglong2*)&Vs[j * 68 + tx * 4];
#pragma unroll
            for (int r = 0; r < 8; r++) {
                unsigned long long pd = dup2(Ps[(ty * 8 + r) * 68 + j]);
                ffma2(O2[r][0], pd, vv.x);
                ffma2(O2[r][1], pd, vv.y);
            }
        }
    }

#pragma unroll
    for (int r = 0; r < 8; r++) {
        int row = qt * 128 + ty * 8 + r;
        float inv = 1.f / lrow[r];
        float2 a = u2f(O2[r][0]), b = u2f(O2[r][1]);
        float4 o = make_float4(a.x * inv, a.y * inv, b.x * inv, b.y * inv);
        *(float4*)(g_O + ((size_t)bh * SEQ + row) * 64 + tx * 4) = o;
    }
}

// ---------------------------------------------------------------------------
// Output projection: C[m,e] = sum_k attn[m,k] * Wo[e,k], gathering attn from
// [B,H,S,d] (k = h*64 + j). BM=128, BN=64, BK=32, 8x4 tiles, f32x2.
// ---------------------------------------------------------------------------
__global__ __launch_bounds__(256) void out_gemm(const float* __restrict__ Wo,
                                                float* __restrict__ out) {
    int mt = blockIdx.x;
    int nt = blockIdx.y;

    __shared__ float As[128 * 36];
    __shared__ float Bs[64 * 36];

    int tid = threadIdx.x;
    int tx = tid & 15, ty = tid >> 4;

    int m = mt * 128 + (tid >> 1);
    int b = m >> 11, s = m & 2047;
    const float* Abase = g_O + ((size_t)b * 16 * SEQ + s) * 64;   // + h*SEQ*64 + j
    int klo = (tid & 1) * 16;
    const float* Bp = Wo + (size_t)(nt * 64 + (tid >> 2)) * 1024 + (tid & 3) * 8;
    float* Asw = &As[(tid >> 1) * 36 + klo];
    float* Bsw = &Bs[(tid >> 2) * 36 + (tid & 3) * 8];

    unsigned long long acc[8][4] = {};

    float4 ra[4], rb[2];
#pragma unroll
    for (int i = 0; i < 4; i++) {
        int kg = klo + i * 4;
        ra[i] = *(const float4*)(Abase + (size_t)(kg >> 6) * SEQ * 64 + (kg & 63));
    }
#pragma unroll
    for (int i = 0; i < 2; i++) rb[i] = *(const float4*)(Bp + i * 4);

    for (int k0 = 0; k0 < 1024; k0 += 32) {
        __syncthreads();
#pragma unroll
        for (int i = 0; i < 4; i++) *(float4*)(Asw + i * 4) = ra[i];
#pragma unroll
        for (int i = 0; i < 2; i++) *(float4*)(Bsw + i * 4) = rb[i];
        __syncthreads();
        if (k0 + 32 < 1024) {
#pragma unroll
            for (int i = 0; i < 4; i++) {
                int kg = k0 + 32 + klo + i * 4;
                ra[i] = *(const float4*)(Abase + (size_t)(kg >> 6) * SEQ * 64 + (kg & 63));
            }
#pragma unroll
            for (int i = 0; i < 2; i++) rb[i] = *(const float4*)(Bp + k0 + 32 + i * 4);
        }
#pragma unroll
        for (int kc = 0; kc < 32; kc += 4) {
            ulonglong2 aq[8], bq[4];
#pragma unroll
            for (int r = 0; r < 8; r++) aq[r] = *(const ulonglong2*)&As[(ty * 8 + r) * 36 + kc];
#pragma unroll
            for (int c = 0; c < 4; c++) bq[c] = *(const ulonglong2*)&Bs[(tx * 4 + c) * 36 + kc];
#pragma unroll
            for (int r = 0; r < 8; r++)
#pragma unroll
                for (int c = 0; c < 4; c++) {
                    ffma2(acc[r][c], aq[r].x, bq[c].x);
                    ffma2(acc[r][c], aq[r].y, bq[c].y);
                }
        }
    }

#pragma unroll
    for (int r = 0; r < 8; r++) {
        int mrow = mt * 128 + ty * 8 + r;
        float2 v0 = u2f(acc[r][0]), v1 = u2f(acc[r][1]), v2 = u2f(acc[r][2]), v3 = u2f(acc[r][3]);
        float4 o = make_float4(v0.x + v0.y, v1.x + v1.y, v2.x + v2.y, v3.x + v3.y);
        *(float4*)(out + (size_t)mrow * 1024 + nt * 64 + tx * 4) = o;
    }
}

// ---------------------------------------------------------------------------
extern "C" void kernel_launch(void* const* d_in, const int* in_sizes, int n_in,
                              void* d_out, int out_size) {
    const float* x  = (const float*)d_in[0];
    const int*   tp = (const int*)d_in[1];
    const float* Wq = (const float*)d_in[2];
    const float* Wk = (const float*)d_in[3];
    const float* Wv = (const float*)d_in[4];
    const float* Wo = (const float*)d_in[5];
    float* out = (float*)d_out;

    qkv_gemm<<<dim3(32, 48), 256>>>(x, Wq, Wk, Wv);
    rope_kernel<<<(BH * SEQ * 32) / 256, 256>>>(tp);

    cudaFuncSetAttribute(flash_attn, cudaFuncAttributeMaxDynamicSharedMemorySize, 104448);
    flash_attn<<<dim3(16, 32), 256, 104448>>>();

    out_gemm<<<dim3(32, 16), 256>>>(Wo, out);
}

// round 3
// speedup vs baseline: 1.6024x; 1.6024x over previous
#include <cuda_runtime.h>
#include <math.h>

#define NUM_HEADS 16
#define D_HEAD 64
#define BATCH 2
#define SEQ 2048
#define BH (BATCH*NUM_HEADS)   // 32

// Scratch (no cudaMalloc allowed): [B,H,S,d] fp32 each = 16 MB
__device__ float g_Q[BH*SEQ*D_HEAD];
__device__ float g_K[BH*SEQ*D_HEAD];
__device__ float g_V[BH*SEQ*D_HEAD];
__device__ float g_O[BH*SEQ*D_HEAD];

// ---------------------------------------------------------------------------
// GEMM core: C[m,e] = sum_k A[m,k] * W[e,k]. 128x128 block, BK=16, 256 thr,
// 8x8 per thread (4+4 split). Transposed smem [k][m] / [k][n] so compute
// reads are contiguous along m/n (conflict-free LDS.128).
// ---------------------------------------------------------------------------
__global__ __launch_bounds__(256, 2) void qkv_gemm(const float* __restrict__ x,
                                                   const float* __restrict__ Wq,
                                                   const float* __restrict__ Wk,
                                                   const float* __restrict__ Wv) {
    int mt = blockIdx.x;
    int which = blockIdx.y >> 3;
    int nt = blockIdx.y & 7;
    const float* W = (which == 0) ? Wq : (which == 1) ? Wk : Wv;
    float* out = (which == 0) ? g_Q : (which == 1) ? g_K : g_V;

    __shared__ float As[16][132];
    __shared__ float Bs[16][132];

    int tid = threadIdx.x;
    int tx = tid & 15, ty = tid >> 4;
    int lrow = tid >> 1;             // 0..127
    int lk = (tid & 1) * 8;          // 0 or 8

    const float* Ap = x + (size_t)(mt * 128 + lrow) * 1024 + lk;
    const float* Bp = W + (size_t)(nt * 128 + lrow) * 1024 + lk;

    float acc[8][8] = {};

    float4 ra0 = *(const float4*)(Ap);
    float4 ra1 = *(const float4*)(Ap + 4);
    float4 rb0 = *(const float4*)(Bp);
    float4 rb1 = *(const float4*)(Bp + 4);

    for (int k0 = 0; k0 < 1024; k0 += 16) {
        __syncthreads();
        As[lk + 0][lrow] = ra0.x; As[lk + 1][lrow] = ra0.y; As[lk + 2][lrow] = ra0.z; As[lk + 3][lrow] = ra0.w;
        As[lk + 4][lrow] = ra1.x; As[lk + 5][lrow] = ra1.y; As[lk + 6][lrow] = ra1.z; As[lk + 7][lrow] = ra1.w;
        Bs[lk + 0][lrow] = rb0.x; Bs[lk + 1][lrow] = rb0.y; Bs[lk + 2][lrow] = rb0.z; Bs[lk + 3][lrow] = rb0.w;
        Bs[lk + 4][lrow] = rb1.x; Bs[lk + 5][lrow] = rb1.y; Bs[lk + 6][lrow] = rb1.z; Bs[lk + 7][lrow] = rb1.w;
        __syncthreads();
        if (k0 + 16 < 1024) {
            ra0 = *(const float4*)(Ap + k0 + 16);
            ra1 = *(const float4*)(Ap + k0 + 20);
            rb0 = *(const float4*)(Bp + k0 + 16);
            rb1 = *(const float4*)(Bp + k0 + 20);
        }
#pragma unroll
        for (int kk = 0; kk < 16; kk++) {
            float4 a0 = *(const float4*)&As[kk][ty * 4];
            float4 a1 = *(const float4*)&As[kk][ty * 4 + 64];
            float4 b0 = *(const float4*)&Bs[kk][tx * 4];
            float4 b1 = *(const float4*)&Bs[kk][tx * 4 + 64];
            float ar[8] = {a0.x, a0.y, a0.z, a0.w, a1.x, a1.y, a1.z, a1.w};
            float br[8] = {b0.x, b0.y, b0.z, b0.w, b1.x, b1.y, b1.z, b1.w};
#pragma unroll
            for (int r = 0; r < 8; r++)
#pragma unroll
                for (int c = 0; c < 8; c++)
                    acc[r][c] += ar[r] * br[c];
        }
    }

    // Epilogue into [B,H,S,d]: e = nt*128 + (hj*64 + tx*4 + c); h = nt*2+hj; d = tx*4+c
#pragma unroll
    for (int hi = 0; hi < 2; hi++)
#pragma unroll
        for (int r = 0; r < 4; r++) {
            int m = mt * 128 + hi * 64 + ty * 4 + r;
            int b = m >> 11, s = m & 2047;
#pragma unroll
            for (int hj = 0; hj < 2; hj++) {
                float4 o = make_float4(acc[hi * 4 + r][hj * 4 + 0], acc[hi * 4 + r][hj * 4 + 1],
                                       acc[hi * 4 + r][hj * 4 + 2], acc[hi * 4 + r][hj * 4 + 3]);
                *(float4*)(out + (((size_t)(b * 16 + nt * 2 + hj) * SEQ + s) * 64 + tx * 4)) = o;
            }
        }
}

// ---------------------------------------------------------------------------
// RoPE on Q and K in-place ([B,H,S,d] layout).
// ---------------------------------------------------------------------------
__global__ void rope_kernel(const int* __restrict__ pos) {
    int t = blockIdx.x * blockDim.x + threadIdx.x;
    if (t >= BH * SEQ * 32) return;
    int p = t & 31;
    int s = (t >> 5) & 2047;
    double inv = exp(-(double)p * (9.210340371976184 / 32.0));
    double ang = (double)pos[s] * inv;
    double sn, cs;
    sincos(ang, &sn, &cs);
    float c = (float)cs, sf = (float)sn;

    float2 q = *(float2*)(g_Q + 2 * (size_t)t);
    float2 k = *(float2*)(g_K + 2 * (size_t)t);
    *(float2*)(g_Q + 2 * (size_t)t) = make_float2(q.x * c - q.y * sf, q.x * sf + q.y * c);
    *(float2*)(g_K + 2 * (size_t)t) = make_float2(k.x * c - k.y * sf, k.x * sf + k.y * c);
}

// ---------------------------------------------------------------------------
// Causal flash attention fp32. Br=128, Bc=64, 256 threads, 8x4 thread tiles.
// Qst/Kst transposed [d][i]/[d][j]; V natural [j][d]; P transposed [j][i].
// All compute reads conflict-free LDS.128. 102400B dynamic smem.
// ---------------------------------------------------------------------------
__global__ __launch_bounds__(256) void flash_attn() {
    int qt = gridDim.x - 1 - blockIdx.x;   // longest first
    int bh = blockIdx.y;
    const float* Qp = g_Q + (size_t)bh * SEQ * 64;
    const float* Kp = g_K + (size_t)bh * SEQ * 64;
    const float* Vp = g_V + (size_t)bh * SEQ * 64;

    extern __shared__ float sm[];
    float* Qst = sm;                 // [64][132]  (d, i) pre-scaled 1/8
    float* Kst = Qst + 64 * 132;     // [64][68]   (d, j)
    float* Vs  = Kst + 64 * 68;      // [64][68]   (j, d)
    float* Pt  = Vs + 64 * 68;       // [64][132]  (j, i)

    int tid = threadIdx.x;
    int tx = tid & 15, ty = tid >> 4;

    // Load Q tile (128 rows x 64 d) transposed, scaled
    {
        int row = tid >> 1, d0 = (tid & 1) * 32;
        const float* src = Qp + (size_t)(qt * 128 + row) * 64 + d0;
#pragma unroll
        for (int i = 0; i < 8; i++) {
            float4 q = *(const float4*)(src + i * 4);
            Qst[(d0 + i * 4 + 0) * 132 + row] = q.x * 0.125f;
            Qst[(d0 + i * 4 + 1) * 132 + row] = q.y * 0.125f;
            Qst[(d0 + i * 4 + 2) * 132 + row] = q.z * 0.125f;
            Qst[(d0 + i * 4 + 3) * 132 + row] = q.w * 0.125f;
        }
    }

    float acc[8][4] = {};
    float mrow[8], lrow[8];
#pragma unroll
    for (int r = 0; r < 8; r++) { mrow[r] = -INFINITY; lrow[r] = 0.f; }

    int kmax = 2 * qt + 1;
    for (int kt = 0; kt <= kmax; kt++) {
        __syncthreads();
        {
            int row = tid >> 2, d0 = (tid & 3) * 16;
            const float* ksrc = Kp + (size_t)(kt * 64 + row) * 64 + d0;
            const float* vsrc = Vp + (size_t)(kt * 64 + row) * 64 + d0;
#pragma unroll
            for (int i = 0; i < 4; i++) {
                float4 k = *(const float4*)(ksrc + i * 4);
                Kst[(d0 + i * 4 + 0) * 68 + row] = k.x;
                Kst[(d0 + i * 4 + 1) * 68 + row] = k.y;
                Kst[(d0 + i * 4 + 2) * 68 + row] = k.z;
                Kst[(d0 + i * 4 + 3) * 68 + row] = k.w;
                *(float4*)(Vs + row * 68 + d0 + i * 4) = *(const float4*)(vsrc + i * 4);
            }
        }
        __syncthreads();

        // S = Q K^T (outer form over d)
        float s[8][4] = {};
#pragma unroll 8
        for (int d = 0; d < 64; d++) {
            float4 q0 = *(const float4*)&Qst[d * 132 + ty * 8];
            float4 q1 = *(const float4*)&Qst[d * 132 + ty * 8 + 4];
            float4 kv = *(const float4*)&Kst[d * 68 + tx * 4];
            float qr[8] = {q0.x, q0.y, q0.z, q0.w, q1.x, q1.y, q1.z, q1.w};
            float kr[4] = {kv.x, kv.y, kv.z, kv.w};
#pragma unroll
            for (int r = 0; r < 8; r++)
#pragma unroll
                for (int c = 0; c < 4; c++)
                    s[r][c] += qr[r] * kr[c];
        }

        if (kt >= 2 * qt) {   // diagonal tiles
#pragma unroll
            for (int r = 0; r < 8; r++) {
                int i = qt * 128 + ty * 8 + r;
#pragma unroll
                for (int c = 0; c < 4; c++)
                    if (kt * 64 + tx * 4 + c > i) s[r][c] = -1e30f;
            }
        }

        // Online softmax (rows shared by the 16 tx-lanes)
#pragma unroll
        for (int r = 0; r < 8; r++) {
            float mx = fmaxf(fmaxf(s[r][0], s[r][1]), fmaxf(s[r][2], s[r][3]));
#pragma unroll
            for (int off = 8; off >= 1; off >>= 1)
                mx = fmaxf(mx, __shfl_xor_sync(0xffffffffu, mx, off, 16));
            float mnew = fmaxf(mrow[r], mx);
            float alpha = __expf(mrow[r] - mnew);
            mrow[r] = mnew;
            float sum = 0.f;
#pragma unroll
            for (int c = 0; c < 4; c++) { s[r][c] = __expf(s[r][c] - mnew); sum += s[r][c]; }
#pragma unroll
            for (int off = 8; off >= 1; off >>= 1)
                sum += __shfl_xor_sync(0xffffffffu, sum, off, 16);
            lrow[r] = lrow[r] * alpha + sum;
#pragma unroll
            for (int c = 0; c < 4; c++) acc[r][c] *= alpha;
        }

        // Store P transposed [j][i]
#pragma unroll
        for (int r = 0; r < 8; r++)
#pragma unroll
            for (int c = 0; c < 4; c++)
                Pt[(tx * 4 + c) * 132 + ty * 8 + r] = s[r][c];
        __syncthreads();

        // O += P V (outer form over j)
#pragma unroll 8
        for (int j = 0; j < 64; j++) {
            float4 p0 = *(const float4*)&Pt[j * 132 + ty * 8];
            float4 p1 = *(const float4*)&Pt[j * 132 + ty * 8 + 4];
            float4 vv = *(const float4*)&Vs[j * 68 + tx * 4];
            float pr[8] = {p0.x, p0.y, p0.z, p0.w, p1.x, p1.y, p1.z, p1.w};
            float vr[4] = {vv.x, vv.y, vv.z, vv.w};
#pragma unroll
            for (int r = 0; r < 8; r++)
#pragma unroll
                for (int c = 0; c < 4; c++)
                    acc[r][c] += pr[r] * vr[c];
        }
    }

#pragma unroll
    for (int r = 0; r < 8; r++) {
        int row = qt * 128 + ty * 8 + r;
        float inv = 1.f / lrow[r];
        float4 o = make_float4(acc[r][0] * inv, acc[r][1] * inv, acc[r][2] * inv, acc[r][3] * inv);
        *(float4*)(g_O + ((size_t)bh * SEQ + row) * 64 + tx * 4) = o;
    }
}

// ---------------------------------------------------------------------------
// Output projection: C[m,e] = sum_k attn[m,k] * Wo[e,k], A gathered from
// [B,H,S,d] (k = h*64 + j). Same 128x128 structure.
// ---------------------------------------------------------------------------
__global__ __launch_bounds__(256, 2) void out_gemm(const float* __restrict__ Wo,
                                                   float* __restrict__ out) {
    int mt = blockIdx.x;
    int nt = blockIdx.y;

    __shared__ float As[16][132];
    __shared__ float Bs[16][132];

    int tid = threadIdx.x;
    int tx = tid & 15, ty = tid >> 4;
    int lrow = tid >> 1;
    int lk = (tid & 1) * 8;

    int m = mt * 128 + lrow;
    int b = m >> 11, s = m & 2047;
    const float* Abase = g_O + ((size_t)b * 16 * SEQ + s) * 64;  // + h*SEQ*64 + j
    const float* Bp = Wo + (size_t)(nt * 128 + lrow) * 1024 + lk;

    float acc[8][8] = {};

    // k-chunk of 16 never straddles a 64-boundary (k0 multiple of 16)
    const float* Ap0 = Abase + (size_t)(lk >> 6) * SEQ * 64 + (lk & 63);
    float4 ra0 = *(const float4*)(Ap0);
    float4 ra1 = *(const float4*)(Ap0 + 4);
    float4 rb0 = *(const float4*)(Bp);
    float4 rb1 = *(const float4*)(Bp + 4);

    for (int k0 = 0; k0 < 1024; k0 += 16) {
        __syncthreads();
        As[lk + 0][lrow] = ra0.x; As[lk + 1][lrow] = ra0.y; As[lk + 2][lrow] = ra0.z; As[lk + 3][lrow] = ra0.w;
        As[lk + 4][lrow] = ra1.x; As[lk + 5][lrow] = ra1.y; As[lk + 6][lrow] = ra1.z; As[lk + 7][lrow] = ra1.w;
        Bs[lk + 0][lrow] = rb0.x; Bs[lk + 1][lrow] = rb0.y; Bs[lk + 2][lrow] = rb0.z; Bs[lk + 3][lrow] = rb0.w;
        Bs[lk + 4][lrow] = rb1.x; Bs[lk + 5][lrow] = rb1.y; Bs[lk + 6][lrow] = rb1.z; Bs[lk + 7][lrow] = rb1.w;
        __syncthreads();
        if (k0 + 16 < 1024) {
            int kg = k0 + 16 + lk;
            const float* Ap = Abase + (size_t)(kg >> 6) * SEQ * 64 + (kg & 63);
            ra0 = *(const float4*)(Ap);
            ra1 = *(const float4*)(Ap + 4);
            rb0 = *(const float4*)(Bp + k0 + 16);
            rb1 = *(const float4*)(Bp + k0 + 20);
        }
#pragma unroll
        for (int kk = 0; kk < 16; kk++) {
            float4 a0 = *(const float4*)&As[kk][ty * 4];
            float4 a1 = *(const float4*)&As[kk][ty * 4 + 64];
            float4 b0 = *(const float4*)&Bs[kk][tx * 4];
            float4 b1 = *(const float4*)&Bs[kk][tx * 4 + 64];
            float ar[8] = {a0.x, a0.y, a0.z, a0.w, a1.x, a1.y, a1.z, a1.w};
            float br[8] = {b0.x, b0.y, b0.z, b0.w, b1.x, b1.y, b1.z, b1.w};
#pragma unroll
            for (int r = 0; r < 8; r++)
#pragma unroll
                for (int c = 0; c < 8; c++)
                    acc[r][c] += ar[r] * br[c];
        }
    }

#pragma unroll
    for (int hi = 0; hi < 2; hi++)
#pragma unroll
        for (int r = 0; r < 4; r++) {
            int mrow = mt * 128 + hi * 64 + ty * 4 + r;
#pragma unroll
            for (int hj = 0; hj < 2; hj++) {
                float4 o = make_float4(acc[hi * 4 + r][hj * 4 + 0], acc[hi * 4 + r][hj * 4 + 1],
                                       acc[hi * 4 + r][hj * 4 + 2], acc[hi * 4 + r][hj * 4 + 3]);
                *(float4*)(out + (size_t)mrow * 1024 + nt * 128 + hj * 64 + tx * 4) = o;
            }
        }
}

// ---------------------------------------------------------------------------
extern "C" void kernel_launch(void* const* d_in, const int* in_sizes, int n_in,
                              void* d_out, int out_size) {
    const float* x  = (const float*)d_in[0];
    const int*   tp = (const int*)d_in[1];
    const float* Wq = (const float*)d_in[2];
    const float* Wk = (const float*)d_in[3];
    const float* Wv = (const float*)d_in[4];
    const float* Wo = (const float*)d_in[5];
    float* out = (float*)d_out;

    qkv_gemm<<<dim3(32, 24), 256>>>(x, Wq, Wk, Wv);
    rope_kernel<<<(BH * SEQ * 32) / 256, 256>>>(tp);

    cudaFuncSetAttribute(flash_attn, cudaFuncAttributeMaxDynamicSharedMemorySize, 102400);
    flash_attn<<<dim3(16, 32), 256, 102400>>>();

    out_gemm<<<dim3(32, 8), 256>>>(Wo, out);
}

// round 5
// speedup vs baseline: 1.9224x; 1.1997x over previous
#include <cuda_runtime.h>
#include <cuda_bf16.h>
#include <cstdint>
#include <math.h>

#define NUM_HEADS 16
#define D_HEAD 64
#define BATCH 2
#define SEQ 2048
#define BH (BATCH*NUM_HEADS)

// fp32 scratch
__device__ float g_Q[BH*SEQ*D_HEAD];
__device__ float g_K[BH*SEQ*D_HEAD];
__device__ float g_V[BH*SEQ*D_HEAD];
__device__ float g_O[BH*SEQ*D_HEAD];
// bf16 split planes
__device__ __nv_bfloat16 g_xh[4096*1024];
__device__ __nv_bfloat16 g_xl[4096*1024];
__device__ __nv_bfloat16 g_wh[4*1024*1024];
__device__ __nv_bfloat16 g_wl[4*1024*1024];

// ---- mma helpers ----------------------------------------------------------
__device__ __forceinline__ void ldsm4(unsigned r[4], unsigned addr) {
    asm volatile("ldmatrix.sync.aligned.m8n8.x4.shared.b16 {%0,%1,%2,%3}, [%4];"
                 : "=r"(r[0]), "=r"(r[1]), "=r"(r[2]), "=r"(r[3]) : "r"(addr));
}

__device__ __forceinline__ void mma16816(float c[4], const unsigned a[4], unsigned b0, unsigned b1) {
    asm volatile("mma.sync.aligned.m16n8k16.row.col.f32.bf16.bf16.f32 "
                 "{%0,%1,%2,%3},{%4,%5,%6,%7},{%8,%9},{%0,%1,%2,%3};"
                 : "+f"(c[0]), "+f"(c[1]), "+f"(c[2]), "+f"(c[3])
                 : "r"(a[0]), "r"(a[1]), "r"(a[2]), "r"(a[3]), "r"(b0), "r"(b1));
}

__device__ __forceinline__ unsigned packbf2(float a, float b) {
    __nv_bfloat162 t = __floats2bfloat162_rn(a, b);
    unsigned u;
    memcpy(&u, &t, 4);
    return u;
}

// ---------------------------------------------------------------------------
// Split fp32 -> bf16 hi/lo planes for x and the 4 weight matrices.
// ---------------------------------------------------------------------------
__global__ void convert_split(const float* __restrict__ x,
                              const float* __restrict__ Wq, const float* __restrict__ Wk,
                              const float* __restrict__ Wv, const float* __restrict__ Wo) {
    int which = blockIdx.y;
    const float* src;
    __nv_bfloat16* dh;
    __nv_bfloat16* dl;
    int n;
    if (which == 0) {
        src = x; dh = g_xh; dl = g_xl; n = 4096 * 1024;
    } else {
        src = (which == 1) ? Wq : (which == 2) ? Wk : (which == 3) ? Wv : Wo;
        dh = g_wh + (size_t)(which - 1) * 1048576;
        dl = g_wl + (size_t)(which - 1) * 1048576;
        n = 1048576;
    }
    int i = (blockIdx.x * 256 + threadIdx.x) * 4;
    if (i >= n) return;
    float4 v = *(const float4*)(src + i);
    float f[4] = {v.x, v.y, v.z, v.w};
    __nv_bfloat16 hv[4];
    __nv_bfloat16 lv[4];
#pragma unroll
    for (int j = 0; j < 4; j++) {
        hv[j] = __float2bfloat16(f[j]);
        lv[j] = __float2bfloat16(f[j] - __bfloat162float(hv[j]));
    }
    uint2 hu, lu;
    memcpy(&hu, hv, 8);
    memcpy(&lu, lv, 8);
    *(uint2*)(dh + i) = hu;
    *(uint2*)(dl + i) = lu;
}

// ---------------------------------------------------------------------------
// mma compute for one 32-wide k chunk. 8 warps (4m x 2n), warp tile 32x64.
// Smem tiles 128 rows x 32 bf16, row stride 40.
// ---------------------------------------------------------------------------
__device__ __forceinline__ void mma_chunk(unsigned ah, unsigned al, unsigned bh, unsigned bl,
                                          int lane, int warp_m, int warp_n, float acc[2][8][4]) {
#pragma unroll
    for (int kk = 0; kk < 32; kk += 16) {
        int col = kk + ((lane >> 4) << 3);
        int arow = warp_m * 32 + (lane & 15);
        int brow = warp_n * 64 + (lane & 15);
        unsigned afh[2][4];
        unsigned afl[2][4];
#pragma unroll
        for (int tm = 0; tm < 2; tm++) {
            ldsm4(afh[tm], ah + (unsigned)(((arow + tm * 16) * 40 + col) * 2));
            ldsm4(afl[tm], al + (unsigned)(((arow + tm * 16) * 40 + col) * 2));
        }
        unsigned bfh[4][4];
        unsigned bfl[4][4];
#pragma unroll
        for (int tg = 0; tg < 4; tg++) {
            ldsm4(bfh[tg], bh + (unsigned)(((brow + tg * 16) * 40 + col) * 2));
            ldsm4(bfl[tg], bl + (unsigned)(((brow + tg * 16) * 40 + col) * 2));
        }
#pragma unroll
        for (int tm = 0; tm < 2; tm++) {
#pragma unroll
            for (int tn = 0; tn < 8; tn++) {
                int tg = tn >> 1;
                int idx = tn & 1;
                mma16816(acc[tm][tn], afh[tm], bfh[tg][idx], bfh[tg][idx + 2]);
                mma16816(acc[tm][tn], afh[tm], bfl[tg][idx], bfl[tg][idx + 2]);
                mma16816(acc[tm][tn], afl[tm], bfh[tg][idx], bfh[tg][idx + 2]);
            }
        }
    }
}

// ---------------------------------------------------------------------------
// QKV projection via tensor cores. grid (32, 24): y>>3 = which, y&7 = ntile.
// ---------------------------------------------------------------------------
__global__ __launch_bounds__(256) void qkv_mma() {
    int mt = blockIdx.x;
    int which = blockIdx.y >> 3;
    int nt = blockIdx.y & 7;
    float* out = (which == 0) ? g_Q : (which == 1) ? g_K : g_V;

    __shared__ __nv_bfloat16 Ah[128 * 40];
    __shared__ __nv_bfloat16 Al[128 * 40];
    __shared__ __nv_bfloat16 Bh[128 * 40];
    __shared__ __nv_bfloat16 Bl[128 * 40];
    unsigned ah = (unsigned)__cvta_generic_to_shared(Ah);
    unsigned al = (unsigned)__cvta_generic_to_shared(Al);
    unsigned bh = (unsigned)__cvta_generic_to_shared(Bh);
    unsigned bl = (unsigned)__cvta_generic_to_shared(Bl);

    int tid = threadIdx.x;
    int lane = tid & 31;
    int wid = tid >> 5;
    int warp_m = wid >> 1;
    int warp_n = wid & 1;
    int lrow = tid >> 1;
    int seg = (tid & 1) * 16;

    const uint4* pAh = (const uint4*)(g_xh + (size_t)(mt * 128 + lrow) * 1024 + seg);
    const uint4* pAl = (const uint4*)(g_xl + (size_t)(mt * 128 + lrow) * 1024 + seg);
    const uint4* pBh = (const uint4*)(g_wh + (size_t)which * 1048576 + (size_t)(nt * 128 + lrow) * 1024 + seg);
    const uint4* pBl = (const uint4*)(g_wl + (size_t)which * 1048576 + (size_t)(nt * 128 + lrow) * 1024 + seg);

    float acc[2][8][4] = {};
    uint4 rah0 = pAh[0], rah1 = pAh[1];
    uint4 ral0 = pAl[0], ral1 = pAl[1];
    uint4 rbh0 = pBh[0], rbh1 = pBh[1];
    uint4 rbl0 = pBl[0], rbl1 = pBl[1];

    for (int c = 0; c < 32; c++) {
        __syncthreads();
        *(uint4*)&Ah[lrow * 40 + seg] = rah0;
        *(uint4*)&Ah[lrow * 40 + seg + 8] = rah1;
        *(uint4*)&Al[lrow * 40 + seg] = ral0;
        *(uint4*)&Al[lrow * 40 + seg + 8] = ral1;
        *(uint4*)&Bh[lrow * 40 + seg] = rbh0;
        *(uint4*)&Bh[lrow * 40 + seg + 8] = rbh1;
        *(uint4*)&Bl[lrow * 40 + seg] = rbl0;
        *(uint4*)&Bl[lrow * 40 + seg + 8] = rbl1;
        __syncthreads();
        if (c < 31) {
            int o = (c + 1) * 4;
            rah0 = pAh[o]; rah1 = pAh[o + 1];
            ral0 = pAl[o]; ral1 = pAl[o + 1];
            rbh0 = pBh[o]; rbh1 = pBh[o + 1];
            rbl0 = pBl[o]; rbl1 = pBl[o + 1];
        }
        mma_chunk(ah, al, bh, bl, lane, warp_m, warp_n, acc);
    }

    int head = nt * 2 + warp_n;
#pragma unroll
    for (int tm = 0; tm < 2; tm++) {
#pragma unroll
        for (int tn = 0; tn < 8; tn++) {
            int m0 = mt * 128 + warp_m * 32 + tm * 16 + (lane >> 2);
            int d = tn * 8 + (lane & 3) * 2;
#pragma unroll
            for (int half = 0; half < 2; half++) {
                int m = m0 + half * 8;
                int b = m >> 11;
                int s = m & 2047;
                float2 v = make_float2(acc[tm][tn][half * 2], acc[tm][tn][half * 2 + 1]);
                *(float2*)(out + (((size_t)(b * 16 + head) * SEQ + s) * 64 + d)) = v;
            }
        }
    }
}

// ---------------------------------------------------------------------------
// Output projection via tensor cores; A gathered+split on the fly from g_O.
// ---------------------------------------------------------------------------
__global__ __launch_bounds__(256) void out_mma(float* __restrict__ out) {
    int mt = blockIdx.x;
    int nt = blockIdx.y;

    __shared__ __nv_bfloat16 Ah[128 * 40];
    __shared__ __nv_bfloat16 Al[128 * 40];
    __shared__ __nv_bfloat16 Bh[128 * 40];
    __shared__ __nv_bfloat16 Bl[128 * 40];
    unsigned ah = (unsigned)__cvta_generic_to_shared(Ah);
    unsigned al = (unsigned)__cvta_generic_to_shared(Al);
    unsigned bh = (unsigned)__cvta_generic_to_shared(Bh);
    unsigned bl = (unsigned)__cvta_generic_to_shared(Bl);

    int tid = threadIdx.x;
    int lane = tid & 31;
    int wid = tid >> 5;
    int warp_m = wid >> 1;
    int warp_n = wid & 1;
    int lrow = tid >> 1;
    int seg = (tid & 1) * 16;

    int m = mt * 128 + lrow;
    int b = m >> 11;
    int s = m & 2047;
    const float* Abase = g_O + ((size_t)b * 16 * SEQ + s) * 64;
    const uint4* pBh = (const uint4*)(g_wh + (size_t)3 * 1048576 + (size_t)(nt * 128 + lrow) * 1024 + seg);
    const uint4* pBl = (const uint4*)(g_wl + (size_t)3 * 1048576 + (size_t)(nt * 128 + lrow) * 1024 + seg);

    float acc[2][8][4] = {};

    float raf[16];
    {
        const float* Ap = Abase + (size_t)(seg >> 6) * SEQ * 64 + (seg & 63);
#pragma unroll
        for (int i = 0; i < 4; i++) {
            *(float4*)&raf[i * 4] = *(const float4*)(Ap + i * 4);
        }
    }
    uint4 rbh0 = pBh[0], rbh1 = pBh[1];
    uint4 rbl0 = pBl[0], rbl1 = pBl[1];

    for (int c = 0; c < 32; c++) {
        __syncthreads();
        {
            unsigned ph[8];
            unsigned pl[8];
#pragma unroll
            for (int i = 0; i < 8; i++) {
                float fa = raf[2 * i];
                float fb = raf[2 * i + 1];
                __nv_bfloat16 ha = __float2bfloat16(fa);
                __nv_bfloat16 hb = __float2bfloat16(fb);
                ph[i] = packbf2(fa, fb);
                pl[i] = packbf2(fa - __bfloat162float(ha), fb - __bfloat162float(hb));
            }
            *(uint4*)&Ah[lrow * 40 + seg] = *(uint4*)&ph[0];
            *(uint4*)&Ah[lrow * 40 + seg + 8] = *(uint4*)&ph[4];
            *(uint4*)&Al[lrow * 40 + seg] = *(uint4*)&pl[0];
            *(uint4*)&Al[lrow * 40 + seg + 8] = *(uint4*)&pl[4];
        }
        *(uint4*)&Bh[lrow * 40 + seg] = rbh0;
        *(uint4*)&Bh[lrow * 40 + seg + 8] = rbh1;
        *(uint4*)&Bl[lrow * 40 + seg] = rbl0;
        *(uint4*)&Bl[lrow * 40 + seg + 8] = rbl1;
        __syncthreads();
        if (c < 31) {
            int k = (c + 1) * 32 + seg;
            const float* Ap = Abase + (size_t)(k >> 6) * SEQ * 64 + (k & 63);
#pragma unroll
            for (int i = 0; i < 4; i++) {
                *(float4*)&raf[i * 4] = *(const float4*)(Ap + i * 4);
            }
            int o = (c + 1) * 4;
            rbh0 = pBh[o]; rbh1 = pBh[o + 1];
            rbl0 = pBl[o]; rbl1 = pBl[o + 1];
        }
        mma_chunk(ah, al, bh, bl, lane, warp_m, warp_n, acc);
    }

#pragma unroll
    for (int tm = 0; tm < 2; tm++) {
#pragma unroll
        for (int tn = 0; tn < 8; tn++) {
            int m0 = mt * 128 + warp_m * 32 + tm * 16 + (lane >> 2);
            int e = nt * 128 + warp_n * 64 + tn * 8 + (lane & 3) * 2;
#pragma unroll
            for (int half = 0; half < 2; half++) {
                int mr = m0 + half * 8;
                float2 v = make_float2(acc[tm][tn][half * 2], acc[tm][tn][half * 2 + 1]);
                *(float2*)(out + (size_t)mr * 1024 + e) = v;
            }
        }
    }
}

// ---------------------------------------------------------------------------
// RoPE on Q and K in-place ([B,H,S,d] layout).
// ---------------------------------------------------------------------------
__global__ void rope_kernel(const int* __restrict__ pos) {
    int t = blockIdx.x * blockDim.x + threadIdx.x;
    if (t >= BH * SEQ * 32) return;
    int p = t & 31;
    int s = (t >> 5) & 2047;
    double inv = exp(-(double)p * (9.210340371976184 / 32.0));
    double ang = (double)pos[s] * inv;
    double sn, cs;
    sincos(ang, &sn, &cs);
    float c = (float)cs;
    float sf = (float)sn;

    float2 q = *(float2*)(g_Q + 2 * (size_t)t);
    float2 k = *(float2*)(g_K + 2 * (size_t)t);
    *(float2*)(g_Q + 2 * (size_t)t) = make_float2(q.x * c - q.y * sf, q.x * sf + q.y * c);
    *(float2*)(g_K + 2 * (size_t)t) = make_float2(k.x * c - k.y * sf, k.x * sf + k.y * c);
}

// ---------------------------------------------------------------------------
// Causal flash attention fp32 (unchanged from R3).
// ---------------------------------------------------------------------------
__global__ __launch_bounds__(256) void flash_attn() {
    int qt = gridDim.x - 1 - blockIdx.x;
    int bh = blockIdx.y;
    const float* Qp = g_Q + (size_t)bh * SEQ * 64;
    const float* Kp = g_K + (size_t)bh * SEQ * 64;
    const float* Vp = g_V + (size_t)bh * SEQ * 64;

    extern __shared__ float sm[];
    float* Qst = sm;
    float* Kst = Qst + 64 * 132;
    float* Vs  = Kst + 64 * 68;
    float* Pt  = Vs + 64 * 68;

    int tid = threadIdx.x;
    int tx = tid & 15;
    int ty = tid >> 4;

    {
        int row = tid >> 1;
        int d0 = (tid & 1) * 32;
        const float* src = Qp + (size_t)(qt * 128 + row) * 64 + d0;
#pragma unroll
        for (int i = 0; i < 8; i++) {
            float4 q = *(const float4*)(src + i * 4);
            Qst[(d0 + i * 4 + 0) * 132 + row] = q.x * 0.125f;
            Qst[(d0 + i * 4 + 1) * 132 + row] = q.y * 0.125f;
            Qst[(d0 + i * 4 + 2) * 132 + row] = q.z * 0.125f;
            Qst[(d0 + i * 4 + 3) * 132 + row] = q.w * 0.125f;
        }
    }

    float acc[8][4] = {};
    float mrow[8];
    float lrow[8];
#pragma unroll
    for (int r = 0; r < 8; r++) {
        mrow[r] = -INFINITY;
        lrow[r] = 0.f;
    }

    int kmax = 2 * qt + 1;
    for (int kt = 0; kt <= kmax; kt++) {
        __syncthreads();
        {
            int row = tid >> 2;
            int d0 = (tid & 3) * 16;
            const float* ksrc = Kp + (size_t)(kt * 64 + row) * 64 + d0;
            const float* vsrc = Vp + (size_t)(kt * 64 + row) * 64 + d0;
#pragma unroll
            for (int i = 0; i < 4; i++) {
                float4 k = *(const float4*)(ksrc + i * 4);
                Kst[(d0 + i * 4 + 0) * 68 + row] = k.x;
                Kst[(d0 + i * 4 + 1) * 68 + row] = k.y;
                Kst[(d0 + i * 4 + 2) * 68 + row] = k.z;
                Kst[(d0 + i * 4 + 3) * 68 + row] = k.w;
                *(float4*)(Vs + row * 68 + d0 + i * 4) = *(const float4*)(vsrc + i * 4);
            }
        }
        __syncthreads();

        float s[8][4] = {};
#pragma unroll 8
        for (int d = 0; d < 64; d++) {
            float4 q0 = *(const float4*)&Qst[d * 132 + ty * 8];
            float4 q1 = *(const float4*)&Qst[d * 132 + ty * 8 + 4];
            float4 kv = *(const float4*)&Kst[d * 68 + tx * 4];
            float qr[8] = {q0.x, q0.y, q0.z, q0.w, q1.x, q1.y, q1.z, q1.w};
            float kr[4] = {kv.x, kv.y, kv.z, kv.w};
#pragma unroll
            for (int r = 0; r < 8; r++) {
#pragma unroll
                for (int c = 0; c < 4; c++) {
                    s[r][c] += qr[r] * kr[c];
                }
            }
        }

        if (kt >= 2 * qt) {
#pragma unroll
            for (int r = 0; r < 8; r++) {
                int i = qt * 128 + ty * 8 + r;
#pragma unroll
                for (int c = 0; c < 4; c++) {
                    if (kt * 64 + tx * 4 + c > i) s[r][c] = -1e30f;
                }
            }
        }

#pragma unroll
        for (int r = 0; r < 8; r++) {
            float mx = fmaxf(fmaxf(s[r][0], s[r][1]), fmaxf(s[r][2], s[r][3]));
#pragma unroll
            for (int off = 8; off >= 1; off >>= 1) {
                mx = fmaxf(mx, __shfl_xor_sync(0xffffffffu, mx, off, 16));
            }
            float mnew = fmaxf(mrow[r], mx);
            float alpha = __expf(mrow[r] - mnew);
            mrow[r] = mnew;
            float sum = 0.f;
#pragma unroll
            for (int c = 0; c < 4; c++) {
                s[r][c] = __expf(s[r][c] - mnew);
                sum += s[r][c];
            }
#pragma unroll
            for (int off = 8; off >= 1; off >>= 1) {
                sum += __shfl_xor_sync(0xffffffffu, sum, off, 16);
            }
            lrow[r] = lrow[r] * alpha + sum;
#pragma unroll
            for (int c = 0; c < 4; c++) acc[r][c] *= alpha;
        }

#pragma unroll
        for (int r = 0; r < 8; r++) {
#pragma unroll
            for (int c = 0; c < 4; c++) {
                Pt[(tx * 4 + c) * 132 + ty * 8 + r] = s[r][c];
            }
        }
        __syncthreads();

#pragma unroll 8
        for (int j = 0; j < 64; j++) {
            float4 p0 = *(const float4*)&Pt[j * 132 + ty * 8];
            float4 p1 = *(const float4*)&Pt[j * 132 + ty * 8 + 4];
            float4 vv = *(const float4*)&Vs[j * 68 + tx * 4];
            float pr[8] = {p0.x, p0.y, p0.z, p0.w, p1.x, p1.y, p1.z, p1.w};
            float vr[4] = {vv.x, vv.y, vv.z, vv.w};
#pragma unroll
            for (int r = 0; r < 8; r++) {
#pragma unroll
                for (int c = 0; c < 4; c++) {
                    acc[r][c] += pr[r] * vr[c];
                }
            }
        }
    }

#pragma unroll
    for (int r = 0; r < 8; r++) {
        int row = qt * 128 + ty * 8 + r;
        float inv = 1.f / lrow[r];
        float4 o = make_float4(acc[r][0] * inv, acc[r][1] * inv, acc[r][2] * inv, acc[r][3] * inv);
        *(float4*)(g_O + ((size_t)bh * SEQ + row) * 64 + tx * 4) = o;
    }
}

// ---------------------------------------------------------------------------
extern "C" void kernel_launch(void* const* d_in, const int* in_sizes, int n_in,
                              void* d_out, int out_size) {
    const float* x  = (const float*)d_in[0];
    const int*   tp = (const int*)d_in[1];
    const float* Wq = (const float*)d_in[2];
    const float* Wk = (const float*)d_in[3];
    const float* Wv = (const float*)d_in[4];
    const float* Wo = (const float*)d_in[5];
    float* out = (float*)d_out;

    convert_split<<<dim3(4096, 5), 256>>>(x, Wq, Wk, Wv, Wo);
    qkv_mma<<<dim3(32, 24), 256>>>();
    rope_kernel<<<(BH * SEQ * 32) / 256, 256>>>(tp);

    cudaFuncSetAttribute(flash_attn, cudaFuncAttributeMaxDynamicSharedMemorySize, 102400);
    flash_attn<<<dim3(16, 32), 256, 102400>>>();

    out_mma<<<dim3(32, 8), 256>>>(out);
}

// round 6
// speedup vs baseline: 2.9005x; 1.5088x over previous
#include <cuda_runtime.h>
#include <cuda_bf16.h>
#include <cstdint>
#include <math.h>

#define NUM_HEADS 16
#define D_HEAD 64
#define BATCH 2
#define SEQ 2048
#define BH (BATCH*NUM_HEADS)
#define SCALE_LOG2E 0.18033688011112042f   // 0.125 * log2(e)

// fp32 scratch
__device__ float g_Q[BH*SEQ*D_HEAD];
__device__ float g_K[BH*SEQ*D_HEAD];
__device__ float g_V[BH*SEQ*D_HEAD];
__device__ float g_O[BH*SEQ*D_HEAD];
// bf16 split planes for GEMMs
__device__ __nv_bfloat16 g_xh[4096*1024];
__device__ __nv_bfloat16 g_xl[4096*1024];
__device__ __nv_bfloat16 g_wh[4*1024*1024];
__device__ __nv_bfloat16 g_wl[4*1024*1024];
// bf16 split planes for attention (post-RoPE)
__device__ __nv_bfloat16 g_Qh[BH*SEQ*D_HEAD];
__device__ __nv_bfloat16 g_Ql[BH*SEQ*D_HEAD];
__device__ __nv_bfloat16 g_Kh[BH*SEQ*D_HEAD];
__device__ __nv_bfloat16 g_Kl[BH*SEQ*D_HEAD];
__device__ __nv_bfloat16 g_Vh[BH*SEQ*D_HEAD];
__device__ __nv_bfloat16 g_Vl[BH*SEQ*D_HEAD];

// ---- helpers ---------------------------------------------------------------
__device__ __forceinline__ void ldsm4(unsigned r[4], unsigned addr) {
    asm volatile("ldmatrix.sync.aligned.m8n8.x4.shared.b16 {%0,%1,%2,%3}, [%4];"
                 : "=r"(r[0]), "=r"(r[1]), "=r"(r[2]), "=r"(r[3]) : "r"(addr));
}
__device__ __forceinline__ void ldsm4t(unsigned r[4], unsigned addr) {
    asm volatile("ldmatrix.sync.aligned.m8n8.x4.trans.shared.b16 {%0,%1,%2,%3}, [%4];"
                 : "=r"(r[0]), "=r"(r[1]), "=r"(r[2]), "=r"(r[3]) : "r"(addr));
}
__device__ __forceinline__ void mma16816(float c[4], const unsigned a[4], unsigned b0, unsigned b1) {
    asm volatile("mma.sync.aligned.m16n8k16.row.col.f32.bf16.bf16.f32 "
                 "{%0,%1,%2,%3},{%4,%5,%6,%7},{%8,%9},{%0,%1,%2,%3};"
                 : "+f"(c[0]), "+f"(c[1]), "+f"(c[2]), "+f"(c[3])
                 : "r"(a[0]), "r"(a[1]), "r"(a[2]), "r"(a[3]), "r"(b0), "r"(b1));
}
__device__ __forceinline__ unsigned packbf2(float a, float b) {
    __nv_bfloat162 t = __floats2bfloat162_rn(a, b);
    unsigned u;
    memcpy(&u, &t, 4);
    return u;
}
__device__ __forceinline__ float exp2a(float x) {
    float y;
    asm("ex2.approx.f32 %0, %1;" : "=f"(y) : "f"(x));
    return y;
}

// ---------------------------------------------------------------------------
// Split fp32 -> bf16 hi/lo planes for x and the 4 weight matrices.
// ---------------------------------------------------------------------------
__global__ void convert_split(const float* __restrict__ x,
                              const float* __restrict__ Wq, const float* __restrict__ Wk,
                              const float* __restrict__ Wv, const float* __restrict__ Wo) {
    int which = blockIdx.y;
    const float* src;
    __nv_bfloat16* dh;
    __nv_bfloat16* dl;
    int n;
    if (which == 0) {
        src = x; dh = g_xh; dl = g_xl; n = 4096 * 1024;
    } else {
        src = (which == 1) ? Wq : (which == 2) ? Wk : (which == 3) ? Wv : Wo;
        dh = g_wh + (size_t)(which - 1) * 1048576;
        dl = g_wl + (size_t)(which - 1) * 1048576;
        n = 1048576;
    }
    int i = (blockIdx.x * 256 + threadIdx.x) * 4;
    if (i >= n) return;
    float4 v = *(const float4*)(src + i);
    float f[4] = {v.x, v.y, v.z, v.w};
    __nv_bfloat16 hv[4];
    __nv_bfloat16 lv[4];
#pragma unroll
    for (int j = 0; j < 4; j++) {
        hv[j] = __float2bfloat16(f[j]);
        lv[j] = __float2bfloat16(f[j] - __bfloat162float(hv[j]));
    }
    uint2 hu, lu;
    memcpy(&hu, hv, 8);
    memcpy(&lu, lv, 8);
    *(uint2*)(dh + i) = hu;
    *(uint2*)(dl + i) = lu;
}

// ---------------------------------------------------------------------------
// mma compute for one 32-wide k chunk of the projection GEMMs.
// ---------------------------------------------------------------------------
__device__ __forceinline__ void mma_chunk(unsigned ah, unsigned al, unsigned bh, unsigned bl,
                                          int lane, int warp_m, int warp_n, float acc[2][8][4]) {
#pragma unroll
    for (int kk = 0; kk < 32; kk += 16) {
        int col = kk + ((lane >> 4) << 3);
        int arow = warp_m * 32 + (lane & 15);
        int brow = warp_n * 64 + (lane & 15);
        unsigned afh[2][4];
        unsigned afl[2][4];
#pragma unroll
        for (int tm = 0; tm < 2; tm++) {
            ldsm4(afh[tm], ah + (unsigned)(((arow + tm * 16) * 40 + col) * 2));
            ldsm4(afl[tm], al + (unsigned)(((arow + tm * 16) * 40 + col) * 2));
        }
        unsigned bfh[4][4];
        unsigned bfl[4][4];
#pragma unroll
        for (int tg = 0; tg < 4; tg++) {
            ldsm4(bfh[tg], bh + (unsigned)(((brow + tg * 16) * 40 + col) * 2));
            ldsm4(bfl[tg], bl + (unsigned)(((brow + tg * 16) * 40 + col) * 2));
        }
#pragma unroll
        for (int tm = 0; tm < 2; tm++) {
#pragma unroll
            for (int tn = 0; tn < 8; tn++) {
                int tg = tn >> 1;
                int idx = tn & 1;
                mma16816(acc[tm][tn], afh[tm], bfh[tg][idx], bfh[tg][idx + 2]);
                mma16816(acc[tm][tn], afh[tm], bfl[tg][idx], bfl[tg][idx + 2]);
                mma16816(acc[tm][tn], afl[tm], bfh[tg][idx], bfh[tg][idx + 2]);
            }
        }
    }
}

// ---------------------------------------------------------------------------
// QKV projection via tensor cores.
// ---------------------------------------------------------------------------
__global__ __launch_bounds__(256) void qkv_mma() {
    int mt = blockIdx.x;
    int which = blockIdx.y >> 3;
    int nt = blockIdx.y & 7;
    float* out = (which == 0) ? g_Q : (which == 1) ? g_K : g_V;

    __shared__ __nv_bfloat16 Ah[128 * 40];
    __shared__ __nv_bfloat16 Al[128 * 40];
    __shared__ __nv_bfloat16 Bh[128 * 40];
    __shared__ __nv_bfloat16 Bl[128 * 40];
    unsigned ah = (unsigned)__cvta_generic_to_shared(Ah);
    unsigned al = (unsigned)__cvta_generic_to_shared(Al);
    unsigned bh = (unsigned)__cvta_generic_to_shared(Bh);
    unsigned bl = (unsigned)__cvta_generic_to_shared(Bl);

    int tid = threadIdx.x;
    int lane = tid & 31;
    int wid = tid >> 5;
    int warp_m = wid >> 1;
    int warp_n = wid & 1;
    int lrow = tid >> 1;
    int seg = (tid & 1) * 16;

    const uint4* pAh = (const uint4*)(g_xh + (size_t)(mt * 128 + lrow) * 1024 + seg);
    const uint4* pAl = (const uint4*)(g_xl + (size_t)(mt * 128 + lrow) * 1024 + seg);
    const uint4* pBh = (const uint4*)(g_wh + (size_t)which * 1048576 + (size_t)(nt * 128 + lrow) * 1024 + seg);
    const uint4* pBl = (const uint4*)(g_wl + (size_t)which * 1048576 + (size_t)(nt * 128 + lrow) * 1024 + seg);

    float acc[2][8][4] = {};
    uint4 rah0 = pAh[0], rah1 = pAh[1];
    uint4 ral0 = pAl[0], ral1 = pAl[1];
    uint4 rbh0 = pBh[0], rbh1 = pBh[1];
    uint4 rbl0 = pBl[0], rbl1 = pBl[1];

    for (int c = 0; c < 32; c++) {
        __syncthreads();
        *(uint4*)&Ah[lrow * 40 + seg] = rah0;
        *(uint4*)&Ah[lrow * 40 + seg + 8] = rah1;
        *(uint4*)&Al[lrow * 40 + seg] = ral0;
        *(uint4*)&Al[lrow * 40 + seg + 8] = ral1;
        *(uint4*)&Bh[lrow * 40 + seg] = rbh0;
        *(uint4*)&Bh[lrow * 40 + seg + 8] = rbh1;
        *(uint4*)&Bl[lrow * 40 + seg] = rbl0;
        *(uint4*)&Bl[lrow * 40 + seg + 8] = rbl1;
        __syncthreads();
        if (c < 31) {
            int o = (c + 1) * 4;
            rah0 = pAh[o]; rah1 = pAh[o + 1];
            ral0 = pAl[o]; ral1 = pAl[o + 1];
            rbh0 = pBh[o]; rbh1 = pBh[o + 1];
            rbl0 = pBl[o]; rbl1 = pBl[o + 1];
        }
        mma_chunk(ah, al, bh, bl, lane, warp_m, warp_n, acc);
    }

    int head = nt * 2 + warp_n;
#pragma unroll
    for (int tm = 0; tm < 2; tm++) {
#pragma unroll
        for (int tn = 0; tn < 8; tn++) {
            int m0 = mt * 128 + warp_m * 32 + tm * 16 + (lane >> 2);
            int d = tn * 8 + (lane & 3) * 2;
#pragma unroll
            for (int half = 0; half < 2; half++) {
                int m = m0 + half * 8;
                int b = m >> 11;
                int s = m & 2047;
                float2 v = make_float2(acc[tm][tn][half * 2], acc[tm][tn][half * 2 + 1]);
                *(float2*)(out + (((size_t)(b * 16 + head) * SEQ + s) * 64 + d)) = v;
            }
        }
    }
}

// ---------------------------------------------------------------------------
// Output projection via tensor cores; A gathered+split on the fly from g_O.
// ---------------------------------------------------------------------------
__global__ __launch_bounds__(256) void out_mma(float* __restrict__ out) {
    int mt = blockIdx.x;
    int nt = blockIdx.y;

    __shared__ __nv_bfloat16 Ah[128 * 40];
    __shared__ __nv_bfloat16 Al[128 * 40];
    __shared__ __nv_bfloat16 Bh[128 * 40];
    __shared__ __nv_bfloat16 Bl[128 * 40];
    unsigned ah = (unsigned)__cvta_generic_to_shared(Ah);
    unsigned al = (unsigned)__cvta_generic_to_shared(Al);
    unsigned bh = (unsigned)__cvta_generic_to_shared(Bh);
    unsigned bl = (unsigned)__cvta_generic_to_shared(Bl);

    int tid = threadIdx.x;
    int lane = tid & 31;
    int wid = tid >> 5;
    int warp_m = wid >> 1;
    int warp_n = wid & 1;
    int lrow = tid >> 1;
    int seg = (tid & 1) * 16;

    int m = mt * 128 + lrow;
    int b = m >> 11;
    int s = m & 2047;
    const float* Abase = g_O + ((size_t)b * 16 * SEQ + s) * 64;
    const uint4* pBh = (const uint4*)(g_wh + (size_t)3 * 1048576 + (size_t)(nt * 128 + lrow) * 1024 + seg);
    const uint4* pBl = (const uint4*)(g_wl + (size_t)3 * 1048576 + (size_t)(nt * 128 + lrow) * 1024 + seg);

    float acc[2][8][4] = {};

    float raf[16];
    {
        const float* Ap = Abase + (size_t)(seg >> 6) * SEQ * 64 + (seg & 63);
#pragma unroll
        for (int i = 0; i < 4; i++) {
            *(float4*)&raf[i * 4] = *(const float4*)(Ap + i * 4);
        }
    }
    uint4 rbh0 = pBh[0], rbh1 = pBh[1];
    uint4 rbl0 = pBl[0], rbl1 = pBl[1];

    for (int c = 0; c < 32; c++) {
        __syncthreads();
        {
            unsigned ph[8];
            unsigned pl[8];
#pragma unroll
            for (int i = 0; i < 8; i++) {
                float fa = raf[2 * i];
                float fb = raf[2 * i + 1];
                __nv_bfloat16 ha = __float2bfloat16(fa);
                __nv_bfloat16 hb = __float2bfloat16(fb);
                ph[i] = packbf2(fa, fb);
                pl[i] = packbf2(fa - __bfloat162float(ha), fb - __bfloat162float(hb));
            }
            *(uint4*)&Ah[lrow * 40 + seg] = *(uint4*)&ph[0];
            *(uint4*)&Ah[lrow * 40 + seg + 8] = *(uint4*)&ph[4];
            *(uint4*)&Al[lrow * 40 + seg] = *(uint4*)&pl[0];
            *(uint4*)&Al[lrow * 40 + seg + 8] = *(uint4*)&pl[4];
        }
        *(uint4*)&Bh[lrow * 40 + seg] = rbh0;
        *(uint4*)&Bh[lrow * 40 + seg + 8] = rbh1;
        *(uint4*)&Bl[lrow * 40 + seg] = rbl0;
        *(uint4*)&Bl[lrow * 40 + seg + 8] = rbl1;
        __syncthreads();
        if (c < 31) {
            int k = (c + 1) * 32 + seg;
            const float* Ap = Abase + (size_t)(k >> 6) * SEQ * 64 + (k & 63);
#pragma unroll
            for (int i = 0; i < 4; i++) {
                *(float4*)&raf[i * 4] = *(const float4*)(Ap + i * 4);
            }
            int o = (c + 1) * 4;
            rbh0 = pBh[o]; rbh1 = pBh[o + 1];
            rbl0 = pBl[o]; rbl1 = pBl[o + 1];
        }
        mma_chunk(ah, al, bh, bl, lane, warp_m, warp_n, acc);
    }

#pragma unroll
    for (int tm = 0; tm < 2; tm++) {
#pragma unroll
        for (int tn = 0; tn < 8; tn++) {
            int m0 = mt * 128 + warp_m * 32 + tm * 16 + (lane >> 2);
            int e = nt * 128 + warp_n * 64 + tn * 8 + (lane & 3) * 2;
#pragma unroll
            for (int half = 0; half < 2; half++) {
                int mr = m0 + half * 8;
                float2 v = make_float2(acc[tm][tn][half * 2], acc[tm][tn][half * 2 + 1]);
                *(float2*)(out + (size_t)mr * 1024 + e) = v;
            }
        }
    }
}

// ---------------------------------------------------------------------------
// RoPE on Q,K; emit bf16 hi/lo planes (Q pre-scaled to log2-softmax domain)
// and split V to bf16 hi/lo.
// ---------------------------------------------------------------------------
__global__ void rope_split(const int* __restrict__ pos) {
    int t = blockIdx.x * blockDim.x + threadIdx.x;
    if (t >= BH * SEQ * 32) return;
    int p = t & 31;
    int s = (t >> 5) & 2047;
    double inv = exp(-(double)p * (9.210340371976184 / 32.0));
    double ang = (double)pos[s] * inv;
    double sn, cs;
    sincos(ang, &sn, &cs);
    float c = (float)cs;
    float sf = (float)sn;

    float2 q = *(float2*)(g_Q + 2 * (size_t)t);
    float2 k = *(float2*)(g_K + 2 * (size_t)t);
    float2 v = *(float2*)(g_V + 2 * (size_t)t);
    float q0 = (q.x * c - q.y * sf) * SCALE_LOG2E;
    float q1 = (q.x * sf + q.y * c) * SCALE_LOG2E;
    float k0 = k.x * c - k.y * sf;
    float k1 = k.x * sf + k.y * c;

    __nv_bfloat16 qh0 = __float2bfloat16(q0), qh1 = __float2bfloat16(q1);
    __nv_bfloat16 kh0 = __float2bfloat16(k0), kh1 = __float2bfloat16(k1);
    __nv_bfloat16 vh0 = __float2bfloat16(v.x), vh1 = __float2bfloat16(v.y);

    ((unsigned*)g_Qh)[t] = packbf2(q0, q1);
    ((unsigned*)g_Ql)[t] = packbf2(q0 - __bfloat162float(qh0), q1 - __bfloat162float(qh1));
    ((unsigned*)g_Kh)[t] = packbf2(k0, k1);
    ((unsigned*)g_Kl)[t] = packbf2(k0 - __bfloat162float(kh0), k1 - __bfloat162float(kh1));
    ((unsigned*)g_Vh)[t] = packbf2(v.x, v.y);
    ((unsigned*)g_Vl)[t] = packbf2(v.x - __bfloat162float(vh0), v.y - __bfloat162float(vh1));
}

// ---------------------------------------------------------------------------
// Causal flash attention on tensor cores. 128 q-rows/block, 8 warps (16 rows
// each), k-tiles of 64. S via split-3 mma, PV via split-3 (Ph*Vh+Pl*Vh+Ph*Vl),
// P fragments repacked from S accumulators in registers. Base-2 softmax.
// ---------------------------------------------------------------------------
__global__ __launch_bounds__(256) void flash_mma() {
    int qt = gridDim.x - 1 - blockIdx.x;
    int bh = blockIdx.y;
    size_t base = (size_t)bh * SEQ * 64;

    extern __shared__ __nv_bfloat16 smem[];
    __nv_bfloat16* Qhs = smem;                 // [128][72]
    __nv_bfloat16* Qls = Qhs + 128 * 72;       // [128][72]
    __nv_bfloat16* Khs = Qls + 128 * 72;       // [64][72]
    __nv_bfloat16* Kls = Khs + 64 * 72;
    __nv_bfloat16* Vhs = Kls + 64 * 72;
    __nv_bfloat16* Vls = Vhs + 64 * 72;
    unsigned qhsB = (unsigned)__cvta_generic_to_shared(Qhs);
    unsigned qlsB = (unsigned)__cvta_generic_to_shared(Qls);
    unsigned khsB = (unsigned)__cvta_generic_to_shared(Khs);
    unsigned klsB = (unsigned)__cvta_generic_to_shared(Kls);
    unsigned vhsB = (unsigned)__cvta_generic_to_shared(Vhs);
    unsigned vlsB = (unsigned)__cvta_generic_to_shared(Vls);

    int tid = threadIdx.x;
    int lane = tid & 31;
    int w = tid >> 5;

    // Stage Q tile (128x64 bf16, hi+lo)
    {
        int row = tid >> 1;
        int col = (tid & 1) * 32;
        const uint4* sh = (const uint4*)(g_Qh + base + (size_t)(qt * 128 + row) * 64 + col);
        const uint4* sl = (const uint4*)(g_Ql + base + (size_t)(qt * 128 + row) * 64 + col);
        uint4* dh = (uint4*)(Qhs + row * 72 + col);
        uint4* dl = (uint4*)(Qls + row * 72 + col);
#pragma unroll
        for (int i = 0; i < 4; i++) { dh[i] = sh[i]; dl[i] = sl[i]; }
    }
    __syncthreads();

    // Load Q fragments into registers (held for whole kernel)
    unsigned qh[4][4], ql[4][4];
#pragma unroll
    for (int dc = 0; dc < 4; dc++) {
        unsigned off = (unsigned)(((w * 16 + (lane & 15)) * 72 + dc * 16 + 8 * (lane >> 4)) * 2);
        ldsm4(qh[dc], qhsB + off);
        ldsm4(ql[dc], qlsB + off);
    }

    float accO[8][4] = {};
    float mrow[2] = {-INFINITY, -INFINITY};
    float lrow[2] = {0.f, 0.f};

    int kmax = 2 * qt + 1;
    for (int kt = 0; kt <= kmax; kt++) {
        __syncthreads();
        {
            int row = tid >> 2;
            int col = (tid & 3) * 16;
            size_t g = base + (size_t)(kt * 64 + row) * 64 + col;
            const uint4* skh = (const uint4*)(g_Kh + g);
            const uint4* skl = (const uint4*)(g_Kl + g);
            const uint4* svh = (const uint4*)(g_Vh + g);
            const uint4* svl = (const uint4*)(g_Vl + g);
            uint4* dkh = (uint4*)(Khs + row * 72 + col);
            uint4* dkl = (uint4*)(Kls + row * 72 + col);
            uint4* dvh = (uint4*)(Vhs + row * 72 + col);
            uint4* dvl = (uint4*)(Vls + row * 72 + col);
#pragma unroll
            for (int i = 0; i < 2; i++) {
                dkh[i] = skh[i]; dkl[i] = skl[i];
                dvh[i] = svh[i]; dvl[i] = svl[i];
            }
        }
        __syncthreads();

        // S = Q K^T (split-3), fragments per j-tile
        float s[8][4] = {};
#pragma unroll
        for (int dc = 0; dc < 4; dc++) {
            unsigned kh[4][4], kl[4][4];
#pragma unroll
            for (int jt2 = 0; jt2 < 4; jt2++) {
                unsigned off = (unsigned)(((jt2 * 16 + (lane & 15)) * 72 + dc * 16 + 8 * (lane >> 4)) * 2);
                ldsm4(kh[jt2], khsB + off);
                ldsm4(kl[jt2], klsB + off);
            }
#pragma unroll
            for (int jt = 0; jt < 8; jt++) {
                int jt2 = jt >> 1;
                int idx = jt & 1;
                mma16816(s[jt], qh[dc], kh[jt2][idx], kh[jt2][idx + 2]);
                mma16816(s[jt], qh[dc], kl[jt2][idx], kl[jt2][idx + 2]);
                mma16816(s[jt], ql[dc], kh[jt2][idx], kh[jt2][idx + 2]);
            }
        }

        // Causal mask on diagonal tiles
        if (kt >= 2 * qt) {
            int i0 = qt * 128 + w * 16 + (lane >> 2);
            int jb = kt * 64 + (lane & 3) * 2;
#pragma unroll
            for (int jt = 0; jt < 8; jt++) {
                int j = jb + jt * 8;
                if (j > i0) s[jt][0] = -1e30f;
                if (j + 1 > i0) s[jt][1] = -1e30f;
                if (j > i0 + 8) s[jt][2] = -1e30f;
                if (j + 1 > i0 + 8) s[jt][3] = -1e30f;
            }
        }

        // Online softmax, base-2
        float mx0 = -1e30f, mx1 = -1e30f;
#pragma unroll
        for (int jt = 0; jt < 8; jt++) {
            mx0 = fmaxf(mx0, fmaxf(s[jt][0], s[jt][1]));
            mx1 = fmaxf(mx1, fmaxf(s[jt][2], s[jt][3]));
        }
        mx0 = fmaxf(mx0, __shfl_xor_sync(0xffffffffu, mx0, 1));
        mx0 = fmaxf(mx0, __shfl_xor_sync(0xffffffffu, mx0, 2));
        mx1 = fmaxf(mx1, __shfl_xor_sync(0xffffffffu, mx1, 1));
        mx1 = fmaxf(mx1, __shfl_xor_sync(0xffffffffu, mx1, 2));
        float mn0 = fmaxf(mrow[0], mx0);
        float mn1 = fmaxf(mrow[1], mx1);
        float a0 = exp2a(mrow[0] - mn0);
        float a1 = exp2a(mrow[1] - mn1);
        mrow[0] = mn0;
        mrow[1] = mn1;
        float sum0 = 0.f, sum1 = 0.f;
#pragma unroll
        for (int jt = 0; jt < 8; jt++) {
            s[jt][0] = exp2a(s[jt][0] - mn0);
            s[jt][1] = exp2a(s[jt][1] - mn0);
            s[jt][2] = exp2a(s[jt][2] - mn1);
            s[jt][3] = exp2a(s[jt][3] - mn1);
            sum0 += s[jt][0] + s[jt][1];
            sum1 += s[jt][2] + s[jt][3];
        }
        sum0 += __shfl_xor_sync(0xffffffffu, sum0, 1);
        sum0 += __shfl_xor_sync(0xffffffffu, sum0, 2);
        sum1 += __shfl_xor_sync(0xffffffffu, sum1, 1);
        sum1 += __shfl_xor_sync(0xffffffffu, sum1, 2);
        lrow[0] = lrow[0] * a0 + sum0;
        lrow[1] = lrow[1] * a1 + sum1;
#pragma unroll
        for (int dt = 0; dt < 8; dt++) {
            accO[dt][0] *= a0;
            accO[dt][1] *= a0;
            accO[dt][2] *= a1;
            accO[dt][3] *= a1;
        }

        // O += P V (P repacked from s, split; V hi/lo from smem)
#pragma unroll
        for (int kc = 0; kc < 4; kc++) {
            unsigned ph[4], pl[4];
            {
                float p00 = s[2 * kc][0], p01 = s[2 * kc][1], p02 = s[2 * kc][2], p03 = s[2 * kc][3];
                float p10 = s[2 * kc + 1][0], p11 = s[2 * kc + 1][1], p12 = s[2 * kc + 1][2], p13 = s[2 * kc + 1][3];
                ph[0] = packbf2(p00, p01);
                ph[1] = packbf2(p02, p03);
                ph[2] = packbf2(p10, p11);
                ph[3] = packbf2(p12, p13);
                pl[0] = packbf2(p00 - __bfloat162float(__float2bfloat16(p00)), p01 - __bfloat162float(__float2bfloat16(p01)));
                pl[1] = packbf2(p02 - __bfloat162float(__float2bfloat16(p02)), p03 - __bfloat162float(__float2bfloat16(p03)));
                pl[2] = packbf2(p10 - __bfloat162float(__float2bfloat16(p10)), p11 - __bfloat162float(__float2bfloat16(p11)));
                pl[3] = packbf2(p12 - __bfloat162float(__float2bfloat16(p12)), p13 - __bfloat162float(__float2bfloat16(p13)));
            }
            unsigned vh[4][4], vl[4][4];
#pragma unroll
            for (int dt2 = 0; dt2 < 4; dt2++) {
                unsigned off = (unsigned)(((kc * 16 + (lane & 15)) * 72 + dt2 * 16 + 8 * (lane >> 4)) * 2);
                ldsm4t(vh[dt2], vhsB + off);
                ldsm4t(vl[dt2], vlsB + off);
            }
#pragma unroll
            for (int dt = 0; dt < 8; dt++) {
                int dt2 = dt >> 1;
                int o = (dt & 1) * 2;
                mma16816(accO[dt], ph, vh[dt2][o], vh[dt2][o + 1]);
                mma16816(accO[dt], pl, vh[dt2][o], vh[dt2][o + 1]);
                mma16816(accO[dt], ph, vl[dt2][o], vl[dt2][o + 1]);
            }
        }
    }

    // Epilogue
    float inv0 = 1.f / lrow[0];
    float inv1 = 1.f / lrow[1];
    int r0 = qt * 128 + w * 16 + (lane >> 2);
#pragma unroll
    for (int dt = 0; dt < 8; dt++) {
        int d = dt * 8 + (lane & 3) * 2;
        *(float2*)(g_O + base + (size_t)r0 * 64 + d) = make_float2(accO[dt][0] * inv0, accO[dt][1] * inv0);
        *(float2*)(g_O + base + (size_t)(r0 + 8) * 64 + d) = make_float2(accO[dt][2] * inv1, accO[dt][3] * inv1);
    }
}

// ---------------------------------------------------------------------------
extern "C" void kernel_launch(void* const* d_in, const int* in_sizes, int n_in,
                              void* d_out, int out_size) {
    const float* x  = (const float*)d_in[0];
    const int*   tp = (const int*)d_in[1];
    const float* Wq = (const float*)d_in[2];
    const float* Wk = (const float*)d_in[3];
    const float* Wv = (const float*)d_in[4];
    const float* Wo = (const float*)d_in[5];
    float* out = (float*)d_out;

    convert_split<<<dim3(4096, 5), 256>>>(x, Wq, Wk, Wv, Wo);
    qkv_mma<<<dim3(32, 24), 256>>>();
    rope_split<<<(BH * SEQ * 32) / 256, 256>>>(tp);

    cudaFuncSetAttribute(flash_mma, cudaFuncAttributeMaxDynamicSharedMemorySize, 82944);
    flash_mma<<<dim3(16, 32), 256, 82944>>>();

    out_mma<<<dim3(32, 8), 256>>>(out);
}

// round 8
// speedup vs baseline: 2.9812x; 1.0278x over previous
#include <cuda_runtime.h>
#include <cuda_bf16.h>
#include <cstdint>
#include <math.h>

#define NUM_HEADS 16
#define D_HEAD 64
#define BATCH 2
#define SEQ 2048
#define BH (BATCH*NUM_HEADS)
#define SCALE_LOG2E 0.18033688011112042f   // 0.125 * log2(e)

// fp32 scratch
__device__ float g_Q[BH*SEQ*D_HEAD];
__device__ float g_K[BH*SEQ*D_HEAD];
__device__ float g_V[BH*SEQ*D_HEAD];
__device__ float g_O[BH*SEQ*D_HEAD];
// bf16 split planes for GEMMs
__device__ __nv_bfloat16 g_xh[4096*1024];
__device__ __nv_bfloat16 g_xl[4096*1024];
__device__ __nv_bfloat16 g_wh[4*1024*1024];
__device__ __nv_bfloat16 g_wl[4*1024*1024];
// bf16 split planes for attention (post-RoPE)
__device__ __nv_bfloat16 g_Qh[BH*SEQ*D_HEAD];
__device__ __nv_bfloat16 g_Ql[BH*SEQ*D_HEAD];
__device__ __nv_bfloat16 g_Kh[BH*SEQ*D_HEAD];
__device__ __nv_bfloat16 g_Kl[BH*SEQ*D_HEAD];
__device__ __nv_bfloat16 g_Vh[BH*SEQ*D_HEAD];
__device__ __nv_bfloat16 g_Vl[BH*SEQ*D_HEAD];

// ---- helpers ---------------------------------------------------------------
__device__ __forceinline__ void ldsm4(unsigned r[4], unsigned addr) {
    asm volatile("ldmatrix.sync.aligned.m8n8.x4.shared.b16 {%0,%1,%2,%3}, [%4];"
                 : "=r"(r[0]), "=r"(r[1]), "=r"(r[2]), "=r"(r[3]) : "r"(addr));
}
__device__ __forceinline__ void ldsm4t(unsigned r[4], unsigned addr) {
    asm volatile("ldmatrix.sync.aligned.m8n8.x4.trans.shared.b16 {%0,%1,%2,%3}, [%4];"
                 : "=r"(r[0]), "=r"(r[1]), "=r"(r[2]), "=r"(r[3]) : "r"(addr));
}
__device__ __forceinline__ void mma16816(float c[4], const unsigned a[4], unsigned b0, unsigned b1) {
    asm volatile("mma.sync.aligned.m16n8k16.row.col.f32.bf16.bf16.f32 "
                 "{%0,%1,%2,%3},{%4,%5,%6,%7},{%8,%9},{%0,%1,%2,%3};"
                 : "+f"(c[0]), "+f"(c[1]), "+f"(c[2]), "+f"(c[3])
                 : "r"(a[0]), "r"(a[1]), "r"(a[2]), "r"(a[3]), "r"(b0), "r"(b1));
}
__device__ __forceinline__ unsigned packbf2(float a, float b) {
    __nv_bfloat162 t = __floats2bfloat162_rn(a, b);
    unsigned u;
    memcpy(&u, &t, 4);
    return u;
}
__device__ __forceinline__ float exp2a(float x) {
    float y;
    asm("ex2.approx.f32 %0, %1;" : "=f"(y) : "f"(x));
    return y;
}

// ---------------------------------------------------------------------------
// Split fp32 -> bf16 hi/lo planes for x and the 4 weight matrices.
// ---------------------------------------------------------------------------
__global__ void convert_split(const float* __restrict__ x,
                              const float* __restrict__ Wq, const float* __restrict__ Wk,
                              const float* __restrict__ Wv, const float* __restrict__ Wo) {
    int which = blockIdx.y;
    const float* src;
    __nv_bfloat16* dh;
    __nv_bfloat16* dl;
    int n;
    if (which == 0) {
        src = x; dh = g_xh; dl = g_xl; n = 4096 * 1024;
    } else {
        src = (which == 1) ? Wq : (which == 2) ? Wk : (which == 3) ? Wv : Wo;
        dh = g_wh + (size_t)(which - 1) * 1048576;
        dl = g_wl + (size_t)(which - 1) * 1048576;
        n = 1048576;
    }
    int i = (blockIdx.x * 256 + threadIdx.x) * 4;
    if (i >= n) return;
    float4 v = *(const float4*)(src + i);
    float f[4] = {v.x, v.y, v.z, v.w};
    __nv_bfloat16 hv[4];
    __nv_bfloat16 lv[4];
#pragma unroll
    for (int j = 0; j < 4; j++) {
        hv[j] = __float2bfloat16(f[j]);
        lv[j] = __float2bfloat16(f[j] - __bfloat162float(hv[j]));
    }
    uint2 hu, lu;
    memcpy(&hu, hv, 8);
    memcpy(&lu, lv, 8);
    *(uint2*)(dh + i) = hu;
    *(uint2*)(dl + i) = lu;
}

// ---------------------------------------------------------------------------
// mma compute for one 32-wide k chunk of the projection GEMMs.
// ---------------------------------------------------------------------------
__device__ __forceinline__ void mma_chunk(unsigned ah, unsigned al, unsigned bh, unsigned bl,
                                          int lane, int warp_m, int warp_n, float acc[2][8][4]) {
#pragma unroll
    for (int kk = 0; kk < 32; kk += 16) {
        int col = kk + ((lane >> 4) << 3);
        int arow = warp_m * 32 + (lane & 15);
        int brow = warp_n * 64 + (lane & 15);
        unsigned afh[2][4];
        unsigned afl[2][4];
#pragma unroll
        for (int tm = 0; tm < 2; tm++) {
            ldsm4(afh[tm], ah + (unsigned)(((arow + tm * 16) * 40 + col) * 2));
            ldsm4(afl[tm], al + (unsigned)(((arow + tm * 16) * 40 + col) * 2));
        }
        unsigned bfh[4][4];
        unsigned bfl[4][4];
#pragma unroll
        for (int tg = 0; tg < 4; tg++) {
            ldsm4(bfh[tg], bh + (unsigned)(((brow + tg * 16) * 40 + col) * 2));
            ldsm4(bfl[tg], bl + (unsigned)(((brow + tg * 16) * 40 + col) * 2));
        }
#pragma unroll
        for (int tm = 0; tm < 2; tm++) {
#pragma unroll
            for (int tn = 0; tn < 8; tn++) {
                int tg = tn >> 1;
                int idx = tn & 1;
                mma16816(acc[tm][tn], afh[tm], bfh[tg][idx], bfh[tg][idx + 2]);
                mma16816(acc[tm][tn], afh[tm], bfl[tg][idx], bfl[tg][idx + 2]);
                mma16816(acc[tm][tn], afl[tm], bfh[tg][idx], bfh[tg][idx + 2]);
            }
        }
    }
}

// ---------------------------------------------------------------------------
// QKV projection: register-staged double-buffered smem, 1 barrier/iter.
// Dynamic smem: 2 stages x 4 planes x 128x40 bf16 = 81920 B.
// ---------------------------------------------------------------------------
#define QPL (128*40)
#define QST (4*QPL)
__global__ __launch_bounds__(256) void qkv_mma() {
    int mt = blockIdx.x;
    int which = blockIdx.y >> 3;
    int nt = blockIdx.y & 7;
    float* out = (which == 0) ? g_Q : (which == 1) ? g_K : g_V;

    extern __shared__ __nv_bfloat16 dynsm[];
    unsigned sb = (unsigned)__cvta_generic_to_shared(dynsm);

    int tid = threadIdx.x;
    int lane = tid & 31;
    int wid = tid >> 5;
    int warp_m = wid >> 1;
    int warp_n = wid & 1;
    int lrow = tid >> 1;
    int seg = (tid & 1) * 16;

    const __nv_bfloat16* srcs[4];
    srcs[0] = g_xh + (size_t)(mt * 128 + lrow) * 1024 + seg;
    srcs[1] = g_xl + (size_t)(mt * 128 + lrow) * 1024 + seg;
    srcs[2] = g_wh + (size_t)which * 1048576 + (size_t)(nt * 128 + lrow) * 1024 + seg;
    srcs[3] = g_wl + (size_t)which * 1048576 + (size_t)(nt * 128 + lrow) * 1024 + seg;

    float acc[2][8][4] = {};
    uint4 rg[4][2];

    // preload chunk 0 and stage into buffer 0
#pragma unroll
    for (int p = 0; p < 4; p++) {
        rg[p][0] = *(const uint4*)(srcs[p]);
        rg[p][1] = *(const uint4*)(srcs[p] + 8);
    }
    {
        __nv_bfloat16* dst = dynsm + lrow * 40 + seg;
#pragma unroll
        for (int p = 0; p < 4; p++) {
            *(uint4*)(dst + p * QPL) = rg[p][0];
            *(uint4*)(dst + p * QPL + 8) = rg[p][1];
        }
    }
    __syncthreads();

    for (int c = 0; c < 32; c++) {
        int s = c & 1;
        if (c < 31) {
#pragma unroll
            for (int p = 0; p < 4; p++) {
                rg[p][0] = *(const uint4*)(srcs[p] + (c + 1) * 32);
                rg[p][1] = *(const uint4*)(srcs[p] + (c + 1) * 32 + 8);
            }
        }
        unsigned stb = sb + (unsigned)(s * QST * 2);
        mma_chunk(stb, stb + QPL * 2, stb + QPL * 4, stb + QPL * 6,
                  lane, warp_m, warp_n, acc);
        if (c < 31) {
            __nv_bfloat16* dst = dynsm + (s ^ 1) * QST + lrow * 40 + seg;
#pragma unroll
            for (int p = 0; p < 4; p++) {
                *(uint4*)(dst + p * QPL) = rg[p][0];
                *(uint4*)(dst + p * QPL + 8) = rg[p][1];
            }
        }
        __syncthreads();
    }

    int head = nt * 2 + warp_n;
#pragma unroll
    for (int tm = 0; tm < 2; tm++) {
#pragma unroll
        for (int tn = 0; tn < 8; tn++) {
            int m0 = mt * 128 + warp_m * 32 + tm * 16 + (lane >> 2);
            int d = tn * 8 + (lane & 3) * 2;
#pragma unroll
            for (int half = 0; half < 2; half++) {
                int m = m0 + half * 8;
                int b = m >> 11;
                int sq = m & 2047;
                float2 v = make_float2(acc[tm][tn][half * 2], acc[tm][tn][half * 2 + 1]);
                *(float2*)(out + (((size_t)(b * 16 + head) * SEQ + sq) * 64 + d)) = v;
            }
        }
    }
}

// ---------------------------------------------------------------------------
// Output projection: same double-buffer pattern; A gathered+split in regs.
// ---------------------------------------------------------------------------
__global__ __launch_bounds__(256) void out_mma(float* __restrict__ out) {
    int mt = blockIdx.x;
    int nt = blockIdx.y;

    extern __shared__ __nv_bfloat16 dynsm2[];
    unsigned sb = (unsigned)__cvta_generic_to_shared(dynsm2);

    int tid = threadIdx.x;
    int lane = tid & 31;
    int wid = tid >> 5;
    int warp_m = wid >> 1;
    int warp_n = wid & 1;
    int lrow = tid >> 1;
    int seg = (tid & 1) * 16;

    int m = mt * 128 + lrow;
    int b = m >> 11;
    int sq0 = m & 2047;
    const float* Abase = g_O + ((size_t)b * 16 * SEQ + sq0) * 64;
    const __nv_bfloat16* srcBh = g_wh + (size_t)3 * 1048576 + (size_t)(nt * 128 + lrow) * 1024 + seg;
    const __nv_bfloat16* srcBl = g_wl + (size_t)3 * 1048576 + (size_t)(nt * 128 + lrow) * 1024 + seg;

    float acc[2][8][4] = {};
    float raf[16];
    uint4 rbh[2], rbl[2];

    // preload chunk 0
    {
        const float* Ap = Abase + (size_t)(seg >> 6) * SEQ * 64 + (seg & 63);
#pragma unroll
        for (int i = 0; i < 4; i++) *(float4*)&raf[i * 4] = *(const float4*)(Ap + i * 4);
        rbh[0] = *(const uint4*)(srcBh);
        rbh[1] = *(const uint4*)(srcBh + 8);
        rbl[0] = *(const uint4*)(srcBl);
        rbl[1] = *(const uint4*)(srcBl + 8);
    }
    // split + stage buffer 0
    {
        unsigned ph[8], pl[8];
#pragma unroll
        for (int i = 0; i < 8; i++) {
            float fa = raf[2 * i];
            float fb = raf[2 * i + 1];
            __nv_bfloat16 ha = __float2bfloat16(fa);
            __nv_bfloat16 hb = __float2bfloat16(fb);
            ph[i] = packbf2(fa, fb);
            pl[i] = packbf2(fa - __bfloat162float(ha), fb - __bfloat162float(hb));
        }
        __nv_bfloat16* dst = dynsm2 + lrow * 40 + seg;
        *(uint4*)(dst) = *(uint4*)&ph[0];
        *(uint4*)(dst + 8) = *(uint4*)&ph[4];
        *(uint4*)(dst + QPL) = *(uint4*)&pl[0];
        *(uint4*)(dst + QPL + 8) = *(uint4*)&pl[4];
        *(uint4*)(dst + QPL * 2) = rbh[0];
        *(uint4*)(dst + QPL * 2 + 8) = rbh[1];
        *(uint4*)(dst + QPL * 3) = rbl[0];
        *(uint4*)(dst + QPL * 3 + 8) = rbl[1];
    }
    __syncthreads();

    for (int c = 0; c < 32; c++) {
        int s = c & 1;
        if (c < 31) {
            int k = (c + 1) * 32 + seg;
            const float* Ap = Abase + (size_t)(k >> 6) * SEQ * 64 + (k & 63);
#pragma unroll
            for (int i = 0; i < 4; i++) *(float4*)&raf[i * 4] = *(const float4*)(Ap + i * 4);
            rbh[0] = *(const uint4*)(srcBh + (c + 1) * 32);
            rbh[1] = *(const uint4*)(srcBh + (c + 1) * 32 + 8);
            rbl[0] = *(const uint4*)(srcBl + (c + 1) * 32);
            rbl[1] = *(const uint4*)(srcBl + (c + 1) * 32 + 8);
        }
        unsigned stb = sb + (unsigned)(s * QST * 2);
        mma_chunk(stb, stb + QPL * 2, stb + QPL * 4, stb + QPL * 6,
                  lane, warp_m, warp_n, acc);
        if (c < 31) {
            unsigned ph[8], pl[8];
#pragma unroll
            for (int i = 0; i < 8; i++) {
                float fa = raf[2 * i];
                float fb = raf[2 * i + 1];
                __nv_bfloat16 ha = __float2bfloat16(fa);
                __nv_bfloat16 hb = __float2bfloat16(fb);
                ph[i] = packbf2(fa, fb);
                pl[i] = packbf2(fa - __bfloat162float(ha), fb - __bfloat162float(hb));
            }
            __nv_bfloat16* dst = dynsm2 + (s ^ 1) * QST + lrow * 40 + seg;
            *(uint4*)(dst) = *(uint4*)&ph[0];
            *(uint4*)(dst + 8) = *(uint4*)&ph[4];
            *(uint4*)(dst + QPL) = *(uint4*)&pl[0];
            *(uint4*)(dst + QPL + 8) = *(uint4*)&pl[4];
            *(uint4*)(dst + QPL * 2) = rbh[0];
            *(uint4*)(dst + QPL * 2 + 8) = rbh[1];
            *(uint4*)(dst + QPL * 3) = rbl[0];
            *(uint4*)(dst + QPL * 3 + 8) = rbl[1];
        }
        __syncthreads();
    }

#pragma unroll
    for (int tm = 0; tm < 2; tm++) {
#pragma unroll
        for (int tn = 0; tn < 8; tn++) {
            int m0 = mt * 128 + warp_m * 32 + tm * 16 + (lane >> 2);
            int e = nt * 128 + warp_n * 64 + tn * 8 + (lane & 3) * 2;
#pragma unroll
            for (int half = 0; half < 2; half++) {
                int mr = m0 + half * 8;
                float2 v = make_float2(acc[tm][tn][half * 2], acc[tm][tn][half * 2 + 1]);
                *(float2*)(out + (size_t)mr * 1024 + e) = v;
            }
        }
    }
}

// ---------------------------------------------------------------------------
// RoPE on Q,K; emit bf16 hi/lo planes; split V.
// ---------------------------------------------------------------------------
__global__ void rope_split(const int* __restrict__ pos) {
    int t = blockIdx.x * blockDim.x + threadIdx.x;
    if (t >= BH * SEQ * 32) return;
    int p = t & 31;
    int s = (t >> 5) & 2047;
    double inv = exp(-(double)p * (9.210340371976184 / 32.0));
    double ang = (double)pos[s] * inv;
    double sn, cs;
    sincos(ang, &sn, &cs);
    float c = (float)cs;
    float sf = (float)sn;

    float2 q = *(float2*)(g_Q + 2 * (size_t)t);
    float2 k = *(float2*)(g_K + 2 * (size_t)t);
    float2 v = *(float2*)(g_V + 2 * (size_t)t);
    float q0 = (q.x * c - q.y * sf) * SCALE_LOG2E;
    float q1 = (q.x * sf + q.y * c) * SCALE_LOG2E;
    float k0 = k.x * c - k.y * sf;
    float k1 = k.x * sf + k.y * c;

    __nv_bfloat16 qh0 = __float2bfloat16(q0), qh1 = __float2bfloat16(q1);
    __nv_bfloat16 kh0 = __float2bfloat16(k0), kh1 = __float2bfloat16(k1);
    __nv_bfloat16 vh0 = __float2bfloat16(v.x), vh1 = __float2bfloat16(v.y);

    ((unsigned*)g_Qh)[t] = packbf2(q0, q1);
    ((unsigned*)g_Ql)[t] = packbf2(q0 - __bfloat162float(qh0), q1 - __bfloat162float(qh1));
    ((unsigned*)g_Kh)[t] = packbf2(k0, k1);
    ((unsigned*)g_Kl)[t] = packbf2(k0 - __bfloat162float(kh0), k1 - __bfloat162float(kh1));
    ((unsigned*)g_Vh)[t] = packbf2(v.x, v.y);
    ((unsigned*)g_Vl)[t] = packbf2(v.x - __bfloat162float(vh0), v.y - __bfloat162float(vh1));
}

// ---------------------------------------------------------------------------
// Causal flash attention on tensor cores, register-staged double-buffered K/V.
// Dynamic smem: Q hi/lo (2x128x72) + 2 stages x 4 planes x 64x72 = 110592 B.
// ---------------------------------------------------------------------------
#define FPL (64*72)
#define FST (4*FPL)
__global__ __launch_bounds__(256) void flash_mma() {
    int qt = gridDim.x - 1 - blockIdx.x;
    int bh = blockIdx.y;
    size_t base = (size_t)bh * SEQ * 64;

    extern __shared__ __nv_bfloat16 smem[];
    __nv_bfloat16* Qhs = smem;                 // [128][72]
    __nv_bfloat16* Qls = Qhs + 128 * 72;       // [128][72]
    __nv_bfloat16* KV  = Qls + 128 * 72;       // 2 stages x {Kh,Kl,Vh,Vl}[64][72]
    unsigned qhsB = (unsigned)__cvta_generic_to_shared(Qhs);
    unsigned qlsB = (unsigned)__cvta_generic_to_shared(Qls);
    unsigned kvB  = (unsigned)__cvta_generic_to_shared(KV);

    int tid = threadIdx.x;
    int lane = tid & 31;
    int w = tid >> 5;

    int ldrow = tid >> 2;
    int ldcol = (tid & 3) * 16;

    const __nv_bfloat16* kvsrc[4] = {g_Kh, g_Kl, g_Vh, g_Vl};

    uint4 rkv[4][2];
    // preload K/V tile 0
    {
        size_t g = base + (size_t)ldrow * 64 + ldcol;
#pragma unroll
        for (int p = 0; p < 4; p++) {
            rkv[p][0] = *(const uint4*)(kvsrc[p] + g);
            rkv[p][1] = *(const uint4*)(kvsrc[p] + g + 8);
        }
    }

    // Stage Q tile (128x64 bf16, hi+lo)
    {
        int row = tid >> 1;
        int col = (tid & 1) * 32;
        const uint4* sh = (const uint4*)(g_Qh + base + (size_t)(qt * 128 + row) * 64 + col);
        const uint4* sl = (const uint4*)(g_Ql + base + (size_t)(qt * 128 + row) * 64 + col);
        uint4* dh = (uint4*)(Qhs + row * 72 + col);
        uint4* dl = (uint4*)(Qls + row * 72 + col);
#pragma unroll
        for (int i = 0; i < 4; i++) { dh[i] = sh[i]; dl[i] = sl[i]; }
    }
    // Stage K/V tile 0 into buffer 0
    {
        __nv_bfloat16* dst = KV + ldrow * 72 + ldcol;
#pragma unroll
        for (int p = 0; p < 4; p++) {
            *(uint4*)(dst + p * FPL) = rkv[p][0];
            *(uint4*)(dst + p * FPL + 8) = rkv[p][1];
        }
    }
    __syncthreads();

    // Q fragments register-resident for the whole kernel
    unsigned qh[4][4], ql[4][4];
#pragma unroll
    for (int dc = 0; dc < 4; dc++) {
        unsigned off = (unsigned)(((w * 16 + (lane & 15)) * 72 + dc * 16 + 8 * (lane >> 4)) * 2);
        ldsm4(qh[dc], qhsB + off);
        ldsm4(ql[dc], qlsB + off);
    }

    float accO[8][4] = {};
    float mrow[2] = {-INFINITY, -INFINITY};
    float lrow[2] = {0.f, 0.f};

    int kmax = 2 * qt + 1;
    for (int kt = 0; kt <= kmax; kt++) {
        int st = kt & 1;
        // prefetch next K/V tile into registers
        if (kt < kmax) {
            size_t g = base + (size_t)((kt + 1) * 64 + ldrow) * 64 + ldcol;
#pragma unroll
            for (int p = 0; p < 4; p++) {
                rkv[p][0] = *(const uint4*)(kvsrc[p] + g);
                rkv[p][1] = *(const uint4*)(kvsrc[p] + g + 8);
            }
        }

        unsigned khsB = kvB + (unsigned)(st * FST * 2);
        unsigned klsB = khsB + FPL * 2;
        unsigned vhsB = khsB + FPL * 4;
        unsigned vlsB = khsB + FPL * 6;

        // S = Q K^T (split-3)
        float s[8][4] = {};
#pragma unroll
        for (int dc = 0; dc < 4; dc++) {
            unsigned kh[4][4], kl[4][4];
#pragma unroll
            for (int jt2 = 0; jt2 < 4; jt2++) {
                unsigned off = (unsigned)(((jt2 * 16 + (lane & 15)) * 72 + dc * 16 + 8 * (lane >> 4)) * 2);
                ldsm4(kh[jt2], khsB + off);
                ldsm4(kl[jt2], klsB + off);
            }
#pragma unroll
            for (int jt = 0; jt < 8; jt++) {
                int jt2 = jt >> 1;
                int idx = jt & 1;
                mma16816(s[jt], qh[dc], kh[jt2][idx], kh[jt2][idx + 2]);
                mma16816(s[jt], qh[dc], kl[jt2][idx], kl[jt2][idx + 2]);
                mma16816(s[jt], ql[dc], kh[jt2][idx], kh[jt2][idx + 2]);
            }
        }

        // Causal mask on diagonal tiles
        if (kt >= 2 * qt) {
            int i0 = qt * 128 + w * 16 + (lane >> 2);
            int jb = kt * 64 + (lane & 3) * 2;
#pragma unroll
            for (int jt = 0; jt < 8; jt++) {
                int j = jb + jt * 8;
                if (j > i0) s[jt][0] = -1e30f;
                if (j + 1 > i0) s[jt][1] = -1e30f;
                if (j > i0 + 8) s[jt][2] = -1e30f;
                if (j + 1 > i0 + 8) s[jt][3] = -1e30f;
            }
        }

        // Online softmax, base-2
        float mx0 = -1e30f, mx1 = -1e30f;
#pragma unroll
        for (int jt = 0; jt < 8; jt++) {
            mx0 = fmaxf(mx0, fmaxf(s[jt][0], s[jt][1]));
            mx1 = fmaxf(mx1, fmaxf(s[jt][2], s[jt][3]));
        }
        mx0 = fmaxf(mx0, __shfl_xor_sync(0xffffffffu, mx0, 1));
        mx0 = fmaxf(mx0, __shfl_xor_sync(0xffffffffu, mx0, 2));
        mx1 = fmaxf(mx1, __shfl_xor_sync(0xffffffffu, mx1, 1));
        mx1 = fmaxf(mx1, __shfl_xor_sync(0xffffffffu, mx1, 2));
        float mn0 = fmaxf(mrow[0], mx0);
        float mn1 = fmaxf(mrow[1], mx1);
        float a0 = exp2a(mrow[0] - mn0);
        float a1 = exp2a(mrow[1] - mn1);
        mrow[0] = mn0;
        mrow[1] = mn1;
        float sum0 = 0.f, sum1 = 0.f;
#pragma unroll
        for (int jt = 0; jt < 8; jt++) {
            s[jt][0] = exp2a(s[jt][0] - mn0);
            s[jt][1] = exp2a(s[jt][1] - mn0);
            s[jt][2] = exp2a(s[jt][2] - mn1);
            s[jt][3] = exp2a(s[jt][3] - mn1);
            sum0 += s[jt][0] + s[jt][1];
            sum1 += s[jt][2] + s[jt][3];
        }
        sum0 += __shfl_xor_sync(0xffffffffu, sum0, 1);
        sum0 += __shfl_xor_sync(0xffffffffu, sum0, 2);
        sum1 += __shfl_xor_sync(0xffffffffu, sum1, 1);
        sum1 += __shfl_xor_sync(0xffffffffu, sum1, 2);
        lrow[0] = lrow[0] * a0 + sum0;
        lrow[1] = lrow[1] * a1 + sum1;
#pragma unroll
        for (int dt = 0; dt < 8; dt++) {
            accO[dt][0] *= a0;
            accO[dt][1] *= a0;
            accO[dt][2] *= a1;
            accO[dt][3] *= a1;
        }

        // O += P V (split-3; P fragments repacked from S accumulators)
#pragma unroll
        for (int kc = 0; kc < 4; kc++) {
            unsigned ph[4], pl[4];
            {
                float p00 = s[2 * kc][0], p01 = s[2 * kc][1], p02 = s[2 * kc][2], p03 = s[2 * kc][3];
                float p10 = s[2 * kc + 1][0], p11 = s[2 * kc + 1][1], p12 = s[2 * kc + 1][2], p13 = s[2 * kc + 1][3];
                ph[0] = packbf2(p00, p01);
                ph[1] = packbf2(p02, p03);
                ph[2] = packbf2(p10, p11);
                ph[3] = packbf2(p12, p13);
                pl[0] = packbf2(p00 - __bfloat162float(__float2bfloat16(p00)), p01 - __bfloat162float(__float2bfloat16(p01)));
                pl[1] = packbf2(p02 - __bfloat162float(__float2bfloat16(p02)), p03 - __bfloat162float(__float2bfloat16(p03)));
                pl[2] = packbf2(p10 - __bfloat162float(__float2bfloat16(p10)), p11 - __bfloat162float(__float2bfloat16(p11)));
                pl[3] = packbf2(p12 - __bfloat162float(__float2bfloat16(p12)), p13 - __bfloat162float(__float2bfloat16(p13)));
            }
            unsigned vh[4][4], vl[4][4];
#pragma unroll
            for (int dt2 = 0; dt2 < 4; dt2++) {
                unsigned off = (unsigned)(((kc * 16 + (lane & 15)) * 72 + dt2 * 16 + 8 * (lane >> 4)) * 2);
                ldsm4t(vh[dt2], vhsB + off);
                ldsm4t(vl[dt2], vlsB + off);
            }
#pragma unroll
            for (int dt = 0; dt < 8; dt++) {
                int dt2 = dt >> 1;
                int o = (dt & 1) * 2;
                mma16816(accO[dt], ph, vh[dt2][o], vh[dt2][o + 1]);
                mma16816(accO[dt], pl, vh[dt2][o], vh[dt2][o + 1]);
                mma16816(accO[dt], ph, vl[dt2][o], vl[dt2][o + 1]);
            }
        }

        // stage prefetched tile into the other buffer
        if (kt < kmax) {
            __nv_bfloat16* dst = KV + (st ^ 1) * FST + ldrow * 72 + ldcol;
#pragma unroll
            for (int p = 0; p < 4; p++) {
                *(uint4*)(dst + p * FPL) = rkv[p][0];
                *(uint4*)(dst + p * FPL + 8) = rkv[p][1];
            }
        }
        __syncthreads();
    }

    // Epilogue
    float inv0 = 1.f / lrow[0];
    float inv1 = 1.f / lrow[1];
    int r0 = qt * 128 + w * 16 + (lane >> 2);
#pragma unroll
    for (int dt = 0; dt < 8; dt++) {
        int d = dt * 8 + (lane & 3) * 2;
        *(float2*)(g_O + base + (size_t)r0 * 64 + d) = make_float2(accO[dt][0] * inv0, accO[dt][1] * inv0);
        *(float2*)(g_O + base + (size_t)(r0 + 8) * 64 + d) = make_float2(accO[dt][2] * inv1, accO[dt][3] * inv1);
    }
}

// ---------------------------------------------------------------------------
extern "C" void kernel_launch(void* const* d_in, const int* in_sizes, int n_in,
                              void* d_out, int out_size) {
    const float* x  = (const float*)d_in[0];
    const int*   tp = (const int*)d_in[1];
    const float* Wq = (const float*)d_in[2];
    const float* Wk = (const float*)d_in[3];
    const float* Wv = (const float*)d_in[4];
    const float* Wo = (const float*)d_in[5];
    float* out = (float*)d_out;

    convert_split<<<dim3(4096, 5), 256>>>(x, Wq, Wk, Wv, Wo);

    cudaFuncSetAttribute(qkv_mma, cudaFuncAttributeMaxDynamicSharedMemorySize, 2 * QST * 2);
    qkv_mma<<<dim3(32, 24), 256, 2 * QST * 2>>>();

    rope_split<<<(BH * SEQ * 32) / 256, 256>>>(tp);

    int flash_smem = (2 * 128 * 72 + 2 * FST) * 2;
    cudaFuncSetAttribute(flash_mma, cudaFuncAttributeMaxDynamicSharedMemorySize, flash_smem);
    flash_mma<<<dim3(16, 32), 256, flash_smem>>>();

    cudaFuncSetAttribute(out_mma, cudaFuncAttributeMaxDynamicSharedMemorySize, 2 * QST * 2);
    out_mma<<<dim3(32, 8), 256, 2 * QST * 2>>>(out);
}

// round 10
// speedup vs baseline: 3.1727x; 1.0643x over previous
#include <cuda_runtime.h>
#include <cuda_bf16.h>
#include <cstdint>
#include <math.h>

#define NUM_HEADS 16
#define D_HEAD 64
#define BATCH 2
#define SEQ 2048
#define BH (BATCH*NUM_HEADS)
#define SCALE_LOG2E 0.18033688011112042f   // 0.125 * log2(e)

// fp32 scratch
__device__ float g_Q[BH*SEQ*D_HEAD];
__device__ float g_K[BH*SEQ*D_HEAD];
__device__ float g_V[BH*SEQ*D_HEAD];
__device__ float g_O[BH*SEQ*D_HEAD];
// bf16 split planes for GEMMs
__device__ __nv_bfloat16 g_xh[4096*1024];
__device__ __nv_bfloat16 g_xl[4096*1024];
__device__ __nv_bfloat16 g_wh[4*1024*1024];
__device__ __nv_bfloat16 g_wl[4*1024*1024];
// bf16 split planes for attention (post-RoPE)
__device__ __nv_bfloat16 g_Qh[BH*SEQ*D_HEAD];
__device__ __nv_bfloat16 g_Ql[BH*SEQ*D_HEAD];
__device__ __nv_bfloat16 g_Kh[BH*SEQ*D_HEAD];
__device__ __nv_bfloat16 g_Kl[BH*SEQ*D_HEAD];
__device__ __nv_bfloat16 g_Vh[BH*SEQ*D_HEAD];
__device__ __nv_bfloat16 g_Vl[BH*SEQ*D_HEAD];

// ---- helpers ---------------------------------------------------------------
__device__ __forceinline__ void ldsm4(unsigned r[4], unsigned addr) {
    asm volatile("ldmatrix.sync.aligned.m8n8.x4.shared.b16 {%0,%1,%2,%3}, [%4];"
                 : "=r"(r[0]), "=r"(r[1]), "=r"(r[2]), "=r"(r[3]) : "r"(addr));
}
__device__ __forceinline__ void ldsm4t(unsigned r[4], unsigned addr) {
    asm volatile("ldmatrix.sync.aligned.m8n8.x4.trans.shared.b16 {%0,%1,%2,%3}, [%4];"
                 : "=r"(r[0]), "=r"(r[1]), "=r"(r[2]), "=r"(r[3]) : "r"(addr));
}
__device__ __forceinline__ void mma16816(float c[4], const unsigned a[4], unsigned b0, unsigned b1) {
    asm volatile("mma.sync.aligned.m16n8k16.row.col.f32.bf16.bf16.f32 "
                 "{%0,%1,%2,%3},{%4,%5,%6,%7},{%8,%9},{%0,%1,%2,%3};"
                 : "+f"(c[0]), "+f"(c[1]), "+f"(c[2]), "+f"(c[3])
                 : "r"(a[0]), "r"(a[1]), "r"(a[2]), "r"(a[3]), "r"(b0), "r"(b1));
}
__device__ __forceinline__ unsigned packbf2(float a, float b) {
    __nv_bfloat162 t = __floats2bfloat162_rn(a, b);
    unsigned u;
    memcpy(&u, &t, 4);
    return u;
}
__device__ __forceinline__ float exp2a(float x) {
    float y;
    asm("ex2.approx.f32 %0, %1;" : "=f"(y) : "f"(x));
    return y;
}

// ---------------------------------------------------------------------------
// Split fp32 -> bf16 hi/lo planes for x and the 4 weight matrices.
// ---------------------------------------------------------------------------
__global__ void convert_split(const float* __restrict__ x,
                              const float* __restrict__ Wq, const float* __restrict__ Wk,
                              const float* __restrict__ Wv, const float* __restrict__ Wo) {
    int which = blockIdx.y;
    const float* src;
    __nv_bfloat16* dh;
    __nv_bfloat16* dl;
    int n;
    if (which == 0) {
        src = x; dh = g_xh; dl = g_xl; n = 4096 * 1024;
    } else {
        src = (which == 1) ? Wq : (which == 2) ? Wk : (which == 3) ? Wv : Wo;
        dh = g_wh + (size_t)(which - 1) * 1048576;
        dl = g_wl + (size_t)(which - 1) * 1048576;
        n = 1048576;
    }
    int i = (blockIdx.x * 256 + threadIdx.x) * 4;
    if (i >= n) return;
    float4 v = *(const float4*)(src + i);
    float f[4] = {v.x, v.y, v.z, v.w};
    __nv_bfloat16 hv[4];
    __nv_bfloat16 lv[4];
#pragma unroll
    for (int j = 0; j < 4; j++) {
        hv[j] = __float2bfloat16(f[j]);
        lv[j] = __float2bfloat16(f[j] - __bfloat162float(hv[j]));
    }
    uint2 hu, lu;
    memcpy(&hu, hv, 8);
    memcpy(&lu, lv, 8);
    *(uint2*)(dh + i) = hu;
    *(uint2*)(dl + i) = lu;
}

// ---------------------------------------------------------------------------
// mma compute for one 32-wide k chunk of the projection GEMMs.
// ---------------------------------------------------------------------------
__device__ __forceinline__ void mma_chunk(unsigned ah, unsigned al, unsigned bh, unsigned bl,
                                          int lane, int warp_m, int warp_n, float acc[2][8][4]) {
#pragma unroll
    for (int kk = 0; kk < 32; kk += 16) {
        int col = kk + ((lane >> 4) << 3);
        int arow = warp_m * 32 + (lane & 15);
        int brow = warp_n * 64 + (lane & 15);
        unsigned afh[2][4];
        unsigned afl[2][4];
#pragma unroll
        for (int tm = 0; tm < 2; tm++) {
            ldsm4(afh[tm], ah + (unsigned)(((arow + tm * 16) * 40 + col) * 2));
            ldsm4(afl[tm], al + (unsigned)(((arow + tm * 16) * 40 + col) * 2));
        }
        unsigned bfh[4][4];
        unsigned bfl[4][4];
#pragma unroll
        for (int tg = 0; tg < 4; tg++) {
            ldsm4(bfh[tg], bh + (unsigned)(((brow + tg * 16) * 40 + col) * 2));
            ldsm4(bfl[tg], bl + (unsigned)(((brow + tg * 16) * 40 + col) * 2));
        }
#pragma unroll
        for (int tm = 0; tm < 2; tm++) {
#pragma unroll
            for (int tn = 0; tn < 8; tn++) {
                int tg = tn >> 1;
                int idx = tn & 1;
                mma16816(acc[tm][tn], afh[tm], bfh[tg][idx], bfh[tg][idx + 2]);
                mma16816(acc[tm][tn], afh[tm], bfl[tg][idx], bfl[tg][idx + 2]);
                mma16816(acc[tm][tn], afl[tm], bfh[tg][idx], bfh[tg][idx + 2]);
            }
        }
    }
}

// ---------------------------------------------------------------------------
// QKV projection: single-buffer smem, 2 CTAs/SM for cross-CTA latency hiding.
// Static smem: 4 planes x 128x40 bf16 = 40960 B.
// ---------------------------------------------------------------------------
__global__ __launch_bounds__(256, 2) void qkv_mma() {
    int mt = blockIdx.x;
    int which = blockIdx.y >> 3;
    int nt = blockIdx.y & 7;
    float* out = (which == 0) ? g_Q : (which == 1) ? g_K : g_V;

    __shared__ __nv_bfloat16 Ah[128 * 40];
    __shared__ __nv_bfloat16 Al[128 * 40];
    __shared__ __nv_bfloat16 Bh[128 * 40];
    __shared__ __nv_bfloat16 Bl[128 * 40];
    unsigned ah = (unsigned)__cvta_generic_to_shared(Ah);
    unsigned al = (unsigned)__cvta_generic_to_shared(Al);
    unsigned bh = (unsigned)__cvta_generic_to_shared(Bh);
    unsigned bl = (unsigned)__cvta_generic_to_shared(Bl);

    int tid = threadIdx.x;
    int lane = tid & 31;
    int wid = tid >> 5;
    int warp_m = wid >> 1;
    int warp_n = wid & 1;
    int lrow = tid >> 1;
    int seg = (tid & 1) * 16;

    const __nv_bfloat16* sAh = g_xh + (size_t)(mt * 128 + lrow) * 1024 + seg;
    const __nv_bfloat16* sAl = g_xl + (size_t)(mt * 128 + lrow) * 1024 + seg;
    const __nv_bfloat16* sBh = g_wh + (size_t)which * 1048576 + (size_t)(nt * 128 + lrow) * 1024 + seg;
    const __nv_bfloat16* sBl = g_wl + (size_t)which * 1048576 + (size_t)(nt * 128 + lrow) * 1024 + seg;

    float acc[2][8][4] = {};

    for (int c = 0; c < 32; c++) {
        __syncthreads();
        int o = c * 32;
        *(uint4*)&Ah[lrow * 40 + seg]     = *(const uint4*)(sAh + o);
        *(uint4*)&Ah[lrow * 40 + seg + 8] = *(const uint4*)(sAh + o + 8);
        *(uint4*)&Al[lrow * 40 + seg]     = *(const uint4*)(sAl + o);
        *(uint4*)&Al[lrow * 40 + seg + 8] = *(const uint4*)(sAl + o + 8);
        *(uint4*)&Bh[lrow * 40 + seg]     = *(const uint4*)(sBh + o);
        *(uint4*)&Bh[lrow * 40 + seg + 8] = *(const uint4*)(sBh + o + 8);
        *(uint4*)&Bl[lrow * 40 + seg]     = *(const uint4*)(sBl + o);
        *(uint4*)&Bl[lrow * 40 + seg + 8] = *(const uint4*)(sBl + o + 8);
        __syncthreads();
        mma_chunk(ah, al, bh, bl, lane, warp_m, warp_n, acc);
    }

    int head = nt * 2 + warp_n;
#pragma unroll
    for (int tm = 0; tm < 2; tm++) {
#pragma unroll
        for (int tn = 0; tn < 8; tn++) {
            int m0 = mt * 128 + warp_m * 32 + tm * 16 + (lane >> 2);
            int d = tn * 8 + (lane & 3) * 2;
#pragma unroll
            for (int half = 0; half < 2; half++) {
                int m = m0 + half * 8;
                int b = m >> 11;
                int sq = m & 2047;
                float2 v = make_float2(acc[tm][tn][half * 2], acc[tm][tn][half * 2 + 1]);
                *(float2*)(out + (((size_t)(b * 16 + head) * SEQ + sq) * 64 + d)) = v;
            }
        }
    }
}

// ---------------------------------------------------------------------------
// Output projection: single-buffer smem, 2 CTAs/SM; A gathered+split inline.
// ---------------------------------------------------------------------------
__global__ __launch_bounds__(256, 2) void out_mma(float* __restrict__ out) {
    int mt = blockIdx.x;
    int nt = blockIdx.y;

    __shared__ __nv_bfloat16 Ah[128 * 40];
    __shared__ __nv_bfloat16 Al[128 * 40];
    __shared__ __nv_bfloat16 Bh[128 * 40];
    __shared__ __nv_bfloat16 Bl[128 * 40];
    unsigned ah = (unsigned)__cvta_generic_to_shared(Ah);
    unsigned al = (unsigned)__cvta_generic_to_shared(Al);
    unsigned bh = (unsigned)__cvta_generic_to_shared(Bh);
    unsigned bl = (unsigned)__cvta_generic_to_shared(Bl);

    int tid = threadIdx.x;
    int lane = tid & 31;
    int wid = tid >> 5;
    int warp_m = wid >> 1;
    int warp_n = wid & 1;
    int lrow = tid >> 1;
    int seg = (tid & 1) * 16;

    int m = mt * 128 + lrow;
    int b = m >> 11;
    int sq0 = m & 2047;
    const float* Abase = g_O + ((size_t)b * 16 * SEQ + sq0) * 64;
    const __nv_bfloat16* sBh = g_wh + (size_t)3 * 1048576 + (size_t)(nt * 128 + lrow) * 1024 + seg;
    const __nv_bfloat16* sBl = g_wl + (size_t)3 * 1048576 + (size_t)(nt * 128 + lrow) * 1024 + seg;

    float acc[2][8][4] = {};

    for (int c = 0; c < 32; c++) {
        __syncthreads();
        {
            int k = c * 32 + seg;
            const float* Ap = Abase + (size_t)(k >> 6) * SEQ * 64 + (k & 63);
            float raf[16];
#pragma unroll
            for (int i = 0; i < 4; i++) *(float4*)&raf[i * 4] = *(const float4*)(Ap + i * 4);
            unsigned ph[8], pl[8];
#pragma unroll
            for (int i = 0; i < 8; i++) {
                float fa = raf[2 * i];
                float fb = raf[2 * i + 1];
                __nv_bfloat16 ha = __float2bfloat16(fa);
                __nv_bfloat16 hb = __float2bfloat16(fb);
                ph[i] = packbf2(fa, fb);
                pl[i] = packbf2(fa - __bfloat162float(ha), fb - __bfloat162float(hb));
            }
            *(uint4*)&Ah[lrow * 40 + seg]     = *(uint4*)&ph[0];
            *(uint4*)&Ah[lrow * 40 + seg + 8] = *(uint4*)&ph[4];
            *(uint4*)&Al[lrow * 40 + seg]     = *(uint4*)&pl[0];
            *(uint4*)&Al[lrow * 40 + seg + 8] = *(uint4*)&pl[4];
            int o = c * 32;
            *(uint4*)&Bh[lrow * 40 + seg]     = *(const uint4*)(sBh + o);
            *(uint4*)&Bh[lrow * 40 + seg + 8] = *(const uint4*)(sBh + o + 8);
            *(uint4*)&Bl[lrow * 40 + seg]     = *(const uint4*)(sBl + o);
            *(uint4*)&Bl[lrow * 40 + seg + 8] = *(const uint4*)(sBl + o + 8);
        }
        __syncthreads();
        mma_chunk(ah, al, bh, bl, lane, warp_m, warp_n, acc);
    }

#pragma unroll
    for (int tm = 0; tm < 2; tm++) {
#pragma unroll
        for (int tn = 0; tn < 8; tn++) {
            int m0 = mt * 128 + warp_m * 32 + tm * 16 + (lane >> 2);
            int e = nt * 128 + warp_n * 64 + tn * 8 + (lane & 3) * 2;
#pragma unroll
            for (int half = 0; half < 2; half++) {
                int mr = m0 + half * 8;
                float2 v = make_float2(acc[tm][tn][half * 2], acc[tm][tn][half * 2 + 1]);
                *(float2*)(out + (size_t)mr * 1024 + e) = v;
            }
        }
    }
}

// ---------------------------------------------------------------------------
// RoPE on Q,K; emit bf16 hi/lo planes; split V.
// ---------------------------------------------------------------------------
__global__ void rope_split(const int* __restrict__ pos) {
    int t = blockIdx.x * blockDim.x + threadIdx.x;
    if (t >= BH * SEQ * 32) return;
    int p = t & 31;
    int s = (t >> 5) & 2047;
    double inv = exp(-(double)p * (9.210340371976184 / 32.0));
    double ang = (double)pos[s] * inv;
    double sn, cs;
    sincos(ang, &sn, &cs);
    float c = (float)cs;
    float sf = (float)sn;

    float2 q = *(float2*)(g_Q + 2 * (size_t)t);
    float2 k = *(float2*)(g_K + 2 * (size_t)t);
    float2 v = *(float2*)(g_V + 2 * (size_t)t);
    float q0 = (q.x * c - q.y * sf) * SCALE_LOG2E;
    float q1 = (q.x * sf + q.y * c) * SCALE_LOG2E;
    float k0 = k.x * c - k.y * sf;
    float k1 = k.x * sf + k.y * c;

    __nv_bfloat16 qh0 = __float2bfloat16(q0), qh1 = __float2bfloat16(q1);
    __nv_bfloat16 kh0 = __float2bfloat16(k0), kh1 = __float2bfloat16(k1);
    __nv_bfloat16 vh0 = __float2bfloat16(v.x), vh1 = __float2bfloat16(v.y);

    ((unsigned*)g_Qh)[t] = packbf2(q0, q1);
    ((unsigned*)g_Ql)[t] = packbf2(q0 - __bfloat162float(qh0), q1 - __bfloat162float(qh1));
    ((unsigned*)g_Kh)[t] = packbf2(k0, k1);
    ((unsigned*)g_Kl)[t] = packbf2(k0 - __bfloat162float(kh0), k1 - __bfloat162float(kh1));
    ((unsigned*)g_Vh)[t] = packbf2(v.x, v.y);
    ((unsigned*)g_Vl)[t] = packbf2(v.x - __bfloat162float(vh0), v.y - __bfloat162float(vh1));
}

// ---------------------------------------------------------------------------
// Causal flash attention on tensor cores, register-staged double-buffered K/V.
// (unchanged from R8)
// ---------------------------------------------------------------------------
#define FPL (64*72)
#define FST (4*FPL)
__global__ __launch_bounds__(256) void flash_mma() {
    int qt = gridDim.x - 1 - blockIdx.x;
    int bh = blockIdx.y;
    size_t base = (size_t)bh * SEQ * 64;

    extern __shared__ __nv_bfloat16 smem[];
    __nv_bfloat16* Qhs = smem;
    __nv_bfloat16* Qls = Qhs + 128 * 72;
    __nv_bfloat16* KV  = Qls + 128 * 72;
    unsigned qhsB = (unsigned)__cvta_generic_to_shared(Qhs);
    unsigned qlsB = (unsigned)__cvta_generic_to_shared(Qls);
    unsigned kvB  = (unsigned)__cvta_generic_to_shared(KV);

    int tid = threadIdx.x;
    int lane = tid & 31;
    int w = tid >> 5;

    int ldrow = tid >> 2;
    int ldcol = (tid & 3) * 16;

    const __nv_bfloat16* kvsrc[4] = {g_Kh, g_Kl, g_Vh, g_Vl};

    uint4 rkv[4][2];
    {
        size_t g = base + (size_t)ldrow * 64 + ldcol;
#pragma unroll
        for (int p = 0; p < 4; p++) {
            rkv[p][0] = *(const uint4*)(kvsrc[p] + g);
            rkv[p][1] = *(const uint4*)(kvsrc[p] + g + 8);
        }
    }

    {
        int row = tid >> 1;
        int col = (tid & 1) * 32;
        const uint4* sh = (const uint4*)(g_Qh + base + (size_t)(qt * 128 + row) * 64 + col);
        const uint4* sl = (const uint4*)(g_Ql + base + (size_t)(qt * 128 + row) * 64 + col);
        uint4* dh = (uint4*)(Qhs + row * 72 + col);
        uint4* dl = (uint4*)(Qls + row * 72 + col);
#pragma unroll
        for (int i = 0; i < 4; i++) { dh[i] = sh[i]; dl[i] = sl[i]; }
    }
    {
        __nv_bfloat16* dst = KV + ldrow * 72 + ldcol;
#pragma unroll
        for (int p = 0; p < 4; p++) {
            *(uint4*)(dst + p * FPL) = rkv[p][0];
            *(uint4*)(dst + p * FPL + 8) = rkv[p][1];
        }
    }
    __syncthreads();

    unsigned qh[4][4], ql[4][4];
#pragma unroll
    for (int dc = 0; dc < 4; dc++) {
        unsigned off = (unsigned)(((w * 16 + (lane & 15)) * 72 + dc * 16 + 8 * (lane >> 4)) * 2);
        ldsm4(qh[dc], qhsB + off);
        ldsm4(ql[dc], qlsB + off);
    }

    float accO[8][4] = {};
    float mrow[2] = {-INFINITY, -INFINITY};
    float lrow[2] = {0.f, 0.f};

    int kmax = 2 * qt + 1;
    for (int kt = 0; kt <= kmax; kt++) {
        int st = kt & 1;
        if (kt < kmax) {
            size_t g = base + (size_t)((kt + 1) * 64 + ldrow) * 64 + ldcol;
#pragma unroll
            for (int p = 0; p < 4; p++) {
                rkv[p][0] = *(const uint4*)(kvsrc[p] + g);
                rkv[p][1] = *(const uint4*)(kvsrc[p] + g + 8);
            }
        }

        unsigned khsB = kvB + (unsigned)(st * FST * 2);
        unsigned klsB = khsB + FPL * 2;
        unsigned vhsB = khsB + FPL * 4;
        unsigned vlsB = khsB + FPL * 6;

        float s[8][4] = {};
#pragma unroll
        for (int dc = 0; dc < 4; dc++) {
            unsigned kh[4][4], kl[4][4];
#pragma unroll
            for (int jt2 = 0; jt2 < 4; jt2++) {
                unsigned off = (unsigned)(((jt2 * 16 + (lane & 15)) * 72 + dc * 16 + 8 * (lane >> 4)) * 2);
                ldsm4(kh[jt2], khsB + off);
                ldsm4(kl[jt2], klsB + off);
            }
#pragma unroll
            for (int jt = 0; jt < 8; jt++) {
                int jt2 = jt >> 1;
                int idx = jt & 1;
                mma16816(s[jt], qh[dc], kh[jt2][idx], kh[jt2][idx + 2]);
                mma16816(s[jt], qh[dc], kl[jt2][idx], kl[jt2][idx + 2]);
                mma16816(s[jt], ql[dc], kh[jt2][idx], kh[jt2][idx + 2]);
            }
        }

        if (kt >= 2 * qt) {
            int i0 = qt * 128 + w * 16 + (lane >> 2);
            int jb = kt * 64 + (lane & 3) * 2;
#pragma unroll
            for (int jt = 0; jt < 8; jt++) {
                int j = jb + jt * 8;
                if (j > i0) s[jt][0] = -1e30f;
                if (j + 1 > i0) s[jt][1] = -1e30f;
                if (j > i0 + 8) s[jt][2] = -1e30f;
                if (j + 1 > i0 + 8) s[jt][3] = -1e30f;
            }
        }

        float mx0 = -1e30f, mx1 = -1e30f;
#pragma unroll
        for (int jt = 0; jt < 8; jt++) {
            mx0 = fmaxf(mx0, fmaxf(s[jt][0], s[jt][1]));
            mx1 = fmaxf(mx1, fmaxf(s[jt][2], s[jt][3]));
        }
        mx0 = fmaxf(mx0, __shfl_xor_sync(0xffffffffu, mx0, 1));
        mx0 = fmaxf(mx0, __shfl_xor_sync(0xffffffffu, mx0, 2));
        mx1 = fmaxf(mx1, __shfl_xor_sync(0xffffffffu, mx1, 1));
        mx1 = fmaxf(mx1, __shfl_xor_sync(0xffffffffu, mx1, 2));
        float mn0 = fmaxf(mrow[0], mx0);
        float mn1 = fmaxf(mrow[1], mx1);
        float a0 = exp2a(mrow[0] - mn0);
        float a1 = exp2a(mrow[1] - mn1);
        mrow[0] = mn0;
        mrow[1] = mn1;
        float sum0 = 0.f, sum1 = 0.f;
#pragma unroll
        for (int jt = 0; jt < 8; jt++) {
            s[jt][0] = exp2a(s[jt][0] - mn0);
            s[jt][1] = exp2a(s[jt][1] - mn0);
            s[jt][2] = exp2a(s[jt][2] - mn1);
            s[jt][3] = exp2a(s[jt][3] - mn1);
            sum0 += s[jt][0] + s[jt][1];
            sum1 += s[jt][2] + s[jt][3];
        }
        sum0 += __shfl_xor_sync(0xffffffffu, sum0, 1);
        sum0 += __shfl_xor_sync(0xffffffffu, sum0, 2);
        sum1 += __shfl_xor_sync(0xffffffffu, sum1, 1);
        sum1 += __shfl_xor_sync(0xffffffffu, sum1, 2);
        lrow[0] = lrow[0] * a0 + sum0;
        lrow[1] = lrow[1] * a1 + sum1;
#pragma unroll
        for (int dt = 0; dt < 8; dt++) {
            accO[dt][0] *= a0;
            accO[dt][1] *= a0;
            accO[dt][2] *= a1;
            accO[dt][3] *= a1;
        }

#pragma unroll
        for (int kc = 0; kc < 4; kc++) {
            unsigned phh[4], pll[4];
            {
                float p00 = s[2 * kc][0], p01 = s[2 * kc][1], p02 = s[2 * kc][2], p03 = s[2 * kc][3];
                float p10 = s[2 * kc + 1][0], p11 = s[2 * kc + 1][1], p12 = s[2 * kc + 1][2], p13 = s[2 * kc + 1][3];
                phh[0] = packbf2(p00, p01);
                phh[1] = packbf2(p02, p03);
                phh[2] = packbf2(p10, p11);
                phh[3] = packbf2(p12, p13);
                pll[0] = packbf2(p00 - __bfloat162float(__float2bfloat16(p00)), p01 - __bfloat162float(__float2bfloat16(p01)));
                pll[1] = packbf2(p02 - __bfloat162float(__float2bfloat16(p02)), p03 - __bfloat162float(__float2bfloat16(p03)));
                pll[2] = packbf2(p10 - __bfloat162float(__float2bfloat16(p10)), p11 - __bfloat162float(__float2bfloat16(p11)));
                pll[3] = packbf2(p12 - __bfloat162float(__float2bfloat16(p12)), p13 - __bfloat162float(__float2bfloat16(p13)));
            }
            unsigned vh[4][4], vl[4][4];
#pragma unroll
            for (int dt2 = 0; dt2 < 4; dt2++) {
                unsigned off = (unsigned)(((kc * 16 + (lane & 15)) * 72 + dt2 * 16 + 8 * (lane >> 4)) * 2);
                ldsm4t(vh[dt2], vhsB + off);
                ldsm4t(vl[dt2], vlsB + off);
            }
#pragma unroll
            for (int dt = 0; dt < 8; dt++) {
                int dt2 = dt >> 1;
                int o = (dt & 1) * 2;
                mma16816(accO[dt], phh, vh[dt2][o], vh[dt2][o + 1]);
                mma16816(accO[dt], pll, vh[dt2][o], vh[dt2][o + 1]);
                mma16816(accO[dt], phh, vl[dt2][o], vl[dt2][o + 1]);
            }
        }

        if (kt < kmax) {
            __nv_bfloat16* dst = KV + (st ^ 1) * FST + ldrow * 72 + ldcol;
#pragma unroll
            for (int p = 0; p < 4; p++) {
                *(uint4*)(dst + p * FPL) = rkv[p][0];
                *(uint4*)(dst + p * FPL + 8) = rkv[p][1];
            }
        }
        __syncthreads();
    }

    float inv0 = 1.f / lrow[0];
    float inv1 = 1.f / lrow[1];
    int r0 = qt * 128 + w * 16 + (lane >> 2);
#pragma unroll
    for (int dt = 0; dt < 8; dt++) {
        int d = dt * 8 + (lane & 3) * 2;
        *(float2*)(g_O + base + (size_t)r0 * 64 + d) = make_float2(accO[dt][0] * inv0, accO[dt][1] * inv0);
        *(float2*)(g_O + base + (size_t)(r0 + 8) * 64 + d) = make_float2(accO[dt][2] * inv1, accO[dt][3] * inv1);
    }
}

// ---------------------------------------------------------------------------
extern "C" void kernel_launch(void* const* d_in, const int* in_sizes, int n_in,
                              void* d_out, int out_size) {
    const float* x  = (const float*)d_in[0];
    const int*   tp = (const int*)d_in[1];
    const float* Wq = (const float*)d_in[2];
    const float* Wk = (const float*)d_in[3];
    const float* Wv = (const float*)d_in[4];
    const float* Wo = (const float*)d_in[5];
    float* out = (float*)d_out;

    convert_split<<<dim3(4096, 5), 256>>>(x, Wq, Wk, Wv, Wo);
    qkv_mma<<<dim3(32, 24), 256>>>();
    rope_split<<<(BH * SEQ * 32) / 256, 256>>>(tp);

    int flash_smem = (2 * 128 * 72 + 2 * FST) * 2;
    cudaFuncSetAttribute(flash_mma, cudaFuncAttributeMaxDynamicSharedMemorySize, flash_smem);
    flash_mma<<<dim3(16, 32), 256, flash_smem>>>();

    out_mma<<<dim3(32, 8), 256>>>(out);
}

// round 11
// speedup vs baseline: 3.3644x; 1.0604x over previous
#include <cuda_runtime.h>
#include <cuda_bf16.h>
#include <cstdint>
#include <math.h>

#define NUM_HEADS 16
#define D_HEAD 64
#define BATCH 2
#define SEQ 2048
#define BH (BATCH*NUM_HEADS)
#define SCALE_LOG2E 0.18033688011112042f   // 0.125 * log2(e)

// fp32 scratch
__device__ float g_Q[BH*SEQ*D_HEAD];
__device__ float g_K[BH*SEQ*D_HEAD];
__device__ float g_V[BH*SEQ*D_HEAD];
__device__ float g_O[BH*SEQ*D_HEAD];
// bf16 split planes for GEMMs
__device__ __nv_bfloat16 g_xh[4096*1024];
__device__ __nv_bfloat16 g_xl[4096*1024];
__device__ __nv_bfloat16 g_wh[4*1024*1024];
__device__ __nv_bfloat16 g_wl[4*1024*1024];
// bf16 split planes for attention (post-RoPE)
__device__ __nv_bfloat16 g_Qh[BH*SEQ*D_HEAD];
__device__ __nv_bfloat16 g_Ql[BH*SEQ*D_HEAD];
__device__ __nv_bfloat16 g_Kh[BH*SEQ*D_HEAD];
__device__ __nv_bfloat16 g_Kl[BH*SEQ*D_HEAD];
__device__ __nv_bfloat16 g_Vh[BH*SEQ*D_HEAD];
__device__ __nv_bfloat16 g_Vl[BH*SEQ*D_HEAD];

// ---- helpers ---------------------------------------------------------------
__device__ __forceinline__ void ldsm4(unsigned r[4], unsigned addr) {
    asm volatile("ldmatrix.sync.aligned.m8n8.x4.shared.b16 {%0,%1,%2,%3}, [%4];"
                 : "=r"(r[0]), "=r"(r[1]), "=r"(r[2]), "=r"(r[3]) : "r"(addr));
}
__device__ __forceinline__ void ldsm4t(unsigned r[4], unsigned addr) {
    asm volatile("ldmatrix.sync.aligned.m8n8.x4.trans.shared.b16 {%0,%1,%2,%3}, [%4];"
                 : "=r"(r[0]), "=r"(r[1]), "=r"(r[2]), "=r"(r[3]) : "r"(addr));
}
__device__ __forceinline__ void mma16816(float c[4], const unsigned a[4], unsigned b0, unsigned b1) {
    asm volatile("mma.sync.aligned.m16n8k16.row.col.f32.bf16.bf16.f32 "
                 "{%0,%1,%2,%3},{%4,%5,%6,%7},{%8,%9},{%0,%1,%2,%3};"
                 : "+f"(c[0]), "+f"(c[1]), "+f"(c[2]), "+f"(c[3])
                 : "r"(a[0]), "r"(a[1]), "r"(a[2]), "r"(a[3]), "r"(b0), "r"(b1));
}
__device__ __forceinline__ unsigned packbf2(float a, float b) {
    __nv_bfloat162 t = __floats2bfloat162_rn(a, b);
    unsigned u;
    memcpy(&u, &t, 4);
    return u;
}
__device__ __forceinline__ float exp2a(float x) {
    float y;
    asm("ex2.approx.f32 %0, %1;" : "=f"(y) : "f"(x));
    return y;
}

// ---------------------------------------------------------------------------
// Split fp32 -> bf16 hi/lo planes for x and the 4 weight matrices.
// ---------------------------------------------------------------------------
__global__ void convert_split(const float* __restrict__ x,
                              const float* __restrict__ Wq, const float* __restrict__ Wk,
                              const float* __restrict__ Wv, const float* __restrict__ Wo) {
    int which = blockIdx.y;
    const float* src;
    __nv_bfloat16* dh;
    __nv_bfloat16* dl;
    int n;
    if (which == 0) {
        src = x; dh = g_xh; dl = g_xl; n = 4096 * 1024;
    } else {
        src = (which == 1) ? Wq : (which == 2) ? Wk : (which == 3) ? Wv : Wo;
        dh = g_wh + (size_t)(which - 1) * 1048576;
        dl = g_wl + (size_t)(which - 1) * 1048576;
        n = 1048576;
    }
    int i = (blockIdx.x * 256 + threadIdx.x) * 4;
    if (i >= n) return;
    float4 v = *(const float4*)(src + i);
    float f[4] = {v.x, v.y, v.z, v.w};
    __nv_bfloat16 hv[4];
    __nv_bfloat16 lv[4];
#pragma unroll
    for (int j = 0; j < 4; j++) {
        hv[j] = __float2bfloat16(f[j]);
        lv[j] = __float2bfloat16(f[j] - __bfloat162float(hv[j]));
    }
    uint2 hu, lu;
    memcpy(&hu, hv, 8);
    memcpy(&lu, lv, 8);
    *(uint2*)(dh + i) = hu;
    *(uint2*)(dl + i) = lu;
}

// ---------------------------------------------------------------------------
// mma compute for one 32-wide k chunk; 512-thread CTA, warp tile 32x32.
// Plane layout per stage: Ah +0, Al +5120, Bh +10240, Bl +15360 (elems).
// ---------------------------------------------------------------------------
__device__ __forceinline__ void mma_chunk512(unsigned stb, int lane, int warp_m, int warp_n,
                                             float acc[2][4][4]) {
    unsigned ah = stb;
    unsigned al = stb + 5120 * 2;
    unsigned bh = stb + 10240 * 2;
    unsigned bl = stb + 15360 * 2;
#pragma unroll
    for (int kk = 0; kk < 32; kk += 16) {
        int col = kk + ((lane >> 4) << 3);
        int arow = warp_m * 32 + (lane & 15);
        int brow = warp_n * 32 + (lane & 15);
        unsigned afh[2][4];
        unsigned afl[2][4];
#pragma unroll
        for (int tm = 0; tm < 2; tm++) {
            ldsm4(afh[tm], ah + (unsigned)(((arow + tm * 16) * 40 + col) * 2));
            ldsm4(afl[tm], al + (unsigned)(((arow + tm * 16) * 40 + col) * 2));
        }
        unsigned bfh[2][4];
        unsigned bfl[2][4];
#pragma unroll
        for (int tg = 0; tg < 2; tg++) {
            ldsm4(bfh[tg], bh + (unsigned)(((brow + tg * 16) * 40 + col) * 2));
            ldsm4(bfl[tg], bl + (unsigned)(((brow + tg * 16) * 40 + col) * 2));
        }
#pragma unroll
        for (int tm = 0; tm < 2; tm++) {
#pragma unroll
            for (int tn = 0; tn < 4; tn++) {
                int tg = tn >> 1;
                int idx = tn & 1;
                mma16816(acc[tm][tn], afh[tm], bfh[tg][idx], bfh[tg][idx + 2]);
                mma16816(acc[tm][tn], afh[tm], bfl[tg][idx], bfl[tg][idx + 2]);
                mma16816(acc[tm][tn], afl[tm], bfh[tg][idx], bfh[tg][idx + 2]);
            }
        }
    }
}

#define GSTAGE 20480   // elems per stage (4 planes x 128x40)

// ---------------------------------------------------------------------------
// QKV projection: 512 threads, 128x128 tile, register-staged double buffer.
// Dynamic smem: 2 x 40960 B = 81920 B.
// ---------------------------------------------------------------------------
__global__ __launch_bounds__(512) void qkv_mma() {
    int mt = blockIdx.x;
    int which = blockIdx.y >> 3;
    int nt = blockIdx.y & 7;
    float* out = (which == 0) ? g_Q : (which == 1) ? g_K : g_V;

    extern __shared__ __nv_bfloat16 dynsm[];
    unsigned sb = (unsigned)__cvta_generic_to_shared(dynsm);

    int tid = threadIdx.x;
    int lane = tid & 31;
    int wid = tid >> 5;
    int warp_m = wid >> 2;
    int warp_n = wid & 3;
    int lrow = tid >> 2;
    int seg = (tid & 3) * 8;

    const __nv_bfloat16* srcs[4];
    srcs[0] = g_xh + (size_t)(mt * 128 + lrow) * 1024 + seg;
    srcs[1] = g_xl + (size_t)(mt * 128 + lrow) * 1024 + seg;
    srcs[2] = g_wh + (size_t)which * 1048576 + (size_t)(nt * 128 + lrow) * 1024 + seg;
    srcs[3] = g_wl + (size_t)which * 1048576 + (size_t)(nt * 128 + lrow) * 1024 + seg;

    float acc[2][4][4] = {};
    uint4 rg[4];

#pragma unroll
    for (int p = 0; p < 4; p++) rg[p] = *(const uint4*)(srcs[p]);
    {
        __nv_bfloat16* dst = dynsm + lrow * 40 + seg;
#pragma unroll
        for (int p = 0; p < 4; p++) *(uint4*)(dst + p * 5120) = rg[p];
    }
    __syncthreads();

    for (int c = 0; c < 32; c++) {
        int s = c & 1;
        if (c < 31) {
#pragma unroll
            for (int p = 0; p < 4; p++) rg[p] = *(const uint4*)(srcs[p] + (c + 1) * 32);
        }
        mma_chunk512(sb + (unsigned)(s * GSTAGE * 2), lane, warp_m, warp_n, acc);
        if (c < 31) {
            __nv_bfloat16* dst = dynsm + (s ^ 1) * GSTAGE + lrow * 40 + seg;
#pragma unroll
            for (int p = 0; p < 4; p++) *(uint4*)(dst + p * 5120) = rg[p];
        }
        __syncthreads();
    }

    // Epilogue: N=128 covers heads nt*2 + (warp_n>>1); d = (warp_n&1)*32 + tn*8 + (lane&3)*2
    int head = nt * 2 + (warp_n >> 1);
#pragma unroll
    for (int tm = 0; tm < 2; tm++) {
#pragma unroll
        for (int tn = 0; tn < 4; tn++) {
            int m0 = mt * 128 + warp_m * 32 + tm * 16 + (lane >> 2);
            int d = (warp_n & 1) * 32 + tn * 8 + (lane & 3) * 2;
#pragma unroll
            for (int half = 0; half < 2; half++) {
                int m = m0 + half * 8;
                int b = m >> 11;
                int sq = m & 2047;
                float2 v = make_float2(acc[tm][tn][half * 2], acc[tm][tn][half * 2 + 1]);
                *(float2*)(out + (((size_t)(b * 16 + head) * SEQ + sq) * 64 + d)) = v;
            }
        }
    }
}

// ---------------------------------------------------------------------------
// Output projection: 512 threads, 128x128 tile, register-staged double buffer;
// A gathered from g_O ([B,H,S,d]) and split to bf16 hi/lo in registers.
// ---------------------------------------------------------------------------
__global__ __launch_bounds__(512) void out_mma(float* __restrict__ out) {
    int mt = blockIdx.x;
    int nt = blockIdx.y;

    extern __shared__ __nv_bfloat16 dynsm2[];
    unsigned sb = (unsigned)__cvta_generic_to_shared(dynsm2);

    int tid = threadIdx.x;
    int lane = tid & 31;
    int wid = tid >> 5;
    int warp_m = wid >> 2;
    int warp_n = wid & 3;
    int lrow = tid >> 2;
    int seg = (tid & 3) * 8;

    int m = mt * 128 + lrow;
    int b = m >> 11;
    int sq0 = m & 2047;
    const float* Abase = g_O + ((size_t)b * 16 * SEQ + sq0) * 64;
    const __nv_bfloat16* sBh = g_wh + (size_t)3 * 1048576 + (size_t)(nt * 128 + lrow) * 1024 + seg;
    const __nv_bfloat16* sBl = g_wl + (size_t)3 * 1048576 + (size_t)(nt * 128 + lrow) * 1024 + seg;

    float acc[2][4][4] = {};
    float raf[8];
    uint4 rbh, rbl;

    {
        const float* Ap = Abase + (size_t)(seg >> 6) * SEQ * 64 + (seg & 63);
        *(float4*)&raf[0] = *(const float4*)(Ap);
        *(float4*)&raf[4] = *(const float4*)(Ap + 4);
        rbh = *(const uint4*)(sBh);
        rbl = *(const uint4*)(sBl);
    }
    // split + stage buffer 0
    {
        unsigned ph[4], pl[4];
#pragma unroll
        for (int i = 0; i < 4; i++) {
            float fa = raf[2 * i];
            float fb = raf[2 * i + 1];
            __nv_bfloat16 ha = __float2bfloat16(fa);
            __nv_bfloat16 hb = __float2bfloat16(fb);
            ph[i] = packbf2(fa, fb);
            pl[i] = packbf2(fa - __bfloat162float(ha), fb - __bfloat162float(hb));
        }
        __nv_bfloat16* dst = dynsm2 + lrow * 40 + seg;
        *(uint4*)(dst)         = *(uint4*)ph;
        *(uint4*)(dst + 5120)  = *(uint4*)pl;
        *(uint4*)(dst + 10240) = rbh;
        *(uint4*)(dst + 15360) = rbl;
    }
    __syncthreads();

    for (int c = 0; c < 32; c++) {
        int s = c & 1;
        if (c < 31) {
            int k = (c + 1) * 32 + seg;
            const float* Ap = Abase + (size_t)(k >> 6) * SEQ * 64 + (k & 63);
            *(float4*)&raf[0] = *(const float4*)(Ap);
            *(float4*)&raf[4] = *(const float4*)(Ap + 4);
            rbh = *(const uint4*)(sBh + (c + 1) * 32);
            rbl = *(const uint4*)(sBl + (c + 1) * 32);
        }
        mma_chunk512(sb + (unsigned)(s * GSTAGE * 2), lane, warp_m, warp_n, acc);
        if (c < 31) {
            unsigned ph[4], pl[4];
#pragma unroll
            for (int i = 0; i < 4; i++) {
                float fa = raf[2 * i];
                float fb = raf[2 * i + 1];
                __nv_bfloat16 ha = __float2bfloat16(fa);
                __nv_bfloat16 hb = __float2bfloat16(fb);
                ph[i] = packbf2(fa, fb);
                pl[i] = packbf2(fa - __bfloat162float(ha), fb - __bfloat162float(hb));
            }
            __nv_bfloat16* dst = dynsm2 + (s ^ 1) * GSTAGE + lrow * 40 + seg;
            *(uint4*)(dst)         = *(uint4*)ph;
            *(uint4*)(dst + 5120)  = *(uint4*)pl;
            *(uint4*)(dst + 10240) = rbh;
            *(uint4*)(dst + 15360) = rbl;
        }
        __syncthreads();
    }

#pragma unroll
    for (int tm = 0; tm < 2; tm++) {
#pragma unroll
        for (int tn = 0; tn < 4; tn++) {
            int m0 = mt * 128 + warp_m * 32 + tm * 16 + (lane >> 2);
            int e = nt * 128 + warp_n * 32 + tn * 8 + (lane & 3) * 2;
#pragma unroll
            for (int half = 0; half < 2; half++) {
                int mr = m0 + half * 8;
                float2 v = make_float2(acc[tm][tn][half * 2], acc[tm][tn][half * 2 + 1]);
                *(float2*)(out + (size_t)mr * 1024 + e) = v;
            }
        }
    }
}

// ---------------------------------------------------------------------------
// RoPE on Q,K; emit bf16 hi/lo planes; split V.
// ---------------------------------------------------------------------------
__global__ void rope_split(const int* __restrict__ pos) {
    int t = blockIdx.x * blockDim.x + threadIdx.x;
    if (t >= BH * SEQ * 32) return;
    int p = t & 31;
    int s = (t >> 5) & 2047;
    double inv = exp(-(double)p * (9.210340371976184 / 32.0));
    double ang = (double)pos[s] * inv;
    double sn, cs;
    sincos(ang, &sn, &cs);
    float c = (float)cs;
    float sf = (float)sn;

    float2 q = *(float2*)(g_Q + 2 * (size_t)t);
    float2 k = *(float2*)(g_K + 2 * (size_t)t);
    float2 v = *(float2*)(g_V + 2 * (size_t)t);
    float q0 = (q.x * c - q.y * sf) * SCALE_LOG2E;
    float q1 = (q.x * sf + q.y * c) * SCALE_LOG2E;
    float k0 = k.x * c - k.y * sf;
    float k1 = k.x * sf + k.y * c;

    __nv_bfloat16 qh0 = __float2bfloat16(q0), qh1 = __float2bfloat16(q1);
    __nv_bfloat16 kh0 = __float2bfloat16(k0), kh1 = __float2bfloat16(k1);
    __nv_bfloat16 vh0 = __float2bfloat16(v.x), vh1 = __float2bfloat16(v.y);

    ((unsigned*)g_Qh)[t] = packbf2(q0, q1);
    ((unsigned*)g_Ql)[t] = packbf2(q0 - __bfloat162float(qh0), q1 - __bfloat162float(qh1));
    ((unsigned*)g_Kh)[t] = packbf2(k0, k1);
    ((unsigned*)g_Kl)[t] = packbf2(k0 - __bfloat162float(kh0), k1 - __bfloat162float(kh1));
    ((unsigned*)g_Vh)[t] = packbf2(v.x, v.y);
    ((unsigned*)g_Vl)[t] = packbf2(v.x - __bfloat162float(vh0), v.y - __bfloat162float(vh1));
}

// ---------------------------------------------------------------------------
// Causal flash attention on tensor cores, register-staged double-buffered K/V.
// (unchanged from R8/R10)
// ---------------------------------------------------------------------------
#define FPL (64*72)
#define FST (4*FPL)
__global__ __launch_bounds__(256) void flash_mma() {
    int qt = gridDim.x - 1 - blockIdx.x;
    int bh = blockIdx.y;
    size_t base = (size_t)bh * SEQ * 64;

    extern __shared__ __nv_bfloat16 smem[];
    __nv_bfloat16* Qhs = smem;
    __nv_bfloat16* Qls = Qhs + 128 * 72;
    __nv_bfloat16* KV  = Qls + 128 * 72;
    unsigned qhsB = (unsigned)__cvta_generic_to_shared(Qhs);
    unsigned qlsB = (unsigned)__cvta_generic_to_shared(Qls);
    unsigned kvB  = (unsigned)__cvta_generic_to_shared(KV);

    int tid = threadIdx.x;
    int lane = tid & 31;
    int w = tid >> 5;

    int ldrow = tid >> 2;
    int ldcol = (tid & 3) * 16;

    const __nv_bfloat16* kvsrc[4] = {g_Kh, g_Kl, g_Vh, g_Vl};

    uint4 rkv[4][2];
    {
        size_t g = base + (size_t)ldrow * 64 + ldcol;
#pragma unroll
        for (int p = 0; p < 4; p++) {
            rkv[p][0] = *(const uint4*)(kvsrc[p] + g);
            rkv[p][1] = *(const uint4*)(kvsrc[p] + g + 8);
        }
    }

    {
        int row = tid >> 1;
        int col = (tid & 1) * 32;
        const uint4* sh = (const uint4*)(g_Qh + base + (size_t)(qt * 128 + row) * 64 + col);
        const uint4* sl = (const uint4*)(g_Ql + base + (size_t)(qt * 128 + row) * 64 + col);
        uint4* dh = (uint4*)(Qhs + row * 72 + col);
        uint4* dl = (uint4*)(Qls + row * 72 + col);
#pragma unroll
        for (int i = 0; i < 4; i++) { dh[i] = sh[i]; dl[i] = sl[i]; }
    }
    {
        __nv_bfloat16* dst = KV + ldrow * 72 + ldcol;
#pragma unroll
        for (int p = 0; p < 4; p++) {
            *(uint4*)(dst + p * FPL) = rkv[p][0];
            *(uint4*)(dst + p * FPL + 8) = rkv[p][1];
        }
    }
    __syncthreads();

    unsigned qh[4][4], ql[4][4];
#pragma unroll
    for (int dc = 0; dc < 4; dc++) {
        unsigned off = (unsigned)(((w * 16 + (lane & 15)) * 72 + dc * 16 + 8 * (lane >> 4)) * 2);
        ldsm4(qh[dc], qhsB + off);
        ldsm4(ql[dc], qlsB + off);
    }

    float accO[8][4] = {};
    float mrow[2] = {-INFINITY, -INFINITY};
    float lrow[2] = {0.f, 0.f};

    int kmax = 2 * qt + 1;
    for (int kt = 0; kt <= kmax; kt++) {
        int st = kt & 1;
        if (kt < kmax) {
            size_t g = base + (size_t)((kt + 1) * 64 + ldrow) * 64 + ldcol;
#pragma unroll
            for (int p = 0; p < 4; p++) {
                rkv[p][0] = *(const uint4*)(kvsrc[p] + g);
                rkv[p][1] = *(const uint4*)(kvsrc[p] + g + 8);
            }
        }

        unsigned khsB = kvB + (unsigned)(st * FST * 2);
        unsigned klsB = khsB + FPL * 2;
        unsigned vhsB = khsB + FPL * 4;
        unsigned vlsB = khsB + FPL * 6;

        float s[8][4] = {};
#pragma unroll
        for (int dc = 0; dc < 4; dc++) {
            unsigned kh[4][4], kl[4][4];
#pragma unroll
            for (int jt2 = 0; jt2 < 4; jt2++) {
                unsigned off = (unsigned)(((jt2 * 16 + (lane & 15)) * 72 + dc * 16 + 8 * (lane >> 4)) * 2);
                ldsm4(kh[jt2], khsB + off);
                ldsm4(kl[jt2], klsB + off);
            }
#pragma unroll
            for (int jt = 0; jt < 8; jt++) {
                int jt2 = jt >> 1;
                int idx = jt & 1;
                mma16816(s[jt], qh[dc], kh[jt2][idx], kh[jt2][idx + 2]);
                mma16816(s[jt], qh[dc], kl[jt2][idx], kl[jt2][idx + 2]);
                mma16816(s[jt], ql[dc], kh[jt2][idx], kh[jt2][idx + 2]);
            }
        }

        if (kt >= 2 * qt) {
            int i0 = qt * 128 + w * 16 + (lane >> 2);
            int jb = kt * 64 + (lane & 3) * 2;
#pragma unroll
            for (int jt = 0; jt < 8; jt++) {
                int j = jb + jt * 8;
                if (j > i0) s[jt][0] = -1e30f;
                if (j + 1 > i0) s[jt][1] = -1e30f;
                if (j > i0 + 8) s[jt][2] = -1e30f;
                if (j + 1 > i0 + 8) s[jt][3] = -1e30f;
            }
        }

        float mx0 = -1e30f, mx1 = -1e30f;
#pragma unroll
        for (int jt = 0; jt < 8; jt++) {
            mx0 = fmaxf(mx0, fmaxf(s[jt][0], s[jt][1]));
            mx1 = fmaxf(mx1, fmaxf(s[jt][2], s[jt][3]));
        }
        mx0 = fmaxf(mx0, __shfl_xor_sync(0xffffffffu, mx0, 1));
        mx0 = fmaxf(mx0, __shfl_xor_sync(0xffffffffu, mx0, 2));
        mx1 = fmaxf(mx1, __shfl_xor_sync(0xffffffffu, mx1, 1));
        mx1 = fmaxf(mx1, __shfl_xor_sync(0xffffffffu, mx1, 2));
        float mn0 = fmaxf(mrow[0], mx0);
        float mn1 = fmaxf(mrow[1], mx1);
        float a0 = exp2a(mrow[0] - mn0);
        float a1 = exp2a(mrow[1] - mn1);
        mrow[0] = mn0;
        mrow[1] = mn1;
        float sum0 = 0.f, sum1 = 0.f;
#pragma unroll
        for (int jt = 0; jt < 8; jt++) {
            s[jt][0] = exp2a(s[jt][0] - mn0);
            s[jt][1] = exp2a(s[jt][1] - mn0);
            s[jt][2] = exp2a(s[jt][2] - mn1);
            s[jt][3] = exp2a(s[jt][3] - mn1);
            sum0 += s[jt][0] + s[jt][1];
            sum1 += s[jt][2] + s[jt][3];
        }
        sum0 += __shfl_xor_sync(0xffffffffu, sum0, 1);
        sum0 += __shfl_xor_sync(0xffffffffu, sum0, 2);
        sum1 += __shfl_xor_sync(0xffffffffu, sum1, 1);
        sum1 += __shfl_xor_sync(0xffffffffu, sum1, 2);
        lrow[0] = lrow[0] * a0 + sum0;
        lrow[1] = lrow[1] * a1 + sum1;
#pragma unroll
        for (int dt = 0; dt < 8; dt++) {
            accO[dt][0] *= a0;
            accO[dt][1] *= a0;
            accO[dt][2] *= a1;
            accO[dt][3] *= a1;
        }

#pragma unroll
        for (int kc = 0; kc < 4; kc++) {
            unsigned phh[4], pll[4];
            {
                float p00 = s[2 * kc][0], p01 = s[2 * kc][1], p02 = s[2 * kc][2], p03 = s[2 * kc][3];
                float p10 = s[2 * kc + 1][0], p11 = s[2 * kc + 1][1], p12 = s[2 * kc + 1][2], p13 = s[2 * kc + 1][3];
                phh[0] = packbf2(p00, p01);
                phh[1] = packbf2(p02, p03);
                phh[2] = packbf2(p10, p11);
                phh[3] = packbf2(p12, p13);
                pll[0] = packbf2(p00 - __bfloat162float(__float2bfloat16(p00)), p01 - __bfloat162float(__float2bfloat16(p01)));
                pll[1] = packbf2(p02 - __bfloat162float(__float2bfloat16(p02)), p03 - __bfloat162float(__float2bfloat16(p03)));
                pll[2] = packbf2(p10 - __bfloat162float(__float2bfloat16(p10)), p11 - __bfloat162float(__float2bfloat16(p11)));
                pll[3] = packbf2(p12 - __bfloat162float(__float2bfloat16(p12)), p13 - __bfloat162float(__float2bfloat16(p13)));
            }
            unsigned vh[4][4], vl[4][4];
#pragma unroll
            for (int dt2 = 0; dt2 < 4; dt2++) {
                unsigned off = (unsigned)(((kc * 16 + (lane & 15)) * 72 + dt2 * 16 + 8 * (lane >> 4)) * 2);
                ldsm4t(vh[dt2], vhsB + off);
                ldsm4t(vl[dt2], vlsB + off);
            }
#pragma unroll
            for (int dt = 0; dt < 8; dt++) {
                int dt2 = dt >> 1;
                int o = (dt & 1) * 2;
                mma16816(accO[dt], phh, vh[dt2][o], vh[dt2][o + 1]);
                mma16816(accO[dt], pll, vh[dt2][o], vh[dt2][o + 1]);
                mma16816(accO[dt], phh, vl[dt2][o], vl[dt2][o + 1]);
            }
        }

        if (kt < kmax) {
            __nv_bfloat16* dst = KV + (st ^ 1) * FST + ldrow * 72 + ldcol;
#pragma unroll
            for (int p = 0; p < 4; p++) {
                *(uint4*)(dst + p * FPL) = rkv[p][0];
                *(uint4*)(dst + p * FPL + 8) = rkv[p][1];
            }
        }
        __syncthreads();
    }

    float inv0 = 1.f / lrow[0];
    float inv1 = 1.f / lrow[1];
    int r0 = qt * 128 + w * 16 + (lane >> 2);
#pragma unroll
    for (int dt = 0; dt < 8; dt++) {
        int d = dt * 8 + (lane & 3) * 2;
        *(float2*)(g_O + base + (size_t)r0 * 64 + d) = make_float2(accO[dt][0] * inv0, accO[dt][1] * inv0);
        *(float2*)(g_O + base + (size_t)(r0 + 8) * 64 + d) = make_float2(accO[dt][2] * inv1, accO[dt][3] * inv1);
    }
}

// ---------------------------------------------------------------------------
extern "C" void kernel_launch(void* const* d_in, const int* in_sizes, int n_in,
                              void* d_out, int out_size) {
    const float* x  = (const float*)d_in[0];
    const int*   tp = (const int*)d_in[1];
    const float* Wq = (const float*)d_in[2];
    const float* Wk = (const float*)d_in[3];
    const float* Wv = (const float*)d_in[4];
    const float* Wo = (const float*)d_in[5];
    float* out = (float*)d_out;

    convert_split<<<dim3(4096, 5), 256>>>(x, Wq, Wk, Wv, Wo);

    cudaFuncSetAttribute(qkv_mma, cudaFuncAttributeMaxDynamicSharedMemorySize, 2 * GSTAGE * 2);
    qkv_mma<<<dim3(32, 24), 512, 2 * GSTAGE * 2>>>();

    rope_split<<<(BH * SEQ * 32) / 256, 256>>>(tp);

    int flash_smem = (2 * 128 * 72 + 2 * FST) * 2;
    cudaFuncSetAttribute(flash_mma, cudaFuncAttributeMaxDynamicSharedMemorySize, flash_smem);
    flash_mma<<<dim3(16, 32), 256, flash_smem>>>();

    cudaFuncSetAttribute(out_mma, cudaFuncAttributeMaxDynamicSharedMemorySize, 2 * GSTAGE * 2);
    out_mma<<<dim3(32, 8), 512, 2 * GSTAGE * 2>>>(out);
}

// round 12
// speedup vs baseline: 4.2969x; 1.2772x over previous
#include <cuda_runtime.h>
#include <cuda_bf16.h>
#include <cstdint>
#include <math.h>

#define NUM_HEADS 16
#define D_HEAD 64
#define BATCH 2
#define SEQ 2048
#define BH (BATCH*NUM_HEADS)
#define SCALE_LOG2E 0.18033688011112042f   // 0.125 * log2(e)

// fp32 scratch
__device__ float g_Q[BH*SEQ*D_HEAD];
__device__ float g_K[BH*SEQ*D_HEAD];
__device__ float g_V[BH*SEQ*D_HEAD];
__device__ float g_O[BH*SEQ*D_HEAD];
// bf16 split planes for GEMMs
__device__ __nv_bfloat16 g_xh[4096*1024];
__device__ __nv_bfloat16 g_xl[4096*1024];
__device__ __nv_bfloat16 g_wh[4*1024*1024];
__device__ __nv_bfloat16 g_wl[4*1024*1024];
// bf16 split planes for attention (post-RoPE)
__device__ __nv_bfloat16 g_Qh[BH*SEQ*D_HEAD];
__device__ __nv_bfloat16 g_Ql[BH*SEQ*D_HEAD];
__device__ __nv_bfloat16 g_Kh[BH*SEQ*D_HEAD];
__device__ __nv_bfloat16 g_Kl[BH*SEQ*D_HEAD];
__device__ __nv_bfloat16 g_Vh[BH*SEQ*D_HEAD];
__device__ __nv_bfloat16 g_Vl[BH*SEQ*D_HEAD];

// ---- helpers ---------------------------------------------------------------
__device__ __forceinline__ void ldsm4(unsigned r[4], unsigned addr) {
    asm volatile("ldmatrix.sync.aligned.m8n8.x4.shared.b16 {%0,%1,%2,%3}, [%4];"
                 : "=r"(r[0]), "=r"(r[1]), "=r"(r[2]), "=r"(r[3]) : "r"(addr));
}
__device__ __forceinline__ void ldsm4t(unsigned r[4], unsigned addr) {
    asm volatile("ldmatrix.sync.aligned.m8n8.x4.trans.shared.b16 {%0,%1,%2,%3}, [%4];"
                 : "=r"(r[0]), "=r"(r[1]), "=r"(r[2]), "=r"(r[3]) : "r"(addr));
}
__device__ __forceinline__ void mma16816(float c[4], const unsigned a[4], unsigned b0, unsigned b1) {
    asm volatile("mma.sync.aligned.m16n8k16.row.col.f32.bf16.bf16.f32 "
                 "{%0,%1,%2,%3},{%4,%5,%6,%7},{%8,%9},{%0,%1,%2,%3};"
                 : "+f"(c[0]), "+f"(c[1]), "+f"(c[2]), "+f"(c[3])
                 : "r"(a[0]), "r"(a[1]), "r"(a[2]), "r"(a[3]), "r"(b0), "r"(b1));
}
__device__ __forceinline__ unsigned packbf2(float a, float b) {
    __nv_bfloat162 t = __floats2bfloat162_rn(a, b);
    unsigned u;
    memcpy(&u, &t, 4);
    return u;
}
__device__ __forceinline__ float exp2a(float x) {
    float y;
    asm("ex2.approx.f32 %0, %1;" : "=f"(y) : "f"(x));
    return y;
}

// ---------------------------------------------------------------------------
// Split fp32 -> bf16 hi/lo planes for x and the 4 weight matrices.
// ---------------------------------------------------------------------------
__global__ void convert_split(const float* __restrict__ x,
                              const float* __restrict__ Wq, const float* __restrict__ Wk,
                              const float* __restrict__ Wv, const float* __restrict__ Wo) {
    int which = blockIdx.y;
    const float* src;
    __nv_bfloat16* dh;
    __nv_bfloat16* dl;
    int n;
    if (which == 0) {
        src = x; dh = g_xh; dl = g_xl; n = 4096 * 1024;
    } else {
        src = (which == 1) ? Wq : (which == 2) ? Wk : (which == 3) ? Wv : Wo;
        dh = g_wh + (size_t)(which - 1) * 1048576;
        dl = g_wl + (size_t)(which - 1) * 1048576;
        n = 1048576;
    }
    int i = (blockIdx.x * 256 + threadIdx.x) * 4;
    if (i >= n) return;
    float4 v = *(const float4*)(src + i);
    float f[4] = {v.x, v.y, v.z, v.w};
    __nv_bfloat16 hv[4];
    __nv_bfloat16 lv[4];
#pragma unroll
    for (int j = 0; j < 4; j++) {
        hv[j] = __float2bfloat16(f[j]);
        lv[j] = __float2bfloat16(f[j] - __bfloat162float(hv[j]));
    }
    uint2 hu, lu;
    memcpy(&hu, hv, 8);
    memcpy(&lu, lv, 8);
    *(uint2*)(dh + i) = hu;
    *(uint2*)(dl + i) = lu;
}

// ---------------------------------------------------------------------------
// mma compute for one 64-wide k chunk; 512-thread CTA (16 warps 4m x 4n),
// warp tile 32x32. Planes (stride 72): Ah +0, Al +9216, Bh +18432, Bl +27648.
// ---------------------------------------------------------------------------
#define GPL 9216            // elems per plane (128 x 72)
#define GSTAGE (4*GPL)      // elems per stage
__device__ __forceinline__ void mma_chunk64(unsigned stb, int lane, int warp_m, int warp_n,
                                            float acc[2][4][4]) {
    unsigned ah = stb;
    unsigned al = stb + GPL * 2;
    unsigned bh = stb + GPL * 4;
    unsigned bl = stb + GPL * 6;
#pragma unroll
    for (int kk = 0; kk < 64; kk += 16) {
        int col = kk + ((lane >> 4) << 3);
        int arow = warp_m * 32 + (lane & 15);
        int brow = warp_n * 32 + (lane & 15);
        unsigned afh[2][4];
        unsigned afl[2][4];
#pragma unroll
        for (int tm = 0; tm < 2; tm++) {
            ldsm4(afh[tm], ah + (unsigned)(((arow + tm * 16) * 72 + col) * 2));
            ldsm4(afl[tm], al + (unsigned)(((arow + tm * 16) * 72 + col) * 2));
        }
        unsigned bfh[2][4];
        unsigned bfl[2][4];
#pragma unroll
        for (int tg = 0; tg < 2; tg++) {
            ldsm4(bfh[tg], bh + (unsigned)(((brow + tg * 16) * 72 + col) * 2));
            ldsm4(bfl[tg], bl + (unsigned)(((brow + tg * 16) * 72 + col) * 2));
        }
#pragma unroll
        for (int tm = 0; tm < 2; tm++) {
#pragma unroll
            for (int tn = 0; tn < 4; tn++) {
                int tg = tn >> 1;
                int idx = tn & 1;
                mma16816(acc[tm][tn], afh[tm], bfh[tg][idx], bfh[tg][idx + 2]);
                mma16816(acc[tm][tn], afh[tm], bfl[tg][idx], bfl[tg][idx + 2]);
                mma16816(acc[tm][tn], afl[tm], bfh[tg][idx], bfh[tg][idx + 2]);
            }
        }
    }
}

// ---------------------------------------------------------------------------
// QKV projection: 512 threads, 128x128 tile, K-chunk 64, register-staged
// double buffer. Dynamic smem: 2 x 73728 B = 147456 B.
// ---------------------------------------------------------------------------
__global__ __launch_bounds__(512) void qkv_mma() {
    int mt = blockIdx.x;
    int which = blockIdx.y >> 3;
    int nt = blockIdx.y & 7;
    float* out = (which == 0) ? g_Q : (which == 1) ? g_K : g_V;

    extern __shared__ __nv_bfloat16 dynsm[];
    unsigned sb = (unsigned)__cvta_generic_to_shared(dynsm);

    int tid = threadIdx.x;
    int lane = tid & 31;
    int wid = tid >> 5;
    int warp_m = wid >> 2;
    int warp_n = wid & 3;
    int lrow = tid >> 2;              // 0..127
    int seg = (tid & 3) * 16;         // 0,16,32,48 within 64-chunk

    const __nv_bfloat16* srcs[4];
    srcs[0] = g_xh + (size_t)(mt * 128 + lrow) * 1024 + seg;
    srcs[1] = g_xl + (size_t)(mt * 128 + lrow) * 1024 + seg;
    srcs[2] = g_wh + (size_t)which * 1048576 + (size_t)(nt * 128 + lrow) * 1024 + seg;
    srcs[3] = g_wl + (size_t)which * 1048576 + (size_t)(nt * 128 + lrow) * 1024 + seg;

    float acc[2][4][4] = {};
    uint4 rg[4][2];

#pragma unroll
    for (int p = 0; p < 4; p++) {
        rg[p][0] = *(const uint4*)(srcs[p]);
        rg[p][1] = *(const uint4*)(srcs[p] + 8);
    }
    {
        __nv_bfloat16* dst = dynsm + lrow * 72 + seg;
#pragma unroll
        for (int p = 0; p < 4; p++) {
            *(uint4*)(dst + p * GPL) = rg[p][0];
            *(uint4*)(dst + p * GPL + 8) = rg[p][1];
        }
    }
    __syncthreads();

    for (int c = 0; c < 16; c++) {
        int s = c & 1;
        if (c < 15) {
#pragma unroll
            for (int p = 0; p < 4; p++) {
                rg[p][0] = *(const uint4*)(srcs[p] + (c + 1) * 64);
                rg[p][1] = *(const uint4*)(srcs[p] + (c + 1) * 64 + 8);
            }
        }
        mma_chunk64(sb + (unsigned)(s * GSTAGE * 2), lane, warp_m, warp_n, acc);
        if (c < 15) {
            __nv_bfloat16* dst = dynsm + (s ^ 1) * GSTAGE + lrow * 72 + seg;
#pragma unroll
            for (int p = 0; p < 4; p++) {
                *(uint4*)(dst + p * GPL) = rg[p][0];
                *(uint4*)(dst + p * GPL + 8) = rg[p][1];
            }
        }
        __syncthreads();
    }

    int head = nt * 2 + (warp_n >> 1);
#pragma unroll
    for (int tm = 0; tm < 2; tm++) {
#pragma unroll
        for (int tn = 0; tn < 4; tn++) {
            int m0 = mt * 128 + warp_m * 32 + tm * 16 + (lane >> 2);
            int d = (warp_n & 1) * 32 + tn * 8 + (lane & 3) * 2;
#pragma unroll
            for (int half = 0; half < 2; half++) {
                int m = m0 + half * 8;
                int b = m >> 11;
                int sq = m & 2047;
                float2 v = make_float2(acc[tm][tn][half * 2], acc[tm][tn][half * 2 + 1]);
                *(float2*)(out + (((size_t)(b * 16 + head) * SEQ + sq) * 64 + d)) = v;
            }
        }
    }
}

// ---------------------------------------------------------------------------
// Output projection: 512 threads, 128x128 tile, K-chunk 64 (= one head).
// A gathered from g_O ([B,H,S,d]) and split to bf16 hi/lo in registers.
// ---------------------------------------------------------------------------
__global__ __launch_bounds__(512) void out_mma(float* __restrict__ out) {
    int mt = blockIdx.x;
    int nt = blockIdx.y;

    extern __shared__ __nv_bfloat16 dynsm2[];
    unsigned sb = (unsigned)__cvta_generic_to_shared(dynsm2);

    int tid = threadIdx.x;
    int lane = tid & 31;
    int wid = tid >> 5;
    int warp_m = wid >> 2;
    int warp_n = wid & 3;
    int lrow = tid >> 2;
    int seg = (tid & 3) * 16;

    int m = mt * 128 + lrow;
    int b = m >> 11;
    int sq0 = m & 2047;
    const float* Abase = g_O + ((size_t)b * 16 * SEQ + sq0) * 64 + seg;  // + h*SEQ*64
    const __nv_bfloat16* sBh = g_wh + (size_t)3 * 1048576 + (size_t)(nt * 128 + lrow) * 1024 + seg;
    const __nv_bfloat16* sBl = g_wl + (size_t)3 * 1048576 + (size_t)(nt * 128 + lrow) * 1024 + seg;

    float acc[2][4][4] = {};
    float raf[16];
    uint4 rbh[2], rbl[2];

    auto stage_a = [&](__nv_bfloat16* dst) {
        unsigned ph[8], pl[8];
#pragma unroll
        for (int i = 0; i < 8; i++) {
            float fa = raf[2 * i];
            float fb = raf[2 * i + 1];
            __nv_bfloat16 ha = __float2bfloat16(fa);
            __nv_bfloat16 hb = __float2bfloat16(fb);
            ph[i] = packbf2(fa, fb);
            pl[i] = packbf2(fa - __bfloat162float(ha), fb - __bfloat162float(hb));
        }
        *(uint4*)(dst)           = *(uint4*)&ph[0];
        *(uint4*)(dst + 8)       = *(uint4*)&ph[4];
        *(uint4*)(dst + GPL)     = *(uint4*)&pl[0];
        *(uint4*)(dst + GPL + 8) = *(uint4*)&pl[4];
        *(uint4*)(dst + GPL * 2)     = rbh[0];
        *(uint4*)(dst + GPL * 2 + 8) = rbh[1];
        *(uint4*)(dst + GPL * 3)     = rbl[0];
        *(uint4*)(dst + GPL * 3 + 8) = rbl[1];
    };

    {
        const float* Ap = Abase;   // h = 0
#pragma unroll
        for (int i = 0; i < 4; i++) *(float4*)&raf[i * 4] = *(const float4*)(Ap + i * 4);
        rbh[0] = *(const uint4*)(sBh);
        rbh[1] = *(const uint4*)(sBh + 8);
        rbl[0] = *(const uint4*)(sBl);
        rbl[1] = *(const uint4*)(sBl + 8);
    }
    stage_a(dynsm2 + lrow * 72 + seg);
    __syncthreads();

    for (int c = 0; c < 16; c++) {
        int s = c & 1;
        if (c < 15) {
            const float* Ap = Abase + (size_t)(c + 1) * SEQ * 64;
#pragma unroll
            for (int i = 0; i < 4; i++) *(float4*)&raf[i * 4] = *(const float4*)(Ap + i * 4);
            rbh[0] = *(const uint4*)(sBh + (c + 1) * 64);
            rbh[1] = *(const uint4*)(sBh + (c + 1) * 64 + 8);
            rbl[0] = *(const uint4*)(sBl + (c + 1) * 64);
            rbl[1] = *(const uint4*)(sBl + (c + 1) * 64 + 8);
        }
        mma_chunk64(sb + (unsigned)(s * GSTAGE * 2), lane, warp_m, warp_n, acc);
        if (c < 15) stage_a(dynsm2 + (s ^ 1) * GSTAGE + lrow * 72 + seg);
        __syncthreads();
    }

#pragma unroll
    for (int tm = 0; tm < 2; tm++) {
#pragma unroll
        for (int tn = 0; tn < 4; tn++) {
            int m0 = mt * 128 + warp_m * 32 + tm * 16 + (lane >> 2);
            int e = nt * 128 + warp_n * 32 + tn * 8 + (lane & 3) * 2;
#pragma unroll
            for (int half = 0; half < 2; half++) {
                int mr = m0 + half * 8;
                float2 v = make_float2(acc[tm][tn][half * 2], acc[tm][tn][half * 2 + 1]);
                *(float2*)(out + (size_t)mr * 1024 + e) = v;
            }
        }
    }
}

// ---------------------------------------------------------------------------
// RoPE: one thread per (s, p) computes the angle ONCE and loops the 32 bh
// slices (coalesced across threads: p is the fast index).
// ---------------------------------------------------------------------------
__global__ void rope_split(const int* __restrict__ pos) {
    int t = blockIdx.x * blockDim.x + threadIdx.x;   // 0 .. SEQ*32-1
    if (t >= SEQ * 32) return;
    int p = t & 31;
    int s = t >> 5;
    double inv = exp(-(double)p * (9.210340371976184 / 32.0));
    double ang = (double)pos[s] * inv;
    double sn, cs;
    sincos(ang, &sn, &cs);
    float c = (float)cs;
    float sf = (float)sn;

#pragma unroll 4
    for (int bh = 0; bh < BH; bh++) {
        size_t idx = (size_t)bh * (SEQ * 32) + t;
        float2 q = *(float2*)(g_Q + 2 * idx);
        float2 k = *(float2*)(g_K + 2 * idx);
        float2 v = *(float2*)(g_V + 2 * idx);
        float q0 = (q.x * c - q.y * sf) * SCALE_LOG2E;
        float q1 = (q.x * sf + q.y * c) * SCALE_LOG2E;
        float k0 = k.x * c - k.y * sf;
        float k1 = k.x * sf + k.y * c;

        __nv_bfloat16 qh0 = __float2bfloat16(q0), qh1 = __float2bfloat16(q1);
        __nv_bfloat16 kh0 = __float2bfloat16(k0), kh1 = __float2bfloat16(k1);
        __nv_bfloat16 vh0 = __float2bfloat16(v.x), vh1 = __float2bfloat16(v.y);

        ((unsigned*)g_Qh)[idx] = packbf2(q0, q1);
        ((unsigned*)g_Ql)[idx] = packbf2(q0 - __bfloat162float(qh0), q1 - __bfloat162float(qh1));
        ((unsigned*)g_Kh)[idx] = packbf2(k0, k1);
        ((unsigned*)g_Kl)[idx] = packbf2(k0 - __bfloat162float(kh0), k1 - __bfloat162float(kh1));
        ((unsigned*)g_Vh)[idx] = packbf2(v.x, v.y);
        ((unsigned*)g_Vl)[idx] = packbf2(v.x - __bfloat162float(vh0), v.y - __bfloat162float(vh1));
    }
}

// ---------------------------------------------------------------------------
// Causal flash attention on tensor cores, register-staged double-buffered K/V.
// (unchanged from R8/R10/R11)
// ---------------------------------------------------------------------------
#define FPL (64*72)
#define FST (4*FPL)
__global__ __launch_bounds__(256) void flash_mma() {
    int qt = gridDim.x - 1 - blockIdx.x;
    int bh = blockIdx.y;
    size_t base = (size_t)bh * SEQ * 64;

    extern __shared__ __nv_bfloat16 smem[];
    __nv_bfloat16* Qhs = smem;
    __nv_bfloat16* Qls = Qhs + 128 * 72;
    __nv_bfloat16* KV  = Qls + 128 * 72;
    unsigned qhsB = (unsigned)__cvta_generic_to_shared(Qhs);
    unsigned qlsB = (unsigned)__cvta_generic_to_shared(Qls);
    unsigned kvB  = (unsigned)__cvta_generic_to_shared(KV);

    int tid = threadIdx.x;
    int lane = tid & 31;
    int w = tid >> 5;

    int ldrow = tid >> 2;
    int ldcol = (tid & 3) * 16;

    const __nv_bfloat16* kvsrc[4] = {g_Kh, g_Kl, g_Vh, g_Vl};

    uint4 rkv[4][2];
    {
        size_t g = base + (size_t)ldrow * 64 + ldcol;
#pragma unroll
        for (int p = 0; p < 4; p++) {
            rkv[p][0] = *(const uint4*)(kvsrc[p] + g);
            rkv[p][1] = *(const uint4*)(kvsrc[p] + g + 8);
        }
    }

    {
        int row = tid >> 1;
        int col = (tid & 1) * 32;
        const uint4* sh = (const uint4*)(g_Qh + base + (size_t)(qt * 128 + row) * 64 + col);
        const uint4* sl = (const uint4*)(g_Ql + base + (size_t)(qt * 128 + row) * 64 + col);
        uint4* dh = (uint4*)(Qhs + row * 72 + col);
        uint4* dl = (uint4*)(Qls + row * 72 + col);
#pragma unroll
        for (int i = 0; i < 4; i++) { dh[i] = sh[i]; dl[i] = sl[i]; }
    }
    {
        __nv_bfloat16* dst = KV + ldrow * 72 + ldcol;
#pragma unroll
        for (int p = 0; p < 4; p++) {
            *(uint4*)(dst + p * FPL) = rkv[p][0];
            *(uint4*)(dst + p * FPL + 8) = rkv[p][1];
        }
    }
    __syncthreads();

    unsigned qh[4][4], ql[4][4];
#pragma unroll
    for (int dc = 0; dc < 4; dc++) {
        unsigned off = (unsigned)(((w * 16 + (lane & 15)) * 72 + dc * 16 + 8 * (lane >> 4)) * 2);
        ldsm4(qh[dc], qhsB + off);
        ldsm4(ql[dc], qlsB + off);
    }

    float accO[8][4] = {};
    float mrow[2] = {-INFINITY, -INFINITY};
    float lrow[2] = {0.f, 0.f};

    int kmax = 2 * qt + 1;
    for (int kt = 0; kt <= kmax; kt++) {
        int st = kt & 1;
        if (kt < kmax) {
            size_t g = base + (size_t)((kt + 1) * 64 + ldrow) * 64 + ldcol;
#pragma unroll
            for (int p = 0; p < 4; p++) {
                rkv[p][0] = *(const uint4*)(kvsrc[p] + g);
                rkv[p][1] = *(const uint4*)(kvsrc[p] + g + 8);
            }
        }

        unsigned khsB = kvB + (unsigned)(st * FST * 2);
        unsigned klsB = khsB + FPL * 2;
        unsigned vhsB = khsB + FPL * 4;
        unsigned vlsB = khsB + FPL * 6;

        float s[8][4] = {};
#pragma unroll
        for (int dc = 0; dc < 4; dc++) {
            unsigned kh[4][4], kl[4][4];
#pragma unroll
            for (int jt2 = 0; jt2 < 4; jt2++) {
                unsigned off = (unsigned)(((jt2 * 16 + (lane & 15)) * 72 + dc * 16 + 8 * (lane >> 4)) * 2);
                ldsm4(kh[jt2], khsB + off);
                ldsm4(kl[jt2], klsB + off);
            }
#pragma unroll
            for (int jt = 0; jt < 8; jt++) {
                int jt2 = jt >> 1;
                int idx = jt & 1;
                mma16816(s[jt], qh[dc], kh[jt2][idx], kh[jt2][idx + 2]);
                mma16816(s[jt], qh[dc], kl[jt2][idx], kl[jt2][idx + 2]);
                mma16816(s[jt], ql[dc], kh[jt2][idx], kh[jt2][idx + 2]);
            }
        }

        if (kt >= 2 * qt) {
            int i0 = qt * 128 + w * 16 + (lane >> 2);
            int jb = kt * 64 + (lane & 3) * 2;
#pragma unroll
            for (int jt = 0; jt < 8; jt++) {
                int j = jb + jt * 8;
                if (j > i0) s[jt][0] = -1e30f;
                if (j + 1 > i0) s[jt][1] = -1e30f;
                if (j > i0 + 8) s[jt][2] = -1e30f;
                if (j + 1 > i0 + 8) s[jt][3] = -1e30f;
            }
        }

        float mx0 = -1e30f, mx1 = -1e30f;
#pragma unroll
        for (int jt = 0; jt < 8; jt++) {
            mx0 = fmaxf(mx0, fmaxf(s[jt][0], s[jt][1]));
            mx1 = fmaxf(mx1, fmaxf(s[jt][2], s[jt][3]));
        }
        mx0 = fmaxf(mx0, __shfl_xor_sync(0xffffffffu, mx0, 1));
        mx0 = fmaxf(mx0, __shfl_xor_sync(0xffffffffu, mx0, 2));
        mx1 = fmaxf(mx1, __shfl_xor_sync(0xffffffffu, mx1, 1));
        mx1 = fmaxf(mx1, __shfl_xor_sync(0xffffffffu, mx1, 2));
        float mn0 = fmaxf(mrow[0], mx0);
        float mn1 = fmaxf(mrow[1], mx1);
        float a0 = exp2a(mrow[0] - mn0);
        float a1 = exp2a(mrow[1] - mn1);
        mrow[0] = mn0;
        mrow[1] = mn1;
        float sum0 = 0.f, sum1 = 0.f;
#pragma unroll
        for (int jt = 0; jt < 8; jt++) {
            s[jt][0] = exp2a(s[jt][0] - mn0);
            s[jt][1] = exp2a(s[jt][1] - mn0);
            s[jt][2] = exp2a(s[jt][2] - mn1);
            s[jt][3] = exp2a(s[jt][3] - mn1);
            sum0 += s[jt][0] + s[jt][1];
            sum1 += s[jt][2] + s[jt][3];
        }
        sum0 += __shfl_xor_sync(0xffffffffu, sum0, 1);
        sum0 += __shfl_xor_sync(0xffffffffu, sum0, 2);
        sum1 += __shfl_xor_sync(0xffffffffu, sum1, 1);
        sum1 += __shfl_xor_sync(0xffffffffu, sum1, 2);
        lrow[0] = lrow[0] * a0 + sum0;
        lrow[1] = lrow[1] * a1 + sum1;
#pragma unroll
        for (int dt = 0; dt < 8; dt++) {
            accO[dt][0] *= a0;
            accO[dt][1] *= a0;
            accO[dt][2] *= a1;
            accO[dt][3] *= a1;
        }

#pragma unroll
        for (int kc = 0; kc < 4; kc++) {
            unsigned phh[4], pll[4];
            {
                float p00 = s[2 * kc][0], p01 = s[2 * kc][1], p02 = s[2 * kc][2], p03 = s[2 * kc][3];
                float p10 = s[2 * kc + 1][0], p11 = s[2 * kc + 1][1], p12 = s[2 * kc + 1][2], p13 = s[2 * kc + 1][3];
                phh[0] = packbf2(p00, p01);
                phh[1] = packbf2(p02, p03);
                phh[2] = packbf2(p10, p11);
                phh[3] = packbf2(p12, p13);
                pll[0] = packbf2(p00 - __bfloat162float(__float2bfloat16(p00)), p01 - __bfloat162float(__float2bfloat16(p01)));
                pll[1] = packbf2(p02 - __bfloat162float(__float2bfloat16(p02)), p03 - __bfloat162float(__float2bfloat16(p03)));
                pll[2] = packbf2(p10 - __bfloat162float(__float2bfloat16(p10)), p11 - __bfloat162float(__float2bfloat16(p11)));
                pll[3] = packbf2(p12 - __bfloat162float(__float2bfloat16(p12)), p13 - __bfloat162float(__float2bfloat16(p13)));
            }
            unsigned vh[4][4], vl[4][4];
#pragma unroll
            for (int dt2 = 0; dt2 < 4; dt2++) {
                unsigned off = (unsigned)(((kc * 16 + (lane & 15)) * 72 + dt2 * 16 + 8 * (lane >> 4)) * 2);
                ldsm4t(vh[dt2], vhsB + off);
                ldsm4t(vl[dt2], vlsB + off);
            }
#pragma unroll
            for (int dt = 0; dt < 8; dt++) {
                int dt2 = dt >> 1;
                int o = (dt & 1) * 2;
                mma16816(accO[dt], phh, vh[dt2][o], vh[dt2][o + 1]);
                mma16816(accO[dt], pll, vh[dt2][o], vh[dt2][o + 1]);
                mma16816(accO[dt], phh, vl[dt2][o], vl[dt2][o + 1]);
            }
        }

        if (kt < kmax) {
            __nv_bfloat16* dst = KV + (st ^ 1) * FST + ldrow * 72 + ldcol;
#pragma unroll
            for (int p = 0; p < 4; p++) {
                *(uint4*)(dst + p * FPL) = rkv[p][0];
                *(uint4*)(dst + p * FPL + 8) = rkv[p][1];
            }
        }
        __syncthreads();
    }

    float inv0 = 1.f / lrow[0];
    float inv1 = 1.f / lrow[1];
    int r0 = qt * 128 + w * 16 + (lane >> 2);
#pragma unroll
    for (int dt = 0; dt < 8; dt++) {
        int d = dt * 8 + (lane & 3) * 2;
        *(float2*)(g_O + base + (size_t)r0 * 64 + d) = make_float2(accO[dt][0] * inv0, accO[dt][1] * inv0);
        *(float2*)(g_O + base + (size_t)(r0 + 8) * 64 + d) = make_float2(accO[dt][2] * inv1, accO[dt][3] * inv1);
    }
}

// ---------------------------------------------------------------------------
extern "C" void kernel_launch(void* const* d_in, const int* in_sizes, int n_in,
                              void* d_out, int out_size) {
    const float* x  = (const float*)d_in[0];
    const int*   tp = (const int*)d_in[1];
    const float* Wq = (const float*)d_in[2];
    const float* Wk = (const float*)d_in[3];
    const float* Wv = (const float*)d_in[4];
    const float* Wo = (const float*)d_in[5];
    float* out = (float*)d_out;

    convert_split<<<dim3(4096, 5), 256>>>(x, Wq, Wk, Wv, Wo);

    cudaFuncSetAttribute(qkv_mma, cudaFuncAttributeMaxDynamicSharedMemorySize, 2 * GSTAGE * 2);
    qkv_mma<<<dim3(32, 24), 512, 2 * GSTAGE * 2>>>();

    rope_split<<<(SEQ * 32) / 256, 256>>>(tp);

    int flash_smem = (2 * 128 * 72 + 2 * FST) * 2;
    cudaFuncSetAttribute(flash_mma, cudaFuncAttributeMaxDynamicSharedMemorySize, flash_smem);
    flash_mma<<<dim3(16, 32), 256, flash_smem>>>();

    cudaFuncSetAttribute(out_mma, cudaFuncAttributeMaxDynamicSharedMemorySize, 2 * GSTAGE * 2);
    out_mma<<<dim3(32, 8), 512, 2 * GSTAGE * 2>>>(out);
}

// round 13
// speedup vs baseline: 4.3743x; 1.0180x over previous
#include <cuda_runtime.h>
#include <cuda_bf16.h>
#include <cstdint>
#include <math.h>

#define NUM_HEADS 16
#define D_HEAD 64
#define BATCH 2
#define SEQ 2048
#define BH (BATCH*NUM_HEADS)
#define SCALE_LOG2E 0.18033688011112042f   // 0.125 * log2(e)

// bf16 split planes for GEMMs
__device__ __nv_bfloat16 g_xh[4096*1024];
__device__ __nv_bfloat16 g_xl[4096*1024];
__device__ __nv_bfloat16 g_wh[4*1024*1024];
__device__ __nv_bfloat16 g_wl[4*1024*1024];
// bf16 split planes for attention (post-RoPE, written directly by qkv)
__device__ __nv_bfloat16 g_Qh[BH*SEQ*D_HEAD];
__device__ __nv_bfloat16 g_Ql[BH*SEQ*D_HEAD];
__device__ __nv_bfloat16 g_Kh[BH*SEQ*D_HEAD];
__device__ __nv_bfloat16 g_Kl[BH*SEQ*D_HEAD];
__device__ __nv_bfloat16 g_Vh[BH*SEQ*D_HEAD];
__device__ __nv_bfloat16 g_Vl[BH*SEQ*D_HEAD];
// attention output planes (written by flash, read by out_mma)
__device__ __nv_bfloat16 g_Oh[BH*SEQ*D_HEAD];
__device__ __nv_bfloat16 g_Ol[BH*SEQ*D_HEAD];
// RoPE table: [s][p] -> (cos, sin), fp32 from double
__device__ float2 g_tbl[SEQ*32];

// ---- helpers ---------------------------------------------------------------
__device__ __forceinline__ void ldsm4(unsigned r[4], unsigned addr) {
    asm volatile("ldmatrix.sync.aligned.m8n8.x4.shared.b16 {%0,%1,%2,%3}, [%4];"
                 : "=r"(r[0]), "=r"(r[1]), "=r"(r[2]), "=r"(r[3]) : "r"(addr));
}
__device__ __forceinline__ void ldsm4t(unsigned r[4], unsigned addr) {
    asm volatile("ldmatrix.sync.aligned.m8n8.x4.trans.shared.b16 {%0,%1,%2,%3}, [%4];"
                 : "=r"(r[0]), "=r"(r[1]), "=r"(r[2]), "=r"(r[3]) : "r"(addr));
}
__device__ __forceinline__ void mma16816(float c[4], const unsigned a[4], unsigned b0, unsigned b1) {
    asm volatile("mma.sync.aligned.m16n8k16.row.col.f32.bf16.bf16.f32 "
                 "{%0,%1,%2,%3},{%4,%5,%6,%7},{%8,%9},{%0,%1,%2,%3};"
                 : "+f"(c[0]), "+f"(c[1]), "+f"(c[2]), "+f"(c[3])
                 : "r"(a[0]), "r"(a[1]), "r"(a[2]), "r"(a[3]), "r"(b0), "r"(b1));
}
__device__ __forceinline__ unsigned packbf2(float a, float b) {
    __nv_bfloat162 t = __floats2bfloat162_rn(a, b);
    unsigned u;
    memcpy(&u, &t, 4);
    return u;
}
__device__ __forceinline__ unsigned packlo2(float a, float b) {
    return packbf2(a - __bfloat162float(__float2bfloat16(a)),
                   b - __bfloat162float(__float2bfloat16(b)));
}
__device__ __forceinline__ float exp2a(float x) {
    float y;
    asm("ex2.approx.f32 %0, %1;" : "=f"(y) : "f"(x));
    return y;
}

// ---------------------------------------------------------------------------
// RoPE cos/sin table (double precision, once).
// ---------------------------------------------------------------------------
__global__ void rope_table(const int* __restrict__ pos) {
    int t = blockIdx.x * 256 + threadIdx.x;
    if (t >= SEQ * 32) return;
    int p = t & 31;
    int s = t >> 5;
    double inv = exp(-(double)p * (9.210340371976184 / 32.0));
    double ang = (double)pos[s] * inv;
    double sn, cs;
    sincos(ang, &sn, &cs);
    g_tbl[t] = make_float2((float)cs, (float)sn);
}

// ---------------------------------------------------------------------------
// Split fp32 -> bf16 hi/lo planes for x and the 4 weight matrices.
// ---------------------------------------------------------------------------
__global__ void convert_split(const float* __restrict__ x,
                              const float* __restrict__ Wq, const float* __restrict__ Wk,
                              const float* __restrict__ Wv, const float* __restrict__ Wo) {
    int which = blockIdx.y;
    const float* src;
    __nv_bfloat16* dh;
    __nv_bfloat16* dl;
    int n;
    if (which == 0) {
        src = x; dh = g_xh; dl = g_xl; n = 4096 * 1024;
    } else {
        src = (which == 1) ? Wq : (which == 2) ? Wk : (which == 3) ? Wv : Wo;
        dh = g_wh + (size_t)(which - 1) * 1048576;
        dl = g_wl + (size_t)(which - 1) * 1048576;
        n = 1048576;
    }
    int i = (blockIdx.x * 256 + threadIdx.x) * 4;
    if (i >= n) return;
    float4 v = *(const float4*)(src + i);
    float f[4] = {v.x, v.y, v.z, v.w};
    __nv_bfloat16 hv[4];
    __nv_bfloat16 lv[4];
#pragma unroll
    for (int j = 0; j < 4; j++) {
        hv[j] = __float2bfloat16(f[j]);
        lv[j] = __float2bfloat16(f[j] - __bfloat162float(hv[j]));
    }
    uint2 hu, lu;
    memcpy(&hu, hv, 8);
    memcpy(&lu, lv, 8);
    *(uint2*)(dh + i) = hu;
    *(uint2*)(dl + i) = lu;
}

// ---------------------------------------------------------------------------
// mma compute for one 64-wide k chunk; 512-thread CTA (16 warps 4m x 4n),
// warp tile 32x32. Planes (stride 72): Ah +0, Al, Bh, Bl at GPL steps.
// ---------------------------------------------------------------------------
#define GPL 9216            // elems per plane (128 x 72)
#define GSTAGE (4*GPL)      // elems per stage
__device__ __forceinline__ void mma_chunk64(unsigned stb, int lane, int warp_m, int warp_n,
                                            float acc[2][4][4]) {
    unsigned ah = stb;
    unsigned al = stb + GPL * 2;
    unsigned bh = stb + GPL * 4;
    unsigned bl = stb + GPL * 6;
#pragma unroll
    for (int kk = 0; kk < 64; kk += 16) {
        int col = kk + ((lane >> 4) << 3);
        int arow = warp_m * 32 + (lane & 15);
        int brow = warp_n * 32 + (lane & 15);
        unsigned afh[2][4];
        unsigned afl[2][4];
#pragma unroll
        for (int tm = 0; tm < 2; tm++) {
            ldsm4(afh[tm], ah + (unsigned)(((arow + tm * 16) * 72 + col) * 2));
            ldsm4(afl[tm], al + (unsigned)(((arow + tm * 16) * 72 + col) * 2));
        }
        unsigned bfh[2][4];
        unsigned bfl[2][4];
#pragma unroll
        for (int tg = 0; tg < 2; tg++) {
            ldsm4(bfh[tg], bh + (unsigned)(((brow + tg * 16) * 72 + col) * 2));
            ldsm4(bfl[tg], bl + (unsigned)(((brow + tg * 16) * 72 + col) * 2));
        }
#pragma unroll
        for (int tm = 0; tm < 2; tm++) {
#pragma unroll
            for (int tn = 0; tn < 4; tn++) {
                int tg = tn >> 1;
                int idx = tn & 1;
                mma16816(acc[tm][tn], afh[tm], bfh[tg][idx], bfh[tg][idx + 2]);
                mma16816(acc[tm][tn], afh[tm], bfl[tg][idx], bfl[tg][idx + 2]);
                mma16816(acc[tm][tn], afl[tm], bfh[tg][idx], bfh[tg][idx + 2]);
            }
        }
    }
}

// ---------------------------------------------------------------------------
// QKV projection with FUSED RoPE + bf16-split epilogue (coalesced via smem).
// 512 threads, 128x128 tile, K-chunk 64, register-staged double buffer.
// ---------------------------------------------------------------------------
__global__ __launch_bounds__(512) void qkv_mma() {
    int mt = blockIdx.x;
    int which = blockIdx.y >> 3;
    int nt = blockIdx.y & 7;

    extern __shared__ __nv_bfloat16 dynsm[];
    unsigned sb = (unsigned)__cvta_generic_to_shared(dynsm);

    int tid = threadIdx.x;
    int lane = tid & 31;
    int wid = tid >> 5;
    int warp_m = wid >> 2;
    int warp_n = wid & 3;
    int lrow = tid >> 2;
    int seg = (tid & 3) * 16;

    const __nv_bfloat16* srcs[4];
    srcs[0] = g_xh + (size_t)(mt * 128 + lrow) * 1024 + seg;
    srcs[1] = g_xl + (size_t)(mt * 128 + lrow) * 1024 + seg;
    srcs[2] = g_wh + (size_t)which * 1048576 + (size_t)(nt * 128 + lrow) * 1024 + seg;
    srcs[3] = g_wl + (size_t)which * 1048576 + (size_t)(nt * 128 + lrow) * 1024 + seg;

    float acc[2][4][4] = {};
    uint4 rg[4][2];

#pragma unroll
    for (int p = 0; p < 4; p++) {
        rg[p][0] = *(const uint4*)(srcs[p]);
        rg[p][1] = *(const uint4*)(srcs[p] + 8);
    }
    {
        __nv_bfloat16* dst = dynsm + lrow * 72 + seg;
#pragma unroll
        for (int p = 0; p < 4; p++) {
            *(uint4*)(dst + p * GPL) = rg[p][0];
            *(uint4*)(dst + p * GPL + 8) = rg[p][1];
        }
    }
    __syncthreads();

    for (int c = 0; c < 16; c++) {
        int s = c & 1;
        if (c < 15) {
#pragma unroll
            for (int p = 0; p < 4; p++) {
                rg[p][0] = *(const uint4*)(srcs[p] + (c + 1) * 64);
                rg[p][1] = *(const uint4*)(srcs[p] + (c + 1) * 64 + 8);
            }
        }
        mma_chunk64(sb + (unsigned)(s * GSTAGE * 2), lane, warp_m, warp_n, acc);
        if (c < 15) {
            __nv_bfloat16* dst = dynsm + (s ^ 1) * GSTAGE + lrow * 72 + seg;
#pragma unroll
            for (int p = 0; p < 4; p++) {
                *(uint4*)(dst + p * GPL) = rg[p][0];
                *(uint4*)(dst + p * GPL + 8) = rg[p][1];
            }
        }
        __syncthreads();
    }

    // ---- fused RoPE + split epilogue ----
    // regions: (head 0/1) x (hi/lo), each 128 rows x 32 words, row stride 36
    unsigned* W = (unsigned*)dynsm;
    int b = mt >> 4;
    int s0 = (mt & 15) * 128;
    int headr = warp_n >> 1;
#pragma unroll
    for (int tm = 0; tm < 2; tm++) {
#pragma unroll
        for (int tn = 0; tn < 4; tn++) {
#pragma unroll
            for (int half = 0; half < 2; half++) {
                int mrow = warp_m * 32 + tm * 16 + (lane >> 2) + half * 8;   // 0..127
                int d = (warp_n & 1) * 32 + tn * 8 + (lane & 3) * 2;
                float a0 = acc[tm][tn][half * 2];
                float a1 = acc[tm][tn][half * 2 + 1];
                if (which < 2) {
                    float2 cs = g_tbl[(s0 + mrow) * 32 + (d >> 1)];
                    float r0 = a0 * cs.x - a1 * cs.y;
                    float r1 = a0 * cs.y + a1 * cs.x;
                    if (which == 0) { r0 *= SCALE_LOG2E; r1 *= SCALE_LOG2E; }
                    a0 = r0; a1 = r1;
                }
                int col = d >> 1;   // 0..31
                W[(headr * 2 + 0) * 4608 + mrow * 36 + col] = packbf2(a0, a1);
                W[(headr * 2 + 1) * 4608 + mrow * 36 + col] = packlo2(a0, a1);
            }
        }
    }
    __syncthreads();

    __nv_bfloat16* gh = (which == 0) ? g_Qh : (which == 1) ? g_Kh : g_Vh;
    __nv_bfloat16* gl = (which == 0) ? g_Ql : (which == 1) ? g_Kl : g_Vl;
#pragma unroll
    for (int i = 0; i < 8; i++) {
        int li = tid * 8 + i;           // 0..4095
        int region = li >> 10;
        int rem = li & 1023;
        int row = rem >> 3;
        int q4 = rem & 7;
        uint4 v = *(uint4*)&W[region * 4608 + row * 36 + q4 * 4];
        int head = nt * 2 + (region >> 1);
        unsigned* dst = (unsigned*)((region & 1) ? gl : gh)
                        + ((size_t)(b * 16 + head) * SEQ + s0 + row) * 32 + q4 * 4;
        *(uint4*)dst = v;
    }
}

// ---------------------------------------------------------------------------
// Output projection: A staged as plain copies of g_Oh/g_Ol planes (k-chunk 64
// = one head). 512 threads, 128x128 tile, register-staged double buffer.
// ---------------------------------------------------------------------------
__global__ __launch_bounds__(512) void out_mma(float* __restrict__ out) {
    int mt = blockIdx.x;
    int nt = blockIdx.y;

    extern __shared__ __nv_bfloat16 dynsm2[];
    unsigned sb = (unsigned)__cvta_generic_to_shared(dynsm2);

    int tid = threadIdx.x;
    int lane = tid & 31;
    int wid = tid >> 5;
    int warp_m = wid >> 2;
    int warp_n = wid & 3;
    int lrow = tid >> 2;
    int seg = (tid & 3) * 16;

    int m = mt * 128 + lrow;
    int b = m >> 11;
    int sq0 = m & 2047;
    const unsigned* pOh = (const unsigned*)g_Oh + ((size_t)(b * 16) * SEQ + sq0) * 32 + (tid & 3) * 8;
    const unsigned* pOl = (const unsigned*)g_Ol + ((size_t)(b * 16) * SEQ + sq0) * 32 + (tid & 3) * 8;
    const __nv_bfloat16* sBh = g_wh + (size_t)3 * 1048576 + (size_t)(nt * 128 + lrow) * 1024 + seg;
    const __nv_bfloat16* sBl = g_wl + (size_t)3 * 1048576 + (size_t)(nt * 128 + lrow) * 1024 + seg;

    float acc[2][4][4] = {};
    uint4 rg[4][2];

#pragma unroll
    for (int p = 0; p < 2; p++) {
        const unsigned* po = p ? pOl : pOh;
        rg[p][0] = *(const uint4*)(po);
        rg[p][1] = *(const uint4*)(po + 4);
    }
    rg[2][0] = *(const uint4*)(sBh);
    rg[2][1] = *(const uint4*)(sBh + 8);
    rg[3][0] = *(const uint4*)(sBl);
    rg[3][1] = *(const uint4*)(sBl + 8);
    {
        __nv_bfloat16* dst = dynsm2 + lrow * 72 + seg;
#pragma unroll
        for (int p = 0; p < 4; p++) {
            *(uint4*)(dst + p * GPL) = rg[p][0];
            *(uint4*)(dst + p * GPL + 8) = rg[p][1];
        }
    }
    __syncthreads();

    for (int c = 0; c < 16; c++) {
        int s = c & 1;
        if (c < 15) {
            size_t ho = (size_t)(c + 1) * SEQ * 32;
            rg[0][0] = *(const uint4*)(pOh + ho);
            rg[0][1] = *(const uint4*)(pOh + ho + 4);
            rg[1][0] = *(const uint4*)(pOl + ho);
            rg[1][1] = *(const uint4*)(pOl + ho + 4);
            rg[2][0] = *(const uint4*)(sBh + (c + 1) * 64);
            rg[2][1] = *(const uint4*)(sBh + (c + 1) * 64 + 8);
            rg[3][0] = *(const uint4*)(sBl + (c + 1) * 64);
            rg[3][1] = *(const uint4*)(sBl + (c + 1) * 64 + 8);
        }
        mma_chunk64(sb + (unsigned)(s * GSTAGE * 2), lane, warp_m, warp_n, acc);
        if (c < 15) {
            __nv_bfloat16* dst = dynsm2 + (s ^ 1) * GSTAGE + lrow * 72 + seg;
#pragma unroll
            for (int p = 0; p < 4; p++) {
                *(uint4*)(dst + p * GPL) = rg[p][0];
                *(uint4*)(dst + p * GPL + 8) = rg[p][1];
            }
        }
        __syncthreads();
    }

#pragma unroll
    for (int tm = 0; tm < 2; tm++) {
#pragma unroll
        for (int tn = 0; tn < 4; tn++) {
            int m0 = mt * 128 + warp_m * 32 + tm * 16 + (lane >> 2);
            int e = nt * 128 + warp_n * 32 + tn * 8 + (lane & 3) * 2;
#pragma unroll
            for (int half = 0; half < 2; half++) {
                int mr = m0 + half * 8;
                float2 v = make_float2(acc[tm][tn][half * 2], acc[tm][tn][half * 2 + 1]);
                *(float2*)(out + (size_t)mr * 1024 + e) = v;
            }
        }
    }
}

// ---------------------------------------------------------------------------
// Causal flash attention on tensor cores, register-staged double-buffered K/V.
// Compute loop identical to R12; epilogue writes bf16 O planes (coalesced).
// ---------------------------------------------------------------------------
#define FPL (64*72)
#define FST (4*FPL)
__global__ __launch_bounds__(256) void flash_mma() {
    int qt = gridDim.x - 1 - blockIdx.x;
    int bh = blockIdx.y;
    size_t base = (size_t)bh * SEQ * 64;

    extern __shared__ __nv_bfloat16 smem[];
    __nv_bfloat16* Qhs = smem;
    __nv_bfloat16* Qls = Qhs + 128 * 72;
    __nv_bfloat16* KV  = Qls + 128 * 72;
    unsigned qhsB = (unsigned)__cvta_generic_to_shared(Qhs);
    unsigned qlsB = (unsigned)__cvta_generic_to_shared(Qls);
    unsigned kvB  = (unsigned)__cvta_generic_to_shared(KV);

    int tid = threadIdx.x;
    int lane = tid & 31;
    int w = tid >> 5;

    int ldrow = tid >> 2;
    int ldcol = (tid & 3) * 16;

    const __nv_bfloat16* kvsrc[4] = {g_Kh, g_Kl, g_Vh, g_Vl};

    uint4 rkv[4][2];
    {
        size_t g = base + (size_t)ldrow * 64 + ldcol;
#pragma unroll
        for (int p = 0; p < 4; p++) {
            rkv[p][0] = *(const uint4*)(kvsrc[p] + g);
            rkv[p][1] = *(const uint4*)(kvsrc[p] + g + 8);
        }
    }

    {
        int row = tid >> 1;
        int col = (tid & 1) * 32;
        const uint4* sh = (const uint4*)(g_Qh + base + (size_t)(qt * 128 + row) * 64 + col);
        const uint4* sl = (const uint4*)(g_Ql + base + (size_t)(qt * 128 + row) * 64 + col);
        uint4* dh = (uint4*)(Qhs + row * 72 + col);
        uint4* dl = (uint4*)(Qls + row * 72 + col);
#pragma unroll
        for (int i = 0; i < 4; i++) { dh[i] = sh[i]; dl[i] = sl[i]; }
    }
    {
        __nv_bfloat16* dst = KV + ldrow * 72 + ldcol;
#pragma unroll
        for (int p = 0; p < 4; p++) {
            *(uint4*)(dst + p * FPL) = rkv[p][0];
            *(uint4*)(dst + p * FPL + 8) = rkv[p][1];
        }
    }
    __syncthreads();

    unsigned qh[4][4], ql[4][4];
#pragma unroll
    for (int dc = 0; dc < 4; dc++) {
        unsigned off = (unsigned)(((w * 16 + (lane & 15)) * 72 + dc * 16 + 8 * (lane >> 4)) * 2);
        ldsm4(qh[dc], qhsB + off);
        ldsm4(ql[dc], qlsB + off);
    }

    float accO[8][4] = {};
    float mrow[2] = {-INFINITY, -INFINITY};
    float lrow[2] = {0.f, 0.f};

    int kmax = 2 * qt + 1;
    for (int kt = 0; kt <= kmax; kt++) {
        int st = kt & 1;
        if (kt < kmax) {
            size_t g = base + (size_t)((kt + 1) * 64 + ldrow) * 64 + ldcol;
#pragma unroll
            for (int p = 0; p < 4; p++) {
                rkv[p][0] = *(const uint4*)(kvsrc[p] + g);
                rkv[p][1] = *(const uint4*)(kvsrc[p] + g + 8);
            }
        }

        unsigned khsB = kvB + (unsigned)(st * FST * 2);
        unsigned klsB = khsB + FPL * 2;
        unsigned vhsB = khsB + FPL * 4;
        unsigned vlsB = khsB + FPL * 6;

        float s[8][4] = {};
#pragma unroll
        for (int dc = 0; dc < 4; dc++) {
            unsigned kh[4][4], kl[4][4];
#pragma unroll
            for (int jt2 = 0; jt2 < 4; jt2++) {
                unsigned off = (unsigned)(((jt2 * 16 + (lane & 15)) * 72 + dc * 16 + 8 * (lane >> 4)) * 2);
                ldsm4(kh[jt2], khsB + off);
                ldsm4(kl[jt2], klsB + off);
            }
#pragma unroll
            for (int jt = 0; jt < 8; jt++) {
                int jt2 = jt >> 1;
                int idx = jt & 1;
                mma16816(s[jt], qh[dc], kh[jt2][idx], kh[jt2][idx + 2]);
                mma16816(s[jt], qh[dc], kl[jt2][idx], kl[jt2][idx + 2]);
                mma16816(s[jt], ql[dc], kh[jt2][idx], kh[jt2][idx + 2]);
            }
        }

        if (kt >= 2 * qt) {
            int i0 = qt * 128 + w * 16 + (lane >> 2);
            int jb = kt * 64 + (lane & 3) * 2;
#pragma unroll
            for (int jt = 0; jt < 8; jt++) {
                int j = jb + jt * 8;
                if (j > i0) s[jt][0] = -1e30f;
                if (j + 1 > i0) s[jt][1] = -1e30f;
                if (j > i0 + 8) s[jt][2] = -1e30f;
                if (j + 1 > i0 + 8) s[jt][3] = -1e30f;
            }
        }

        float mx0 = -1e30f, mx1 = -1e30f;
#pragma unroll
        for (int jt = 0; jt < 8; jt++) {
            mx0 = fmaxf(mx0, fmaxf(s[jt][0], s[jt][1]));
            mx1 = fmaxf(mx1, fmaxf(s[jt][2], s[jt][3]));
        }
        mx0 = fmaxf(mx0, __shfl_xor_sync(0xffffffffu, mx0, 1));
        mx0 = fmaxf(mx0, __shfl_xor_sync(0xffffffffu, mx0, 2));
        mx1 = fmaxf(mx1, __shfl_xor_sync(0xffffffffu, mx1, 1));
        mx1 = fmaxf(mx1, __shfl_xor_sync(0xffffffffu, mx1, 2));
        float mn0 = fmaxf(mrow[0], mx0);
        float mn1 = fmaxf(mrow[1], mx1);
        float a0 = exp2a(mrow[0] - mn0);
        float a1 = exp2a(mrow[1] - mn1);
        mrow[0] = mn0;
        mrow[1] = mn1;
        float sum0 = 0.f, sum1 = 0.f;
#pragma unroll
        for (int jt = 0; jt < 8; jt++) {
            s[jt][0] = exp2a(s[jt][0] - mn0);
            s[jt][1] = exp2a(s[jt][1] - mn0);
            s[jt][2] = exp2a(s[jt][2] - mn1);
            s[jt][3] = exp2a(s[jt][3] - mn1);
            sum0 += s[jt][0] + s[jt][1];
            sum1 += s[jt][2] + s[jt][3];
        }
        sum0 += __shfl_xor_sync(0xffffffffu, sum0, 1);
        sum0 += __shfl_xor_sync(0xffffffffu, sum0, 2);
        sum1 += __shfl_xor_sync(0xffffffffu, sum1, 1);
        sum1 += __shfl_xor_sync(0xffffffffu, sum1, 2);
        lrow[0] = lrow[0] * a0 + sum0;
        lrow[1] = lrow[1] * a1 + sum1;
#pragma unroll
        for (int dt = 0; dt < 8; dt++) {
            accO[dt][0] *= a0;
            accO[dt][1] *= a0;
            accO[dt][2] *= a1;
            accO[dt][3] *= a1;
        }

#pragma unroll
        for (int kc = 0; kc < 4; kc++) {
            unsigned phh[4], pll[4];
            {
                float p00 = s[2 * kc][0], p01 = s[2 * kc][1], p02 = s[2 * kc][2], p03 = s[2 * kc][3];
                float p10 = s[2 * kc + 1][0], p11 = s[2 * kc + 1][1], p12 = s[2 * kc + 1][2], p13 = s[2 * kc + 1][3];
                phh[0] = packbf2(p00, p01);
                phh[1] = packbf2(p02, p03);
                phh[2] = packbf2(p10, p11);
                phh[3] = packbf2(p12, p13);
                pll[0] = packlo2(p00, p01);
                pll[1] = packlo2(p02, p03);
                pll[2] = packlo2(p10, p11);
                pll[3] = packlo2(p12, p13);
            }
            unsigned vh[4][4], vl[4][4];
#pragma unroll
            for (int dt2 = 0; dt2 < 4; dt2++) {
                unsigned off = (unsigned)(((kc * 16 + (lane & 15)) * 72 + dt2 * 16 + 8 * (lane >> 4)) * 2);
                ldsm4t(vh[dt2], vhsB + off);
                ldsm4t(vl[dt2], vlsB + off);
            }
#pragma unroll
            for (int dt = 0; dt < 8; dt++) {
                int dt2 = dt >> 1;
                int o = (dt & 1) * 2;
                mma16816(accO[dt], phh, vh[dt2][o], vh[dt2][o + 1]);
                mma16816(accO[dt], pll, vh[dt2][o], vh[dt2][o + 1]);
                mma16816(accO[dt], phh, vl[dt2][o], vl[dt2][o + 1]);
            }
        }

        if (kt < kmax) {
            __nv_bfloat16* dst = KV + (st ^ 1) * FST + ldrow * 72 + ldcol;
#pragma unroll
            for (int p = 0; p < 4; p++) {
                *(uint4*)(dst + p * FPL) = rkv[p][0];
                *(uint4*)(dst + p * FPL + 8) = rkv[p][1];
            }
        }
        __syncthreads();
    }

    // ---- epilogue: split O to bf16 planes, coalesced via smem ----
    float inv0 = 1.f / lrow[0];
    float inv1 = 1.f / lrow[1];
    unsigned* W = (unsigned*)smem;   // 2 regions x 128 x 32 words, row stride 36
#pragma unroll
    for (int dt = 0; dt < 8; dt++) {
        int col = dt * 4 + (lane & 3);
        {
            float a0 = accO[dt][0] * inv0;
            float a1 = accO[dt][1] * inv0;
            int row = w * 16 + (lane >> 2);
            W[row * 36 + col] = packbf2(a0, a1);
            W[4608 + row * 36 + col] = packlo2(a0, a1);
        }
        {
            float a0 = accO[dt][2] * inv1;
            float a1 = accO[dt][3] * inv1;
            int row = w * 16 + (lane >> 2) + 8;
            W[row * 36 + col] = packbf2(a0, a1);
            W[4608 + row * 36 + col] = packlo2(a0, a1);
        }
    }
    __syncthreads();
#pragma unroll
    for (int i = 0; i < 8; i++) {
        int li = tid * 8 + i;        // 0..2047
        int region = li >> 10;
        int rem = li & 1023;
        int row = rem >> 3;
        int q4 = rem & 7;
        uint4 v = *(uint4*)&W[region * 4608 + row * 36 + q4 * 4];
        unsigned* dst = (unsigned*)(region ? g_Ol : g_Oh)
                        + ((size_t)bh * SEQ + qt * 128 + row) * 32 + q4 * 4;
        *(uint4*)dst = v;
    }
}

// ---------------------------------------------------------------------------
extern "C" void kernel_launch(void* const* d_in, const int* in_sizes, int n_in,
                              void* d_out, int out_size) {
    const float* x  = (const float*)d_in[0];
    const int*   tp = (const int*)d_in[1];
    const float* Wq = (const float*)d_in[2];
    const float* Wk = (const float*)d_in[3];
    const float* Wv = (const float*)d_in[4];
    const float* Wo = (const float*)d_in[5];
    float* out = (float*)d_out;

    rope_table<<<(SEQ * 32 + 255) / 256, 256>>>(tp);
    convert_split<<<dim3(4096, 5), 256>>>(x, Wq, Wk, Wv, Wo);

    cudaFuncSetAttribute(qkv_mma, cudaFuncAttributeMaxDynamicSharedMemorySize, 2 * GSTAGE * 2);
    qkv_mma<<<dim3(32, 24), 512, 2 * GSTAGE * 2>>>();

    int flash_smem = (2 * 128 * 72 + 2 * FST) * 2;
    cudaFuncSetAttribute(flash_mma, cudaFuncAttributeMaxDynamicSharedMemorySize, flash_smem);
    flash_mma<<<dim3(16, 32), 256, flash_smem>>>();

    cudaFuncSetAttribute(out_mma, cudaFuncAttributeMaxDynamicSharedMemorySize, 2 * GSTAGE * 2);
    out_mma<<<dim3(32, 8), 512, 2 * GSTAGE * 2>>>(out);
}